// round 9
// baseline (speedup 1.0000x reference)
#include <cuda_runtime.h>
#include <cuda_bf16.h>
#include <math.h>
#include <stdint.h>

#define S_LEN 2048
#define H_DIM 4096
#define NQH 32
#define NKVH 8
#define HDIM 128
#define KDIM 4096
#define NQKV 6144

// ---------------------------------------------------------------------------
// Scratch (device globals; no allocation allowed)
// ---------------------------------------------------------------------------
__device__ float g_QKV[S_LEN * NQKV];          // fused QKV projection output
__device__ float g_Ctx[S_LEN * H_DIM];

__device__ __nv_bfloat16 g_Ahi[S_LEN * KDIM];  // activations hi
__device__ __nv_bfloat16 g_Alo[S_LEN * KDIM];  // activations lo
__device__ __nv_bfloat16 g_Bhi[NQKV * KDIM];   // weights (transposed [N,K]) hi
__device__ __nv_bfloat16 g_Blo[NQKV * KDIM];   // weights lo

// attention operands (bf16 split, rope+scale applied)
__device__ __nv_bfloat16 g_Qh[S_LEN * NQH * HDIM];
__device__ __nv_bfloat16 g_Ql[S_LEN * NQH * HDIM];
__device__ __nv_bfloat16 g_Kh[S_LEN * NKVH * HDIM];
__device__ __nv_bfloat16 g_Kl[S_LEN * NKVH * HDIM];
__device__ __nv_bfloat16 g_Vh[S_LEN * NKVH * HDIM];
__device__ __nv_bfloat16 g_Vl[S_LEN * NKVH * HDIM];

// ---------------------------------------------------------------------------
// Helpers
// ---------------------------------------------------------------------------
__device__ __forceinline__ uint32_t smem_u32(const void* p) {
  uint32_t a;
  asm("{ .reg .u64 t; cvta.to.shared.u64 t, %1; cvt.u32.u64 %0, t; }"
      : "=r"(a) : "l"(p));
  return a;
}

__device__ __forceinline__ void cp16(uint32_t dst, const void* src) {
  asm volatile("cp.async.cg.shared.global [%0], [%1], 16;" ::"r"(dst), "l"(src));
}

#define LDSM4(R, ADDR)                                                         \
  asm volatile("ldmatrix.sync.aligned.m8n8.x4.shared.b16 {%0,%1,%2,%3}, [%4];" \
               : "=r"((R)[0]), "=r"((R)[1]), "=r"((R)[2]), "=r"((R)[3])        \
               : "r"(ADDR))

#define LDSM4T(R, ADDR)                                                        \
  asm volatile(                                                                \
      "ldmatrix.sync.aligned.m8n8.x4.trans.shared.b16 {%0,%1,%2,%3}, [%4];"    \
      : "=r"((R)[0]), "=r"((R)[1]), "=r"((R)[2]), "=r"((R)[3])                 \
      : "r"(ADDR))

#define MMA16816(D, A, B)                                                      \
  asm volatile(                                                                \
      "mma.sync.aligned.m16n8k16.row.col.f32.bf16.bf16.f32 "                   \
      "{%0,%1,%2,%3}, {%4,%5,%6,%7}, {%8,%9}, {%0,%1,%2,%3};"                  \
      : "+f"((D)[0]), "+f"((D)[1]), "+f"((D)[2]), "+f"((D)[3])                 \
      : "r"((A)[0]), "r"((A)[1]), "r"((A)[2]), "r"((A)[3]), "r"((B)[0]),       \
        "r"((B)[1]))

__device__ __forceinline__ uint32_t bf2bits(__nv_bfloat162 v) {
  return *reinterpret_cast<uint32_t*>(&v);
}

// ---------------------------------------------------------------------------
// Split-convert fp32 -> bf16 hi/lo (row-major, same layout)
// ---------------------------------------------------------------------------
__global__ void split_convert(const float* __restrict__ X,
                              __nv_bfloat16* __restrict__ Hi,
                              __nv_bfloat16* __restrict__ Lo, int n) {
  int i = (blockIdx.x * 256 + threadIdx.x) * 4;
  if (i >= n) return;
  float4 x = *(const float4*)(X + i);
  float v[4] = {x.x, x.y, x.z, x.w};
  __nv_bfloat16 h[4], l[4];
#pragma unroll
  for (int j = 0; j < 4; j++) {
    h[j] = __float2bfloat16_rn(v[j]);
    l[j] = __float2bfloat16_rn(v[j] - __bfloat162float(h[j]));
  }
  __nv_bfloat162 h01, h23, l01, l23;
  h01.x = h[0]; h01.y = h[1]; h23.x = h[2]; h23.y = h[3];
  l01.x = l[0]; l01.y = l[1]; l23.x = l[2]; l23.y = l[3];
  *(__nv_bfloat162*)(Hi + i) = h01;
  *(__nv_bfloat162*)(Hi + i + 2) = h23;
  *(__nv_bfloat162*)(Lo + i) = l01;
  *(__nv_bfloat162*)(Lo + i + 2) = l23;
}

// ---------------------------------------------------------------------------
// Transpose-convert W[K,N] fp32 -> [N,K] bf16 hi/lo
// ---------------------------------------------------------------------------
__global__ void transpose_split(const float* __restrict__ W,
                                __nv_bfloat16* __restrict__ Hi,
                                __nv_bfloat16* __restrict__ Lo, int K, int N) {
  __shared__ float tile[32][33];
  int tx = threadIdx.x, ty = threadIdx.y;
  int k0 = blockIdx.y * 32, n0 = blockIdx.x * 32;
#pragma unroll
  for (int i = 0; i < 4; i++)
    tile[ty + i * 8][tx] = W[(size_t)(k0 + ty + i * 8) * N + n0 + tx];
  __syncthreads();
#pragma unroll
  for (int i = 0; i < 4; i++) {
    float v = tile[tx][ty + i * 8];
    __nv_bfloat16 h = __float2bfloat16_rn(v);
    __nv_bfloat16 l = __float2bfloat16_rn(v - __bfloat162float(h));
    size_t o = (size_t)(n0 + ty + i * 8) * K + k0 + tx;
    Hi[o] = h;
    Lo[o] = l;
  }
}

// ---------------------------------------------------------------------------
// HMMA bf16 split-precision GEMM with L2-friendly CTA raster swizzle.
// Groups of 8 n-blocks x all m-blocks: group working set (B-slice + A) ~50MB
// stays in L2, so DRAM traffic collapses to compulsory reads.
// ---------------------------------------------------------------------------
#define NCH (KDIM / 32)
#define MAT_BYTES 10240       // 128 * 40 * 2
#define STAGE_BYTES 40960
#define GEMM_SMEM (3 * STAGE_BYTES)  // 122880

__global__ __launch_bounds__(256, 1) void gemm_mma(
    const __nv_bfloat16* __restrict__ Ahi, const __nv_bfloat16* __restrict__ Alo,
    const __nv_bfloat16* __restrict__ Bhi, const __nv_bfloat16* __restrict__ Blo,
    float* __restrict__ C, int N) {
  extern __shared__ char smc[];
  const int tid = threadIdx.x;
  const int lane = tid & 31, wid = tid >> 5;
  const int wm = wid & 1, wn = wid >> 1;

  // raster swizzle: group = 8 n-blocks x gridDim.y m-blocks, m fastest
  const int GM = gridDim.y;
  int l = (int)blockIdx.y * (int)gridDim.x + (int)blockIdx.x;
  int gsize = GM * 8;
  int g = l / gsize, rr = l % gsize;
  const int bm = (rr % GM) * 128;
  const int bn = (g * 8 + rr / GM) * 128;

  const size_t Kb = (size_t)KDIM * 2;

  uint32_t sbase = smem_u32(smc);

  const char* gp0 = (const char*)Ahi + (size_t)bm * Kb;
  const char* gp1 = (const char*)Alo + (size_t)bm * Kb;
  const char* gp2 = (const char*)Bhi + (size_t)bn * Kb;
  const char* gp3 = (const char*)Blo + (size_t)bn * Kb;

  const int r = tid >> 2;
  const int cb = (tid & 3) * 16;

  auto load_stage = [&](int stage, int k0) {
    uint32_t sb = sbase + stage * STAGE_BYTES;
    size_t gk = (size_t)k0 * 2;
    const char* gp[4] = {gp0, gp1, gp2, gp3};
#pragma unroll
    for (int m = 0; m < 4; m++) {
      uint32_t sd = sb + m * MAT_BYTES;
#pragma unroll
      for (int j = 0; j < 2; j++) {
        int rr2 = r + j * 64;
        cp16(sd + rr2 * 80 + cb, gp[m] + (size_t)rr2 * Kb + gk + cb);
      }
    }
    asm volatile("cp.async.commit_group;" ::: "memory");
  };

  float acc[4][4][4];
#pragma unroll
  for (int a = 0; a < 4; a++)
#pragma unroll
    for (int b = 0; b < 4; b++)
#pragma unroll
      for (int c = 0; c < 4; c++) acc[a][b][c] = 0.f;

  const int arow = wm * 64 + (lane & 15);
  const int aoff = (lane >> 4) * 8;
  const int brow = wn * 32 + (lane >> 4) * 8 + (lane & 7);
  const int boff = ((lane >> 3) & 1) * 8;

  load_stage(0, 0);
  load_stage(1, 32);

  for (int i = 0; i < NCH; ++i) {
    if (i + 2 < NCH)
      asm volatile("cp.async.wait_group 1;" ::: "memory");
    else
      asm volatile("cp.async.wait_group 0;" ::: "memory");
    __syncthreads();
    if (i + 2 < NCH) load_stage((i + 2) % 3, (i + 2) * 32);

    uint32_t sb = sbase + (i % 3) * STAGE_BYTES;
    uint32_t sAh = sb;
    uint32_t sBh = sb + 2 * MAT_BYTES;

#pragma unroll
    for (int ks = 0; ks < 32; ks += 16) {
      uint32_t Ah[4][4], Al[4][4], Bh[4][2], Bl[4][2];
#pragma unroll
      for (int mi = 0; mi < 4; mi++) {
        uint32_t ad = sAh + ((arow + mi * 16) * 40 + ks + aoff) * 2;
        LDSM4(Ah[mi], ad);
        LDSM4(Al[mi], ad + MAT_BYTES);
      }
#pragma unroll
      for (int ni = 0; ni < 2; ni++) {
        uint32_t bd = sBh + ((brow + ni * 16) * 40 + ks + boff) * 2;
        uint32_t t[4];
        LDSM4(t, bd);
        Bh[ni * 2][0] = t[0]; Bh[ni * 2][1] = t[1];
        Bh[ni * 2 + 1][0] = t[2]; Bh[ni * 2 + 1][1] = t[3];
        LDSM4(t, bd + MAT_BYTES);
        Bl[ni * 2][0] = t[0]; Bl[ni * 2][1] = t[1];
        Bl[ni * 2 + 1][0] = t[2]; Bl[ni * 2 + 1][1] = t[3];
      }
#pragma unroll
      for (int mi = 0; mi < 4; mi++)
#pragma unroll
        for (int nj = 0; nj < 4; nj++) {
          MMA16816(acc[mi][nj], Ah[mi], Bh[nj]);
          MMA16816(acc[mi][nj], Ah[mi], Bl[nj]);
          MMA16816(acc[mi][nj], Al[mi], Bh[nj]);
        }
    }
  }

  const int tg = lane >> 2, tc = (lane & 3) * 2;
#pragma unroll
  for (int mi = 0; mi < 4; mi++) {
    int row = bm + wm * 64 + mi * 16 + tg;
#pragma unroll
    for (int nj = 0; nj < 4; nj++) {
      int col = bn + wn * 32 + nj * 8 + tc;
      float* p = C + (size_t)row * N + col;
      p[0] = acc[mi][nj][0];
      p[1] = acc[mi][nj][1];
      float* p2 = p + 8 * (size_t)N;
      p2[0] = acc[mi][nj][2];
      p2[1] = acc[mi][nj][3];
    }
  }
}

// ---------------------------------------------------------------------------
// RoPE + scale + bf16 split. Q gets rope+softmax scale, K gets rope, V plain.
// QKV fused layout: [s][6144] with Q at 0, K at 4096, V at 5120.
// ---------------------------------------------------------------------------
#define FA_SCALE 0.08838834764831845f

__global__ void rope_split(const float* __restrict__ QKV,
                           const float* __restrict__ cosp,
                           const float* __restrict__ sinp) {
  int idx = blockIdx.x * blockDim.x + threadIdx.x;
  const int nq = S_LEN * NQH * 64;
  const int nk = S_LEN * NKVH * 64;
  if (idx < nq) {
    int d = idx & 63;
    int h = (idx >> 6) & 31;
    int s = idx >> 11;
    const float* src = QKV + (size_t)s * NQKV + h * 128;
    float c1 = cosp[s * 128 + d], s1 = sinp[s * 128 + d];
    float c2 = cosp[s * 128 + d + 64], s2 = sinp[s * 128 + d + 64];
    float x1 = src[d], x2 = src[d + 64];
    float y1 = (x1 * c1 - x2 * s1) * FA_SCALE;
    float y2 = (x2 * c2 + x1 * s2) * FA_SCALE;
    size_t o = ((size_t)s * NQH + h) * 128 + d;
    __nv_bfloat16 h1 = __float2bfloat16_rn(y1);
    __nv_bfloat16 h2 = __float2bfloat16_rn(y2);
    g_Qh[o] = h1;
    g_Ql[o] = __float2bfloat16_rn(y1 - __bfloat162float(h1));
    g_Qh[o + 64] = h2;
    g_Ql[o + 64] = __float2bfloat16_rn(y2 - __bfloat162float(h2));
  } else if (idx < nq + nk) {
    int t = idx - nq;
    int d = t & 63;
    int h = (t >> 6) & 7;
    int s = t >> 9;
    const float* src = QKV + (size_t)s * NQKV + 4096 + h * 128;
    float c1 = cosp[s * 128 + d], s1 = sinp[s * 128 + d];
    float c2 = cosp[s * 128 + d + 64], s2 = sinp[s * 128 + d + 64];
    float x1 = src[d], x2 = src[d + 64];
    float y1 = x1 * c1 - x2 * s1;
    float y2 = x2 * c2 + x1 * s2;
    size_t o = ((size_t)s * NKVH + h) * 128 + d;
    __nv_bfloat16 h1 = __float2bfloat16_rn(y1);
    __nv_bfloat16 h2 = __float2bfloat16_rn(y2);
    g_Kh[o] = h1;
    g_Kl[o] = __float2bfloat16_rn(y1 - __bfloat162float(h1));
    g_Kh[o + 64] = h2;
    g_Kl[o + 64] = __float2bfloat16_rn(y2 - __bfloat162float(h2));
  } else if (idx < nq + 2 * nk) {
    int t = idx - nq - nk;
    int d = t & 63;
    int h = (t >> 6) & 7;
    int s = t >> 9;
    const float* src = QKV + (size_t)s * NQKV + 5120 + h * 128;
    float x1 = src[d], x2 = src[d + 64];
    size_t o = ((size_t)s * NKVH + h) * 128 + d;
    __nv_bfloat16 h1 = __float2bfloat16_rn(x1);
    __nv_bfloat16 h2 = __float2bfloat16_rn(x2);
    g_Vh[o] = h1;
    g_Vl[o] = __float2bfloat16_rn(x1 - __bfloat162float(h1));
    g_Vh[o + 64] = h2;
    g_Vl[o + 64] = __float2bfloat16_rn(x2 - __bfloat162float(h2));
  }
}

// ---------------------------------------------------------------------------
// HMMA flash attention, causal, GQA. Tile 64(M)x64(N), HD=128.
// Double-buffered KV via cp.async prefetch (overlap loads with compute).
// SMEM: Q(2 mats) + 2 x KV(4 mats) = 10 x 17408 = 174080 B.
// ---------------------------------------------------------------------------
#define FA_STRIDE 136
#define FA_MAT 17408
#define FA_SMEM (10 * FA_MAT)  // 174080

__global__ __launch_bounds__(128) void flash_mma(
    const __nv_bfloat16* __restrict__ Qh_, const __nv_bfloat16* __restrict__ Ql_,
    const __nv_bfloat16* __restrict__ Kh_, const __nv_bfloat16* __restrict__ Kl_,
    const __nv_bfloat16* __restrict__ Vh_, const __nv_bfloat16* __restrict__ Vl_,
    float* __restrict__ Ctx) {
  extern __shared__ char smf[];
  const uint32_t sb = smem_u32(smf);
  const uint32_t sQh = sb;

  const int tid = threadIdx.x;
  const int lane = tid & 31, w = tid >> 5;
  const int qb = (int)gridDim.x - 1 - (int)blockIdx.x;
  const int hq = blockIdx.y, hkv = hq >> 2;

  auto load_kv = [&](int kb, int buf) {
    uint32_t sK = sb + (2 + 4 * buf) * FA_MAT;
    uint32_t sV = sK + 2 * FA_MAT;
#pragma unroll
    for (int j = 0; j < 8; j++) {
      int idx = tid + j * 128;
      int r = idx >> 4;
      int c = (idx & 15) * 16;
      size_t g = ((size_t)(kb * 64 + r) * NKVH + hkv) * 256 + c;
      uint32_t d = r * (FA_STRIDE * 2) + c;
      cp16(sK + d, (const char*)Kh_ + g);
      cp16(sK + FA_MAT + d, (const char*)Kl_ + g);
      cp16(sV + d, (const char*)Vh_ + g);
      cp16(sV + FA_MAT + d, (const char*)Vl_ + g);
    }
    asm volatile("cp.async.commit_group;" ::: "memory");
  };

  // Q tile (hi+lo) + KV(0) in group 0
#pragma unroll
  for (int j = 0; j < 8; j++) {
    int idx = tid + j * 128;
    int r = idx >> 4;
    int c = (idx & 15) * 16;
    size_t g = ((size_t)(qb * 64 + r) * NQH + hq) * 256 + c;
    uint32_t d = r * (FA_STRIDE * 2) + c;
    cp16(sQh + d, (const char*)Qh_ + g);
    cp16(sQh + FA_MAT + d, (const char*)Ql_ + g);
  }
  load_kv(0, 0);  // commits Q + KV0 together

  float o[16][4];
#pragma unroll
  for (int t = 0; t < 16; t++)
#pragma unroll
    for (int c = 0; c < 4; c++) o[t][c] = 0.f;
  float m0 = -1e30f, m1 = -1e30f, l0 = 0.f, l1 = 0.f;

  const int arow = w * 16 + (lane & 15);
  const int aoff = (lane >> 4) * 8;
  const int bRow = (lane >> 4) * 8 + (lane & 7);
  const int bCol = ((lane >> 3) & 1) * 8;
  const int vRow = (lane & 7) + ((lane >> 3) & 1) * 8;
  const int vCol = (lane >> 4) * 8;
  const int rloc = w * 16 + (lane >> 2);

  for (int kb = 0; kb <= qb; ++kb) {
    const int buf = kb & 1;
    const uint32_t sKh = sb + (2 + 4 * buf) * FA_MAT;
    const uint32_t sVh = sKh + 2 * FA_MAT;

    if (kb + 1 <= qb) {
      load_kv(kb + 1, buf ^ 1);
      asm volatile("cp.async.wait_group 1;" ::: "memory");
    } else {
      asm volatile("cp.async.wait_group 0;" ::: "memory");
    }
    __syncthreads();

    // S = Q @ K^T
    float sacc[8][4];
#pragma unroll
    for (int t = 0; t < 8; t++)
#pragma unroll
      for (int c = 0; c < 4; c++) sacc[t][c] = 0.f;

#pragma unroll
    for (int kk = 0; kk < 8; ++kk) {
      uint32_t qh[4], ql[4];
      uint32_t qa = sQh + (arow * FA_STRIDE + kk * 16 + aoff) * 2;
      LDSM4(qh, qa);
      LDSM4(ql, qa + FA_MAT);
#pragma unroll
      for (int np = 0; np < 4; np++) {
        uint32_t ka = sKh + ((np * 16 + bRow) * FA_STRIDE + kk * 16 + bCol) * 2;
        uint32_t kh[4], kl[4];
        LDSM4(kh, ka);
        LDSM4(kl, ka + FA_MAT);
        MMA16816(sacc[2 * np], qh, kh);
        MMA16816(sacc[2 * np], qh, kl);
        MMA16816(sacc[2 * np], ql, kh);
        MMA16816(sacc[2 * np + 1], qh, kh + 2);
        MMA16816(sacc[2 * np + 1], qh, kl + 2);
        MMA16816(sacc[2 * np + 1], ql, kh + 2);
      }
    }

    if (kb == qb) {
#pragma unroll
      for (int t = 0; t < 8; t++) {
        int n = t * 8 + (lane & 3) * 2;
        if (n > rloc) sacc[t][0] = -1e30f;
        if (n + 1 > rloc) sacc[t][1] = -1e30f;
        if (n > rloc + 8) sacc[t][2] = -1e30f;
        if (n + 1 > rloc + 8) sacc[t][3] = -1e30f;
      }
    }

    float mx0 = -1e30f, mx1 = -1e30f;
#pragma unroll
    for (int t = 0; t < 8; t++) {
      mx0 = fmaxf(mx0, fmaxf(sacc[t][0], sacc[t][1]));
      mx1 = fmaxf(mx1, fmaxf(sacc[t][2], sacc[t][3]));
    }
    mx0 = fmaxf(mx0, __shfl_xor_sync(0xffffffffu, mx0, 1));
    mx0 = fmaxf(mx0, __shfl_xor_sync(0xffffffffu, mx0, 2));
    mx1 = fmaxf(mx1, __shfl_xor_sync(0xffffffffu, mx1, 1));
    mx1 = fmaxf(mx1, __shfl_xor_sync(0xffffffffu, mx1, 2));
    float mn0 = fmaxf(m0, mx0), mn1 = fmaxf(m1, mx1);
    float al0 = __expf(m0 - mn0), al1 = __expf(m1 - mn1);
    m0 = mn0;
    m1 = mn1;
    float sum0 = 0.f, sum1 = 0.f;
#pragma unroll
    for (int t = 0; t < 8; t++) {
      sacc[t][0] = __expf(sacc[t][0] - m0);
      sacc[t][1] = __expf(sacc[t][1] - m0);
      sacc[t][2] = __expf(sacc[t][2] - m1);
      sacc[t][3] = __expf(sacc[t][3] - m1);
      sum0 += sacc[t][0] + sacc[t][1];
      sum1 += sacc[t][2] + sacc[t][3];
    }
    sum0 += __shfl_xor_sync(0xffffffffu, sum0, 1);
    sum0 += __shfl_xor_sync(0xffffffffu, sum0, 2);
    sum1 += __shfl_xor_sync(0xffffffffu, sum1, 1);
    sum1 += __shfl_xor_sync(0xffffffffu, sum1, 2);
    l0 = l0 * al0 + sum0;
    l1 = l1 * al1 + sum1;
#pragma unroll
    for (int t = 0; t < 16; t++) {
      o[t][0] *= al0;
      o[t][1] *= al0;
      o[t][2] *= al1;
      o[t][3] *= al1;
    }

    // O += P @ V
#pragma unroll
    for (int j = 0; j < 4; j++) {
      uint32_t pha[4], pla[4];
      {
        __nv_bfloat162 h01 = __floats2bfloat162_rn(sacc[2 * j][0], sacc[2 * j][1]);
        __nv_bfloat162 h23 = __floats2bfloat162_rn(sacc[2 * j][2], sacc[2 * j][3]);
        pha[0] = bf2bits(h01);
        pha[1] = bf2bits(h23);
        pla[0] = bf2bits(__floats2bfloat162_rn(
            sacc[2 * j][0] - __low2float(h01), sacc[2 * j][1] - __high2float(h01)));
        pla[1] = bf2bits(__floats2bfloat162_rn(
            sacc[2 * j][2] - __low2float(h23), sacc[2 * j][3] - __high2float(h23)));
        __nv_bfloat162 g01 =
            __floats2bfloat162_rn(sacc[2 * j + 1][0], sacc[2 * j + 1][1]);
        __nv_bfloat162 g23 =
            __floats2bfloat162_rn(sacc[2 * j + 1][2], sacc[2 * j + 1][3]);
        pha[2] = bf2bits(g01);
        pha[3] = bf2bits(g23);
        pla[2] = bf2bits(__floats2bfloat162_rn(sacc[2 * j + 1][0] - __low2float(g01),
                                               sacc[2 * j + 1][1] - __high2float(g01)));
        pla[3] = bf2bits(__floats2bfloat162_rn(sacc[2 * j + 1][2] - __low2float(g23),
                                               sacc[2 * j + 1][3] - __high2float(g23)));
      }
#pragma unroll
      for (int np = 0; np < 8; np++) {
        uint32_t va = sVh + ((j * 16 + vRow) * FA_STRIDE + np * 16 + vCol) * 2;
        uint32_t vh[4], vl[4];
        LDSM4T(vh, va);
        LDSM4T(vl, va + FA_MAT);
        MMA16816(o[2 * np], pha, vh);
        MMA16816(o[2 * np], pha, vl);
        MMA16816(o[2 * np], pla, vh);
        MMA16816(o[2 * np + 1], pha, vh + 2);
        MMA16816(o[2 * np + 1], pha, vl + 2);
        MMA16816(o[2 * np + 1], pla, vh + 2);
      }
    }
    __syncthreads();  // all warps done with buffers before next prefetch
  }

  float inv0 = 1.0f / l0, inv1 = 1.0f / l1;
  int r0 = qb * 64 + rloc;
#pragma unroll
  for (int t = 0; t < 16; t++) {
    int col = t * 8 + (lane & 3) * 2;
    float* p0 = Ctx + ((size_t)r0 * NQH + hq) * 128 + col;
    *(float2*)p0 = make_float2(o[t][0] * inv0, o[t][1] * inv0);
    float* p1 = Ctx + ((size_t)(r0 + 8) * NQH + hq) * 128 + col;
    *(float2*)p1 = make_float2(o[t][2] * inv1, o[t][3] * inv1);
  }
}

// ---------------------------------------------------------------------------
// Launch
// ---------------------------------------------------------------------------
extern "C" void kernel_launch(void* const* d_in, const int* in_sizes, int n_in,
                              void* d_out, int out_size) {
  const float* X = (const float*)d_in[0];
  const float* cosp = (const float*)d_in[1];
  const float* sinp = (const float*)d_in[2];
  const float* wq = (const float*)d_in[3];
  const float* wk = (const float*)d_in[4];
  const float* wv = (const float*)d_in[5];
  const float* wo = (const float*)d_in[6];
  float* out = (float*)d_out;

  float *QKV, *Ctx;
  __nv_bfloat16 *Ahi, *Alo, *Bhi, *Blo, *Qh, *Ql, *Kh, *Kl, *Vh, *Vl;
  cudaGetSymbolAddress((void**)&QKV, g_QKV);
  cudaGetSymbolAddress((void**)&Ctx, g_Ctx);
  cudaGetSymbolAddress((void**)&Ahi, g_Ahi);
  cudaGetSymbolAddress((void**)&Alo, g_Alo);
  cudaGetSymbolAddress((void**)&Bhi, g_Bhi);
  cudaGetSymbolAddress((void**)&Blo, g_Blo);
  cudaGetSymbolAddress((void**)&Qh, g_Qh);
  cudaGetSymbolAddress((void**)&Ql, g_Ql);
  cudaGetSymbolAddress((void**)&Kh, g_Kh);
  cudaGetSymbolAddress((void**)&Kl, g_Kl);
  cudaGetSymbolAddress((void**)&Vh, g_Vh);
  cudaGetSymbolAddress((void**)&Vl, g_Vl);

  cudaFuncSetAttribute(gemm_mma, cudaFuncAttributeMaxDynamicSharedMemorySize,
                       GEMM_SMEM);
  cudaFuncSetAttribute(flash_mma, cudaFuncAttributeMaxDynamicSharedMemorySize,
                       FA_SMEM);

  dim3 blk(256);
  dim3 tblk(32, 8);

  // Activations -> bf16 split
  split_convert<<<(S_LEN * KDIM / 4 + 255) / 256, 256>>>(X, Ahi, Alo,
                                                         S_LEN * KDIM);
  // Fused QKV weights -> [N,K] bf16 split
  transpose_split<<<dim3(128, 128), tblk>>>(wq, Bhi, Blo, KDIM, 4096);
  transpose_split<<<dim3(32, 128), tblk>>>(wk, Bhi + (size_t)4096 * KDIM,
                                           Blo + (size_t)4096 * KDIM, KDIM, 1024);
  transpose_split<<<dim3(32, 128), tblk>>>(wv, Bhi + (size_t)5120 * KDIM,
                                           Blo + (size_t)5120 * KDIM, KDIM, 1024);
  // Fused QKV projection
  gemm_mma<<<dim3(48, 16), blk, GEMM_SMEM>>>(Ahi, Alo, Bhi, Blo, QKV, NQKV);
  // RoPE + scale + split for attention
  int rtot = S_LEN * NQH * 64 + 2 * S_LEN * NKVH * 64;
  rope_split<<<(rtot + 255) / 256, 256>>>(QKV, cosp, sinp);
  // Attention (HMMA, double-buffered)
  flash_mma<<<dim3(32, 32), dim3(128), FA_SMEM>>>(Qh, Ql, Kh, Kl, Vh, Vl, Ctx);
  // Output projection
  split_convert<<<(S_LEN * KDIM / 4 + 255) / 256, 256>>>(Ctx, Ahi, Alo,
                                                         S_LEN * KDIM);
  transpose_split<<<dim3(128, 128), tblk>>>(wo, Bhi, Blo, KDIM, 4096);
  gemm_mma<<<dim3(32, 16), blk, GEMM_SMEM>>>(Ahi, Alo, Bhi, Blo, out, 4096);
}

// round 10
// speedup vs baseline: 1.6473x; 1.6473x over previous
#include <cuda_runtime.h>
#include <cuda_bf16.h>
#include <math.h>
#include <stdint.h>

#define S_LEN 2048
#define H_DIM 4096
#define NQH 32
#define NKVH 8
#define HDIM 128
#define KDIM 4096
#define NQKV 6144

// ---------------------------------------------------------------------------
// Scratch (device globals; no allocation allowed)
// ---------------------------------------------------------------------------
__device__ float g_QKV[S_LEN * NQKV];
__device__ float g_Ctx[S_LEN * H_DIM];

__device__ __nv_bfloat16 g_Ahi[S_LEN * KDIM];
__device__ __nv_bfloat16 g_Alo[S_LEN * KDIM];
__device__ __nv_bfloat16 g_Bhi[NQKV * KDIM];
__device__ __nv_bfloat16 g_Blo[NQKV * KDIM];

__device__ __nv_bfloat16 g_Qh[S_LEN * NQH * HDIM];
__device__ __nv_bfloat16 g_Ql[S_LEN * NQH * HDIM];
__device__ __nv_bfloat16 g_Kh[S_LEN * NKVH * HDIM];
__device__ __nv_bfloat16 g_Kl[S_LEN * NKVH * HDIM];
__device__ __nv_bfloat16 g_Vh[S_LEN * NKVH * HDIM];
__device__ __nv_bfloat16 g_Vl[S_LEN * NKVH * HDIM];

// ---------------------------------------------------------------------------
// Helpers
// ---------------------------------------------------------------------------
__device__ __forceinline__ uint32_t smem_u32(const void* p) {
  uint32_t a;
  asm("{ .reg .u64 t; cvta.to.shared.u64 t, %1; cvt.u32.u64 %0, t; }"
      : "=r"(a) : "l"(p));
  return a;
}

__device__ __forceinline__ void cp16(uint32_t dst, const void* src) {
  asm volatile("cp.async.cg.shared.global [%0], [%1], 16;" ::"r"(dst), "l"(src));
}

#define LDSM4(R, ADDR)                                                         \
  asm volatile("ldmatrix.sync.aligned.m8n8.x4.shared.b16 {%0,%1,%2,%3}, [%4];" \
               : "=r"((R)[0]), "=r"((R)[1]), "=r"((R)[2]), "=r"((R)[3])        \
               : "r"(ADDR))

#define LDSM4T(R, ADDR)                                                        \
  asm volatile(                                                                \
      "ldmatrix.sync.aligned.m8n8.x4.trans.shared.b16 {%0,%1,%2,%3}, [%4];"    \
      : "=r"((R)[0]), "=r"((R)[1]), "=r"((R)[2]), "=r"((R)[3])                 \
      : "r"(ADDR))

#define MMA16816(D, A, B)                                                      \
  asm volatile(                                                                \
      "mma.sync.aligned.m16n8k16.row.col.f32.bf16.bf16.f32 "                   \
      "{%0,%1,%2,%3}, {%4,%5,%6,%7}, {%8,%9}, {%0,%1,%2,%3};"                  \
      : "+f"((D)[0]), "+f"((D)[1]), "+f"((D)[2]), "+f"((D)[3])                 \
      : "r"((A)[0]), "r"((A)[1]), "r"((A)[2]), "r"((A)[3]), "r"((B)[0]),       \
        "r"((B)[1]))

__device__ __forceinline__ uint32_t bf2bits(__nv_bfloat162 v) {
  return *reinterpret_cast<uint32_t*>(&v);
}

// ---------------------------------------------------------------------------
// Split-convert fp32 -> bf16 hi/lo
// ---------------------------------------------------------------------------
__global__ void split_convert(const float* __restrict__ X,
                              __nv_bfloat16* __restrict__ Hi,
                              __nv_bfloat16* __restrict__ Lo, int n) {
  int i = (blockIdx.x * 256 + threadIdx.x) * 4;
  if (i >= n) return;
  float4 x = *(const float4*)(X + i);
  float v[4] = {x.x, x.y, x.z, x.w};
  __nv_bfloat16 h[4], l[4];
#pragma unroll
  for (int j = 0; j < 4; j++) {
    h[j] = __float2bfloat16_rn(v[j]);
    l[j] = __float2bfloat16_rn(v[j] - __bfloat162float(h[j]));
  }
  __nv_bfloat162 h01, h23, l01, l23;
  h01.x = h[0]; h01.y = h[1]; h23.x = h[2]; h23.y = h[3];
  l01.x = l[0]; l01.y = l[1]; l23.x = l[2]; l23.y = l[3];
  *(__nv_bfloat162*)(Hi + i) = h01;
  *(__nv_bfloat162*)(Hi + i + 2) = h23;
  *(__nv_bfloat162*)(Lo + i) = l01;
  *(__nv_bfloat162*)(Lo + i + 2) = l23;
}

// ---------------------------------------------------------------------------
// Transpose-convert W[K,N] fp32 -> [N,K] bf16 hi/lo
// ---------------------------------------------------------------------------
__global__ void transpose_split(const float* __restrict__ W,
                                __nv_bfloat16* __restrict__ Hi,
                                __nv_bfloat16* __restrict__ Lo, int K, int N) {
  __shared__ float tile[32][33];
  int tx = threadIdx.x, ty = threadIdx.y;
  int k0 = blockIdx.y * 32, n0 = blockIdx.x * 32;
#pragma unroll
  for (int i = 0; i < 4; i++)
    tile[ty + i * 8][tx] = W[(size_t)(k0 + ty + i * 8) * N + n0 + tx];
  __syncthreads();
#pragma unroll
  for (int i = 0; i < 4; i++) {
    float v = tile[tx][ty + i * 8];
    __nv_bfloat16 h = __float2bfloat16_rn(v);
    __nv_bfloat16 l = __float2bfloat16_rn(v - __bfloat162float(h));
    size_t o = (size_t)(n0 + ty + i * 8) * K + k0 + tx;
    Hi[o] = h;
    Lo[o] = l;
  }
}

// ---------------------------------------------------------------------------
// HMMA bf16 split-precision GEMM. 2-stage cp.async pipeline, 2 CTAs/SM
// (16 warps/SM) for latency hiding. Register-lean inner loop (B hoisted,
// A loaded per-mi) to fit the 128-reg cap without spills.
// ---------------------------------------------------------------------------
#define NCH (KDIM / 32)
#define MAT_BYTES 10240       // 128 * 40 * 2
#define STAGE_BYTES 40960
#define GEMM_SMEM (2 * STAGE_BYTES)  // 81920 -> 2 CTAs/SM

__global__ __launch_bounds__(256, 2) void gemm_mma(
    const __nv_bfloat16* __restrict__ Ahi, const __nv_bfloat16* __restrict__ Alo,
    const __nv_bfloat16* __restrict__ Bhi, const __nv_bfloat16* __restrict__ Blo,
    float* __restrict__ C, int N) {
  extern __shared__ char smc[];
  const int tid = threadIdx.x;
  const int lane = tid & 31, wid = tid >> 5;
  const int wm = wid & 1, wn = wid >> 1;
  const int bm = blockIdx.y * 128, bn = blockIdx.x * 128;
  const size_t Kb = (size_t)KDIM * 2;

  uint32_t sbase = smem_u32(smc);

  const char* gp0 = (const char*)Ahi + (size_t)bm * Kb;
  const char* gp1 = (const char*)Alo + (size_t)bm * Kb;
  const char* gp2 = (const char*)Bhi + (size_t)bn * Kb;
  const char* gp3 = (const char*)Blo + (size_t)bn * Kb;

  const int r = tid >> 2;
  const int cb = (tid & 3) * 16;

  auto load_stage = [&](int stage, int k0) {
    uint32_t sb = sbase + stage * STAGE_BYTES;
    size_t gk = (size_t)k0 * 2;
    const char* gp[4] = {gp0, gp1, gp2, gp3};
#pragma unroll
    for (int m = 0; m < 4; m++) {
      uint32_t sd = sb + m * MAT_BYTES;
#pragma unroll
      for (int j = 0; j < 2; j++) {
        int rr = r + j * 64;
        cp16(sd + rr * 80 + cb, gp[m] + (size_t)rr * Kb + gk + cb);
      }
    }
    asm volatile("cp.async.commit_group;" ::: "memory");
  };

  float acc[4][4][4];
#pragma unroll
  for (int a = 0; a < 4; a++)
#pragma unroll
    for (int b = 0; b < 4; b++)
#pragma unroll
      for (int c = 0; c < 4; c++) acc[a][b][c] = 0.f;

  const int arow = wm * 64 + (lane & 15);
  const int aoff = (lane >> 4) * 8;
  const int brow = wn * 32 + (lane >> 4) * 8 + (lane & 7);
  const int boff = ((lane >> 3) & 1) * 8;

  load_stage(0, 0);

  for (int i = 0; i < NCH; ++i) {
    if (i + 1 < NCH) {
      load_stage((i + 1) & 1, (i + 1) * 32);
      asm volatile("cp.async.wait_group 1;" ::: "memory");
    } else {
      asm volatile("cp.async.wait_group 0;" ::: "memory");
    }
    __syncthreads();

    uint32_t sb = sbase + (i & 1) * STAGE_BYTES;
    uint32_t sAh = sb;
    uint32_t sBh = sb + 2 * MAT_BYTES;

#pragma unroll
    for (int ks = 0; ks < 32; ks += 16) {
      // B fragments for all 4 n-tiles (hoisted; 16 live regs)
      uint32_t Bh[4][2], Bl[4][2];
#pragma unroll
      for (int ni = 0; ni < 2; ni++) {
        uint32_t bd = sBh + ((brow + ni * 16) * 40 + ks + boff) * 2;
        uint32_t t[4];
        LDSM4(t, bd);
        Bh[ni * 2][0] = t[0]; Bh[ni * 2][1] = t[1];
        Bh[ni * 2 + 1][0] = t[2]; Bh[ni * 2 + 1][1] = t[3];
        LDSM4(t, bd + MAT_BYTES);
        Bl[ni * 2][0] = t[0]; Bl[ni * 2][1] = t[1];
        Bl[ni * 2 + 1][0] = t[2]; Bl[ni * 2 + 1][1] = t[3];
      }
      // A fragments per m-tile (8 live regs at a time)
#pragma unroll
      for (int mi = 0; mi < 4; mi++) {
        uint32_t ad = sAh + ((arow + mi * 16) * 40 + ks + aoff) * 2;
        uint32_t Ah[4], Al[4];
        LDSM4(Ah, ad);
        LDSM4(Al, ad + MAT_BYTES);
#pragma unroll
        for (int nj = 0; nj < 4; nj++) {
          MMA16816(acc[mi][nj], Ah, Bh[nj]);
          MMA16816(acc[mi][nj], Ah, Bl[nj]);
          MMA16816(acc[mi][nj], Al, Bh[nj]);
        }
      }
    }
    __syncthreads();
  }

  const int tg = lane >> 2, tc = (lane & 3) * 2;
#pragma unroll
  for (int mi = 0; mi < 4; mi++) {
    int row = bm + wm * 64 + mi * 16 + tg;
#pragma unroll
    for (int nj = 0; nj < 4; nj++) {
      int col = bn + wn * 32 + nj * 8 + tc;
      float* p = C + (size_t)row * N + col;
      p[0] = acc[mi][nj][0];
      p[1] = acc[mi][nj][1];
      float* p2 = p + 8 * (size_t)N;
      p2[0] = acc[mi][nj][2];
      p2[1] = acc[mi][nj][3];
    }
  }
}

// ---------------------------------------------------------------------------
// RoPE + scale + bf16 split. Q gets rope+softmax scale, K gets rope, V plain.
// ---------------------------------------------------------------------------
#define FA_SCALE 0.08838834764831845f

__global__ void rope_split(const float* __restrict__ QKV,
                           const float* __restrict__ cosp,
                           const float* __restrict__ sinp) {
  int idx = blockIdx.x * blockDim.x + threadIdx.x;
  const int nq = S_LEN * NQH * 64;
  const int nk = S_LEN * NKVH * 64;
  if (idx < nq) {
    int d = idx & 63;
    int h = (idx >> 6) & 31;
    int s = idx >> 11;
    const float* src = QKV + (size_t)s * NQKV + h * 128;
    float c1 = cosp[s * 128 + d], s1 = sinp[s * 128 + d];
    float c2 = cosp[s * 128 + d + 64], s2 = sinp[s * 128 + d + 64];
    float x1 = src[d], x2 = src[d + 64];
    float y1 = (x1 * c1 - x2 * s1) * FA_SCALE;
    float y2 = (x2 * c2 + x1 * s2) * FA_SCALE;
    size_t o = ((size_t)s * NQH + h) * 128 + d;
    __nv_bfloat16 h1 = __float2bfloat16_rn(y1);
    __nv_bfloat16 h2 = __float2bfloat16_rn(y2);
    g_Qh[o] = h1;
    g_Ql[o] = __float2bfloat16_rn(y1 - __bfloat162float(h1));
    g_Qh[o + 64] = h2;
    g_Ql[o + 64] = __float2bfloat16_rn(y2 - __bfloat162float(h2));
  } else if (idx < nq + nk) {
    int t = idx - nq;
    int d = t & 63;
    int h = (t >> 6) & 7;
    int s = t >> 9;
    const float* src = QKV + (size_t)s * NQKV + 4096 + h * 128;
    float c1 = cosp[s * 128 + d], s1 = sinp[s * 128 + d];
    float c2 = cosp[s * 128 + d + 64], s2 = sinp[s * 128 + d + 64];
    float x1 = src[d], x2 = src[d + 64];
    float y1 = x1 * c1 - x2 * s1;
    float y2 = x2 * c2 + x1 * s2;
    size_t o = ((size_t)s * NKVH + h) * 128 + d;
    __nv_bfloat16 h1 = __float2bfloat16_rn(y1);
    __nv_bfloat16 h2 = __float2bfloat16_rn(y2);
    g_Kh[o] = h1;
    g_Kl[o] = __float2bfloat16_rn(y1 - __bfloat162float(h1));
    g_Kh[o + 64] = h2;
    g_Kl[o + 64] = __float2bfloat16_rn(y2 - __bfloat162float(h2));
  } else if (idx < nq + 2 * nk) {
    int t = idx - nq - nk;
    int d = t & 63;
    int h = (t >> 6) & 7;
    int s = t >> 9;
    const float* src = QKV + (size_t)s * NQKV + 5120 + h * 128;
    float x1 = src[d], x2 = src[d + 64];
    size_t o = ((size_t)s * NKVH + h) * 128 + d;
    __nv_bfloat16 h1 = __float2bfloat16_rn(x1);
    __nv_bfloat16 h2 = __float2bfloat16_rn(x2);
    g_Vh[o] = h1;
    g_Vl[o] = __float2bfloat16_rn(x1 - __bfloat162float(h1));
    g_Vh[o + 64] = h2;
    g_Vl[o + 64] = __float2bfloat16_rn(x2 - __bfloat162float(h2));
  }
}

// ---------------------------------------------------------------------------
// HMMA flash attention (round-7 version: single KV buffer, 104KB -> 2 CTAs/SM)
// ---------------------------------------------------------------------------
#define FA_STRIDE 136
#define FA_MAT 17408
#define FA_SMEM (6 * FA_MAT)  // 104448

__global__ __launch_bounds__(128) void flash_mma(
    const __nv_bfloat16* __restrict__ Qh_, const __nv_bfloat16* __restrict__ Ql_,
    const __nv_bfloat16* __restrict__ Kh_, const __nv_bfloat16* __restrict__ Kl_,
    const __nv_bfloat16* __restrict__ Vh_, const __nv_bfloat16* __restrict__ Vl_,
    float* __restrict__ Ctx) {
  extern __shared__ char smf[];
  const uint32_t sb = smem_u32(smf);
  const uint32_t sQh = sb;
  const uint32_t sKh = sb + 2 * FA_MAT;
  const uint32_t sVh = sb + 4 * FA_MAT;

  const int tid = threadIdx.x;
  const int lane = tid & 31, w = tid >> 5;
  const int qb = (int)gridDim.x - 1 - (int)blockIdx.x;
  const int hq = blockIdx.y, hkv = hq >> 2;

#pragma unroll
  for (int j = 0; j < 8; j++) {
    int idx = tid + j * 128;
    int r = idx >> 4;
    int c = (idx & 15) * 16;
    size_t g = ((size_t)(qb * 64 + r) * NQH + hq) * 256 + c;
    uint32_t d = r * (FA_STRIDE * 2) + c;
    cp16(sQh + d, (const char*)Qh_ + g);
    cp16(sQh + FA_MAT + d, (const char*)Ql_ + g);
  }
  asm volatile("cp.async.commit_group;" ::: "memory");

  float o[16][4];
#pragma unroll
  for (int t = 0; t < 16; t++)
#pragma unroll
    for (int c = 0; c < 4; c++) o[t][c] = 0.f;
  float m0 = -1e30f, m1 = -1e30f, l0 = 0.f, l1 = 0.f;

  const int arow = w * 16 + (lane & 15);
  const int aoff = (lane >> 4) * 8;
  const int bRow = (lane >> 4) * 8 + (lane & 7);
  const int bCol = ((lane >> 3) & 1) * 8;
  const int vRow = (lane & 7) + ((lane >> 3) & 1) * 8;
  const int vCol = (lane >> 4) * 8;
  const int rloc = w * 16 + (lane >> 2);

  for (int kb = 0; kb <= qb; ++kb) {
#pragma unroll
    for (int j = 0; j < 8; j++) {
      int idx = tid + j * 128;
      int r = idx >> 4;
      int c = (idx & 15) * 16;
      size_t g = ((size_t)(kb * 64 + r) * NKVH + hkv) * 256 + c;
      uint32_t d = r * (FA_STRIDE * 2) + c;
      cp16(sKh + d, (const char*)Kh_ + g);
      cp16(sKh + FA_MAT + d, (const char*)Kl_ + g);
      cp16(sVh + d, (const char*)Vh_ + g);
      cp16(sVh + FA_MAT + d, (const char*)Vl_ + g);
    }
    asm volatile("cp.async.commit_group;" ::: "memory");
    asm volatile("cp.async.wait_group 0;" ::: "memory");
    __syncthreads();

    float sacc[8][4];
#pragma unroll
    for (int t = 0; t < 8; t++)
#pragma unroll
      for (int c = 0; c < 4; c++) sacc[t][c] = 0.f;

#pragma unroll
    for (int kk = 0; kk < 8; ++kk) {
      uint32_t qh[4], ql[4];
      uint32_t qa = sQh + (arow * FA_STRIDE + kk * 16 + aoff) * 2;
      LDSM4(qh, qa);
      LDSM4(ql, qa + FA_MAT);
#pragma unroll
      for (int np = 0; np < 4; np++) {
        uint32_t ka = sKh + ((np * 16 + bRow) * FA_STRIDE + kk * 16 + bCol) * 2;
        uint32_t kh[4], kl[4];
        LDSM4(kh, ka);
        LDSM4(kl, ka + FA_MAT);
        MMA16816(sacc[2 * np], qh, kh);
        MMA16816(sacc[2 * np], qh, kl);
        MMA16816(sacc[2 * np], ql, kh);
        MMA16816(sacc[2 * np + 1], qh, kh + 2);
        MMA16816(sacc[2 * np + 1], qh, kl + 2);
        MMA16816(sacc[2 * np + 1], ql, kh + 2);
      }
    }

    if (kb == qb) {
#pragma unroll
      for (int t = 0; t < 8; t++) {
        int n = t * 8 + (lane & 3) * 2;
        if (n > rloc) sacc[t][0] = -1e30f;
        if (n + 1 > rloc) sacc[t][1] = -1e30f;
        if (n > rloc + 8) sacc[t][2] = -1e30f;
        if (n + 1 > rloc + 8) sacc[t][3] = -1e30f;
      }
    }

    float mx0 = -1e30f, mx1 = -1e30f;
#pragma unroll
    for (int t = 0; t < 8; t++) {
      mx0 = fmaxf(mx0, fmaxf(sacc[t][0], sacc[t][1]));
      mx1 = fmaxf(mx1, fmaxf(sacc[t][2], sacc[t][3]));
    }
    mx0 = fmaxf(mx0, __shfl_xor_sync(0xffffffffu, mx0, 1));
    mx0 = fmaxf(mx0, __shfl_xor_sync(0xffffffffu, mx0, 2));
    mx1 = fmaxf(mx1, __shfl_xor_sync(0xffffffffu, mx1, 1));
    mx1 = fmaxf(mx1, __shfl_xor_sync(0xffffffffu, mx1, 2));
    float mn0 = fmaxf(m0, mx0), mn1 = fmaxf(m1, mx1);
    float al0 = __expf(m0 - mn0), al1 = __expf(m1 - mn1);
    m0 = mn0;
    m1 = mn1;
    float sum0 = 0.f, sum1 = 0.f;
#pragma unroll
    for (int t = 0; t < 8; t++) {
      sacc[t][0] = __expf(sacc[t][0] - m0);
      sacc[t][1] = __expf(sacc[t][1] - m0);
      sacc[t][2] = __expf(sacc[t][2] - m1);
      sacc[t][3] = __expf(sacc[t][3] - m1);
      sum0 += sacc[t][0] + sacc[t][1];
      sum1 += sacc[t][2] + sacc[t][3];
    }
    sum0 += __shfl_xor_sync(0xffffffffu, sum0, 1);
    sum0 += __shfl_xor_sync(0xffffffffu, sum0, 2);
    sum1 += __shfl_xor_sync(0xffffffffu, sum1, 1);
    sum1 += __shfl_xor_sync(0xffffffffu, sum1, 2);
    l0 = l0 * al0 + sum0;
    l1 = l1 * al1 + sum1;
#pragma unroll
    for (int t = 0; t < 16; t++) {
      o[t][0] *= al0;
      o[t][1] *= al0;
      o[t][2] *= al1;
      o[t][3] *= al1;
    }

#pragma unroll
    for (int j = 0; j < 4; j++) {
      uint32_t pha[4], pla[4];
      {
        __nv_bfloat162 h01 = __floats2bfloat162_rn(sacc[2 * j][0], sacc[2 * j][1]);
        __nv_bfloat162 h23 = __floats2bfloat162_rn(sacc[2 * j][2], sacc[2 * j][3]);
        pha[0] = bf2bits(h01);
        pha[1] = bf2bits(h23);
        pla[0] = bf2bits(__floats2bfloat162_rn(
            sacc[2 * j][0] - __low2float(h01), sacc[2 * j][1] - __high2float(h01)));
        pla[1] = bf2bits(__floats2bfloat162_rn(
            sacc[2 * j][2] - __low2float(h23), sacc[2 * j][3] - __high2float(h23)));
        __nv_bfloat162 g01 =
            __floats2bfloat162_rn(sacc[2 * j + 1][0], sacc[2 * j + 1][1]);
        __nv_bfloat162 g23 =
            __floats2bfloat162_rn(sacc[2 * j + 1][2], sacc[2 * j + 1][3]);
        pha[2] = bf2bits(g01);
        pha[3] = bf2bits(g23);
        pla[2] = bf2bits(__floats2bfloat162_rn(sacc[2 * j + 1][0] - __low2float(g01),
                                               sacc[2 * j + 1][1] - __high2float(g01)));
        pla[3] = bf2bits(__floats2bfloat162_rn(sacc[2 * j + 1][2] - __low2float(g23),
                                               sacc[2 * j + 1][3] - __high2float(g23)));
      }
#pragma unroll
      for (int np = 0; np < 8; np++) {
        uint32_t va = sVh + ((j * 16 + vRow) * FA_STRIDE + np * 16 + vCol) * 2;
        uint32_t vh[4], vl[4];
        LDSM4T(vh, va);
        LDSM4T(vl, va + FA_MAT);
        MMA16816(o[2 * np], pha, vh);
        MMA16816(o[2 * np], pha, vl);
        MMA16816(o[2 * np], pla, vh);
        MMA16816(o[2 * np + 1], pha, vh + 2);
        MMA16816(o[2 * np + 1], pha, vl + 2);
        MMA16816(o[2 * np + 1], pla, vh + 2);
      }
    }
    __syncthreads();
  }

  float inv0 = 1.0f / l0, inv1 = 1.0f / l1;
  int r0 = qb * 64 + rloc;
#pragma unroll
  for (int t = 0; t < 16; t++) {
    int col = t * 8 + (lane & 3) * 2;
    float* p0 = Ctx + ((size_t)r0 * NQH + hq) * 128 + col;
    *(float2*)p0 = make_float2(o[t][0] * inv0, o[t][1] * inv0);
    float* p1 = Ctx + ((size_t)(r0 + 8) * NQH + hq) * 128 + col;
    *(float2*)p1 = make_float2(o[t][2] * inv1, o[t][3] * inv1);
  }
}

// ---------------------------------------------------------------------------
// Launch
// ---------------------------------------------------------------------------
extern "C" void kernel_launch(void* const* d_in, const int* in_sizes, int n_in,
                              void* d_out, int out_size) {
  const float* X = (const float*)d_in[0];
  const float* cosp = (const float*)d_in[1];
  const float* sinp = (const float*)d_in[2];
  const float* wq = (const float*)d_in[3];
  const float* wk = (const float*)d_in[4];
  const float* wv = (const float*)d_in[5];
  const float* wo = (const float*)d_in[6];
  float* out = (float*)d_out;

  float *QKV, *Ctx;
  __nv_bfloat16 *Ahi, *Alo, *Bhi, *Blo, *Qh, *Ql, *Kh, *Kl, *Vh, *Vl;
  cudaGetSymbolAddress((void**)&QKV, g_QKV);
  cudaGetSymbolAddress((void**)&Ctx, g_Ctx);
  cudaGetSymbolAddress((void**)&Ahi, g_Ahi);
  cudaGetSymbolAddress((void**)&Alo, g_Alo);
  cudaGetSymbolAddress((void**)&Bhi, g_Bhi);
  cudaGetSymbolAddress((void**)&Blo, g_Blo);
  cudaGetSymbolAddress((void**)&Qh, g_Qh);
  cudaGetSymbolAddress((void**)&Ql, g_Ql);
  cudaGetSymbolAddress((void**)&Kh, g_Kh);
  cudaGetSymbolAddress((void**)&Kl, g_Kl);
  cudaGetSymbolAddress((void**)&Vh, g_Vh);
  cudaGetSymbolAddress((void**)&Vl, g_Vl);

  cudaFuncSetAttribute(gemm_mma, cudaFuncAttributeMaxDynamicSharedMemorySize,
                       GEMM_SMEM);
  cudaFuncSetAttribute(flash_mma, cudaFuncAttributeMaxDynamicSharedMemorySize,
                       FA_SMEM);

  dim3 blk(256);
  dim3 tblk(32, 8);

  split_convert<<<(S_LEN * KDIM / 4 + 255) / 256, 256>>>(X, Ahi, Alo,
                                                         S_LEN * KDIM);
  transpose_split<<<dim3(128, 128), tblk>>>(wq, Bhi, Blo, KDIM, 4096);
  transpose_split<<<dim3(32, 128), tblk>>>(wk, Bhi + (size_t)4096 * KDIM,
                                           Blo + (size_t)4096 * KDIM, KDIM, 1024);
  transpose_split<<<dim3(32, 128), tblk>>>(wv, Bhi + (size_t)5120 * KDIM,
                                           Blo + (size_t)5120 * KDIM, KDIM, 1024);
  gemm_mma<<<dim3(48, 16), blk, GEMM_SMEM>>>(Ahi, Alo, Bhi, Blo, QKV, NQKV);
  int rtot = S_LEN * NQH * 64 + 2 * S_LEN * NKVH * 64;
  rope_split<<<(rtot + 255) / 256, 256>>>(QKV, cosp, sinp);
  flash_mma<<<dim3(32, 32), dim3(128), FA_SMEM>>>(Qh, Ql, Kh, Kl, Vh, Vl, Ctx);
  split_convert<<<(S_LEN * KDIM / 4 + 255) / 256, 256>>>(Ctx, Ahi, Alo,
                                                         S_LEN * KDIM);
  transpose_split<<<dim3(128, 128), tblk>>>(wo, Bhi, Blo, KDIM, 4096);
  gemm_mma<<<dim3(32, 16), blk, GEMM_SMEM>>>(Ahi, Alo, Bhi, Blo, out, 4096);
}

// round 11
// speedup vs baseline: 2.2504x; 1.3662x over previous
#include <cuda_runtime.h>
#include <cuda_bf16.h>
#include <cuda_fp16.h>
#include <math.h>
#include <stdint.h>

#define S_LEN 2048
#define H_DIM 4096
#define NQH 32
#define NKVH 8
#define HDIM 128
#define KDIM 4096
#define NQKV 6144

// ---------------------------------------------------------------------------
// Scratch (device globals; no allocation allowed)
// ---------------------------------------------------------------------------
__device__ float g_QKV[S_LEN * NQKV];
__device__ float g_Ctx[S_LEN * H_DIM];

// fp16 GEMM operands: activations hi/lo, weights single fp16 [N,K]
__device__ __half g_Ahi[S_LEN * KDIM];
__device__ __half g_Alo[S_LEN * KDIM];
__device__ __half g_Bh[NQKV * KDIM];

// attention operands (bf16 split, rope+scale applied)
__device__ __nv_bfloat16 g_Qh[S_LEN * NQH * HDIM];
__device__ __nv_bfloat16 g_Ql[S_LEN * NQH * HDIM];
__device__ __nv_bfloat16 g_Kh[S_LEN * NKVH * HDIM];
__device__ __nv_bfloat16 g_Kl[S_LEN * NKVH * HDIM];
__device__ __nv_bfloat16 g_Vh[S_LEN * NKVH * HDIM];
__device__ __nv_bfloat16 g_Vl[S_LEN * NKVH * HDIM];

// ---------------------------------------------------------------------------
// Helpers
// ---------------------------------------------------------------------------
__device__ __forceinline__ uint32_t smem_u32(const void* p) {
  uint32_t a;
  asm("{ .reg .u64 t; cvta.to.shared.u64 t, %1; cvt.u32.u64 %0, t; }"
      : "=r"(a) : "l"(p));
  return a;
}

__device__ __forceinline__ void cp16(uint32_t dst, const void* src) {
  asm volatile("cp.async.cg.shared.global [%0], [%1], 16;" ::"r"(dst), "l"(src));
}

#define LDSM4(R, ADDR)                                                         \
  asm volatile("ldmatrix.sync.aligned.m8n8.x4.shared.b16 {%0,%1,%2,%3}, [%4];" \
               : "=r"((R)[0]), "=r"((R)[1]), "=r"((R)[2]), "=r"((R)[3])        \
               : "r"(ADDR))

#define LDSM4T(R, ADDR)                                                        \
  asm volatile(                                                                \
      "ldmatrix.sync.aligned.m8n8.x4.trans.shared.b16 {%0,%1,%2,%3}, [%4];"    \
      : "=r"((R)[0]), "=r"((R)[1]), "=r"((R)[2]), "=r"((R)[3])                 \
      : "r"(ADDR))

// bf16 MMA (flash)
#define MMA16816(D, A, B)                                                      \
  asm volatile(                                                                \
      "mma.sync.aligned.m16n8k16.row.col.f32.bf16.bf16.f32 "                   \
      "{%0,%1,%2,%3}, {%4,%5,%6,%7}, {%8,%9}, {%0,%1,%2,%3};"                  \
      : "+f"((D)[0]), "+f"((D)[1]), "+f"((D)[2]), "+f"((D)[3])                 \
      : "r"((A)[0]), "r"((A)[1]), "r"((A)[2]), "r"((A)[3]), "r"((B)[0]),       \
        "r"((B)[1]))

// fp16 MMA (projection GEMMs)
#define MMAH16816(D, A, B)                                                     \
  asm volatile(                                                                \
      "mma.sync.aligned.m16n8k16.row.col.f32.f16.f16.f32 "                     \
      "{%0,%1,%2,%3}, {%4,%5,%6,%7}, {%8,%9}, {%0,%1,%2,%3};"                  \
      : "+f"((D)[0]), "+f"((D)[1]), "+f"((D)[2]), "+f"((D)[3])                 \
      : "r"((A)[0]), "r"((A)[1]), "r"((A)[2]), "r"((A)[3]), "r"((B)[0]),       \
        "r"((B)[1]))

__device__ __forceinline__ uint32_t bf2bits(__nv_bfloat162 v) {
  return *reinterpret_cast<uint32_t*>(&v);
}

// ---------------------------------------------------------------------------
// Split-convert fp32 -> fp16 hi/lo (activations; exact to ~22 bits)
// ---------------------------------------------------------------------------
__global__ void split_convert_h(const float* __restrict__ X,
                                __half* __restrict__ Hi,
                                __half* __restrict__ Lo, int n) {
  int i = (blockIdx.x * 256 + threadIdx.x) * 4;
  if (i >= n) return;
  float4 x = *(const float4*)(X + i);
  float v[4] = {x.x, x.y, x.z, x.w};
  __half h[4], l[4];
#pragma unroll
  for (int j = 0; j < 4; j++) {
    h[j] = __float2half_rn(v[j]);
    l[j] = __float2half_rn(v[j] - __half2float(h[j]));
  }
  __half2 h01, h23, l01, l23;
  h01.x = h[0]; h01.y = h[1]; h23.x = h[2]; h23.y = h[3];
  l01.x = l[0]; l01.y = l[1]; l23.x = l[2]; l23.y = l[3];
  *(__half2*)(Hi + i) = h01;
  *(__half2*)(Hi + i + 2) = h23;
  *(__half2*)(Lo + i) = l01;
  *(__half2*)(Lo + i + 2) = l23;
}

// ---------------------------------------------------------------------------
// Transpose-convert W[K,N] fp32 -> [N,K] fp16 (single)
// ---------------------------------------------------------------------------
__global__ void transpose_half(const float* __restrict__ W,
                               __half* __restrict__ Hi, int K, int N) {
  __shared__ float tile[32][33];
  int tx = threadIdx.x, ty = threadIdx.y;
  int k0 = blockIdx.y * 32, n0 = blockIdx.x * 32;
#pragma unroll
  for (int i = 0; i < 4; i++)
    tile[ty + i * 8][tx] = W[(size_t)(k0 + ty + i * 8) * N + n0 + tx];
  __syncthreads();
#pragma unroll
  for (int i = 0; i < 4; i++) {
    float v = tile[tx][ty + i * 8];
    Hi[(size_t)(n0 + ty + i * 8) * K + k0 + tx] = __float2half_rn(v);
  }
}

// ---------------------------------------------------------------------------
// fp16 2-term GEMM: C = (Ah+Al) * Bh^T  (B stored [N,K]).
// CTA 128x128, BK=32, 8 warps (2x4), warp tile 64x32.
// 3-stage cp.async pipeline, 2 CTAs/SM (16 warps/SM).
// Stage: 3 matrices x 128 rows x 40 halves (pad 8) = 30720 B.
// ---------------------------------------------------------------------------
#define NCH (KDIM / 32)
#define MAT_BYTES 10240       // 128 * 40 * 2
#define STAGE_BYTES 30720     // 3 matrices
#define GEMM_SMEM (3 * STAGE_BYTES)  // 92160 -> 2 CTAs/SM (184KB)

__global__ __launch_bounds__(256, 2) void gemm_mma_h(
    const __half* __restrict__ Ahi, const __half* __restrict__ Alo,
    const __half* __restrict__ Bh_, float* __restrict__ C, int N) {
  extern __shared__ char smc[];
  const int tid = threadIdx.x;
  const int lane = tid & 31, wid = tid >> 5;
  const int wm = wid & 1, wn = wid >> 1;
  const int bm = blockIdx.y * 128, bn = blockIdx.x * 128;
  const size_t Kb = (size_t)KDIM * 2;

  uint32_t sbase = smem_u32(smc);

  const char* gp0 = (const char*)Ahi + (size_t)bm * Kb;
  const char* gp1 = (const char*)Alo + (size_t)bm * Kb;
  const char* gp2 = (const char*)Bh_ + (size_t)bn * Kb;

  const int r = tid >> 2;
  const int cb = (tid & 3) * 16;

  auto load_stage = [&](int stage, int k0) {
    uint32_t sb = sbase + stage * STAGE_BYTES;
    size_t gk = (size_t)k0 * 2;
    const char* gp[3] = {gp0, gp1, gp2};
#pragma unroll
    for (int m = 0; m < 3; m++) {
      uint32_t sd = sb + m * MAT_BYTES;
#pragma unroll
      for (int j = 0; j < 2; j++) {
        int rr = r + j * 64;
        cp16(sd + rr * 80 + cb, gp[m] + (size_t)rr * Kb + gk + cb);
      }
    }
    asm volatile("cp.async.commit_group;" ::: "memory");
  };

  float acc[4][4][4];
#pragma unroll
  for (int a = 0; a < 4; a++)
#pragma unroll
    for (int b = 0; b < 4; b++)
#pragma unroll
      for (int c = 0; c < 4; c++) acc[a][b][c] = 0.f;

  const int arow = wm * 64 + (lane & 15);
  const int aoff = (lane >> 4) * 8;
  const int brow = wn * 32 + (lane >> 4) * 8 + (lane & 7);
  const int boff = ((lane >> 3) & 1) * 8;

  load_stage(0, 0);
  load_stage(1, 32);

  for (int i = 0; i < NCH; ++i) {
    if (i + 2 < NCH)
      asm volatile("cp.async.wait_group 1;" ::: "memory");
    else
      asm volatile("cp.async.wait_group 0;" ::: "memory");
    __syncthreads();
    if (i + 2 < NCH) load_stage((i + 2) % 3, (i + 2) * 32);

    uint32_t sb = sbase + (i % 3) * STAGE_BYTES;
    uint32_t sAh = sb;                  // Alo at +MAT_BYTES
    uint32_t sBh = sb + 2 * MAT_BYTES;

#pragma unroll
    for (int ks = 0; ks < 32; ks += 16) {
      // B fragments for all 4 n-tiles (hoisted)
      uint32_t Bh[4][2];
#pragma unroll
      for (int ni = 0; ni < 2; ni++) {
        uint32_t bd = sBh + ((brow + ni * 16) * 40 + ks + boff) * 2;
        uint32_t t[4];
        LDSM4(t, bd);
        Bh[ni * 2][0] = t[0]; Bh[ni * 2][1] = t[1];
        Bh[ni * 2 + 1][0] = t[2]; Bh[ni * 2 + 1][1] = t[3];
      }
#pragma unroll
      for (int mi = 0; mi < 4; mi++) {
        uint32_t ad = sAh + ((arow + mi * 16) * 40 + ks + aoff) * 2;
        uint32_t Ah[4], Al[4];
        LDSM4(Ah, ad);
        LDSM4(Al, ad + MAT_BYTES);
#pragma unroll
        for (int nj = 0; nj < 4; nj++) {
          MMAH16816(acc[mi][nj], Ah, Bh[nj]);
          MMAH16816(acc[mi][nj], Al, Bh[nj]);
        }
      }
    }
  }

  const int tg = lane >> 2, tc = (lane & 3) * 2;
#pragma unroll
  for (int mi = 0; mi < 4; mi++) {
    int row = bm + wm * 64 + mi * 16 + tg;
#pragma unroll
    for (int nj = 0; nj < 4; nj++) {
      int col = bn + wn * 32 + nj * 8 + tc;
      float* p = C + (size_t)row * N + col;
      p[0] = acc[mi][nj][0];
      p[1] = acc[mi][nj][1];
      float* p2 = p + 8 * (size_t)N;
      p2[0] = acc[mi][nj][2];
      p2[1] = acc[mi][nj][3];
    }
  }
}

// ---------------------------------------------------------------------------
// RoPE + scale + bf16 split for attention operands.
// ---------------------------------------------------------------------------
#define FA_SCALE 0.08838834764831845f

__global__ void rope_split(const float* __restrict__ QKV,
                           const float* __restrict__ cosp,
                           const float* __restrict__ sinp) {
  int idx = blockIdx.x * blockDim.x + threadIdx.x;
  const int nq = S_LEN * NQH * 64;
  const int nk = S_LEN * NKVH * 64;
  if (idx < nq) {
    int d = idx & 63;
    int h = (idx >> 6) & 31;
    int s = idx >> 11;
    const float* src = QKV + (size_t)s * NQKV + h * 128;
    float c1 = cosp[s * 128 + d], s1 = sinp[s * 128 + d];
    float c2 = cosp[s * 128 + d + 64], s2 = sinp[s * 128 + d + 64];
    float x1 = src[d], x2 = src[d + 64];
    float y1 = (x1 * c1 - x2 * s1) * FA_SCALE;
    float y2 = (x2 * c2 + x1 * s2) * FA_SCALE;
    size_t o = ((size_t)s * NQH + h) * 128 + d;
    __nv_bfloat16 h1 = __float2bfloat16_rn(y1);
    __nv_bfloat16 h2 = __float2bfloat16_rn(y2);
    g_Qh[o] = h1;
    g_Ql[o] = __float2bfloat16_rn(y1 - __bfloat162float(h1));
    g_Qh[o + 64] = h2;
    g_Ql[o + 64] = __float2bfloat16_rn(y2 - __bfloat162float(h2));
  } else if (idx < nq + nk) {
    int t = idx - nq;
    int d = t & 63;
    int h = (t >> 6) & 7;
    int s = t >> 9;
    const float* src = QKV + (size_t)s * NQKV + 4096 + h * 128;
    float c1 = cosp[s * 128 + d], s1 = sinp[s * 128 + d];
    float c2 = cosp[s * 128 + d + 64], s2 = sinp[s * 128 + d + 64];
    float x1 = src[d], x2 = src[d + 64];
    float y1 = x1 * c1 - x2 * s1;
    float y2 = x2 * c2 + x1 * s2;
    size_t o = ((size_t)s * NKVH + h) * 128 + d;
    __nv_bfloat16 h1 = __float2bfloat16_rn(y1);
    __nv_bfloat16 h2 = __float2bfloat16_rn(y2);
    g_Kh[o] = h1;
    g_Kl[o] = __float2bfloat16_rn(y1 - __bfloat162float(h1));
    g_Kh[o + 64] = h2;
    g_Kl[o + 64] = __float2bfloat16_rn(y2 - __bfloat162float(h2));
  } else if (idx < nq + 2 * nk) {
    int t = idx - nq - nk;
    int d = t & 63;
    int h = (t >> 6) & 7;
    int s = t >> 9;
    const float* src = QKV + (size_t)s * NQKV + 5120 + h * 128;
    float x1 = src[d], x2 = src[d + 64];
    size_t o = ((size_t)s * NKVH + h) * 128 + d;
    __nv_bfloat16 h1 = __float2bfloat16_rn(x1);
    __nv_bfloat16 h2 = __float2bfloat16_rn(x2);
    g_Vh[o] = h1;
    g_Vl[o] = __float2bfloat16_rn(x1 - __bfloat162float(h1));
    g_Vh[o + 64] = h2;
    g_Vl[o + 64] = __float2bfloat16_rn(x2 - __bfloat162float(h2));
  }
}

// ---------------------------------------------------------------------------
// HMMA flash attention (unchanged passing version: 104KB smem, 2 CTAs/SM)
// ---------------------------------------------------------------------------
#define FA_STRIDE 136
#define FA_MAT 17408
#define FA_SMEM (6 * FA_MAT)  // 104448

__global__ __launch_bounds__(128) void flash_mma(
    const __nv_bfloat16* __restrict__ Qh_, const __nv_bfloat16* __restrict__ Ql_,
    const __nv_bfloat16* __restrict__ Kh_, const __nv_bfloat16* __restrict__ Kl_,
    const __nv_bfloat16* __restrict__ Vh_, const __nv_bfloat16* __restrict__ Vl_,
    float* __restrict__ Ctx) {
  extern __shared__ char smf[];
  const uint32_t sb = smem_u32(smf);
  const uint32_t sQh = sb;
  const uint32_t sKh = sb + 2 * FA_MAT;
  const uint32_t sVh = sb + 4 * FA_MAT;

  const int tid = threadIdx.x;
  const int lane = tid & 31, w = tid >> 5;
  const int qb = (int)gridDim.x - 1 - (int)blockIdx.x;
  const int hq = blockIdx.y, hkv = hq >> 2;

#pragma unroll
  for (int j = 0; j < 8; j++) {
    int idx = tid + j * 128;
    int r = idx >> 4;
    int c = (idx & 15) * 16;
    size_t g = ((size_t)(qb * 64 + r) * NQH + hq) * 256 + c;
    uint32_t d = r * (FA_STRIDE * 2) + c;
    cp16(sQh + d, (const char*)Qh_ + g);
    cp16(sQh + FA_MAT + d, (const char*)Ql_ + g);
  }
  asm volatile("cp.async.commit_group;" ::: "memory");

  float o[16][4];
#pragma unroll
  for (int t = 0; t < 16; t++)
#pragma unroll
    for (int c = 0; c < 4; c++) o[t][c] = 0.f;
  float m0 = -1e30f, m1 = -1e30f, l0 = 0.f, l1 = 0.f;

  const int arow = w * 16 + (lane & 15);
  const int aoff = (lane >> 4) * 8;
  const int bRow = (lane >> 4) * 8 + (lane & 7);
  const int bCol = ((lane >> 3) & 1) * 8;
  const int vRow = (lane & 7) + ((lane >> 3) & 1) * 8;
  const int vCol = (lane >> 4) * 8;
  const int rloc = w * 16 + (lane >> 2);

  for (int kb = 0; kb <= qb; ++kb) {
#pragma unroll
    for (int j = 0; j < 8; j++) {
      int idx = tid + j * 128;
      int r = idx >> 4;
      int c = (idx & 15) * 16;
      size_t g = ((size_t)(kb * 64 + r) * NKVH + hkv) * 256 + c;
      uint32_t d = r * (FA_STRIDE * 2) + c;
      cp16(sKh + d, (const char*)Kh_ + g);
      cp16(sKh + FA_MAT + d, (const char*)Kl_ + g);
      cp16(sVh + d, (const char*)Vh_ + g);
      cp16(sVh + FA_MAT + d, (const char*)Vl_ + g);
    }
    asm volatile("cp.async.commit_group;" ::: "memory");
    asm volatile("cp.async.wait_group 0;" ::: "memory");
    __syncthreads();

    float sacc[8][4];
#pragma unroll
    for (int t = 0; t < 8; t++)
#pragma unroll
      for (int c = 0; c < 4; c++) sacc[t][c] = 0.f;

#pragma unroll
    for (int kk = 0; kk < 8; ++kk) {
      uint32_t qh[4], ql[4];
      uint32_t qa = sQh + (arow * FA_STRIDE + kk * 16 + aoff) * 2;
      LDSM4(qh, qa);
      LDSM4(ql, qa + FA_MAT);
#pragma unroll
      for (int np = 0; np < 4; np++) {
        uint32_t ka = sKh + ((np * 16 + bRow) * FA_STRIDE + kk * 16 + bCol) * 2;
        uint32_t kh[4], kl[4];
        LDSM4(kh, ka);
        LDSM4(kl, ka + FA_MAT);
        MMA16816(sacc[2 * np], qh, kh);
        MMA16816(sacc[2 * np], qh, kl);
        MMA16816(sacc[2 * np], ql, kh);
        MMA16816(sacc[2 * np + 1], qh, kh + 2);
        MMA16816(sacc[2 * np + 1], qh, kl + 2);
        MMA16816(sacc[2 * np + 1], ql, kh + 2);
      }
    }

    if (kb == qb) {
#pragma unroll
      for (int t = 0; t < 8; t++) {
        int n = t * 8 + (lane & 3) * 2;
        if (n > rloc) sacc[t][0] = -1e30f;
        if (n + 1 > rloc) sacc[t][1] = -1e30f;
        if (n > rloc + 8) sacc[t][2] = -1e30f;
        if (n + 1 > rloc + 8) sacc[t][3] = -1e30f;
      }
    }

    float mx0 = -1e30f, mx1 = -1e30f;
#pragma unroll
    for (int t = 0; t < 8; t++) {
      mx0 = fmaxf(mx0, fmaxf(sacc[t][0], sacc[t][1]));
      mx1 = fmaxf(mx1, fmaxf(sacc[t][2], sacc[t][3]));
    }
    mx0 = fmaxf(mx0, __shfl_xor_sync(0xffffffffu, mx0, 1));
    mx0 = fmaxf(mx0, __shfl_xor_sync(0xffffffffu, mx0, 2));
    mx1 = fmaxf(mx1, __shfl_xor_sync(0xffffffffu, mx1, 1));
    mx1 = fmaxf(mx1, __shfl_xor_sync(0xffffffffu, mx1, 2));
    float mn0 = fmaxf(m0, mx0), mn1 = fmaxf(m1, mx1);
    float al0 = __expf(m0 - mn0), al1 = __expf(m1 - mn1);
    m0 = mn0;
    m1 = mn1;
    float sum0 = 0.f, sum1 = 0.f;
#pragma unroll
    for (int t = 0; t < 8; t++) {
      sacc[t][0] = __expf(sacc[t][0] - m0);
      sacc[t][1] = __expf(sacc[t][1] - m0);
      sacc[t][2] = __expf(sacc[t][2] - m1);
      sacc[t][3] = __expf(sacc[t][3] - m1);
      sum0 += sacc[t][0] + sacc[t][1];
      sum1 += sacc[t][2] + sacc[t][3];
    }
    sum0 += __shfl_xor_sync(0xffffffffu, sum0, 1);
    sum0 += __shfl_xor_sync(0xffffffffu, sum0, 2);
    sum1 += __shfl_xor_sync(0xffffffffu, sum1, 1);
    sum1 += __shfl_xor_sync(0xffffffffu, sum1, 2);
    l0 = l0 * al0 + sum0;
    l1 = l1 * al1 + sum1;
#pragma unroll
    for (int t = 0; t < 16; t++) {
      o[t][0] *= al0;
      o[t][1] *= al0;
      o[t][2] *= al1;
      o[t][3] *= al1;
    }

#pragma unroll
    for (int j = 0; j < 4; j++) {
      uint32_t pha[4], pla[4];
      {
        __nv_bfloat162 h01 = __floats2bfloat162_rn(sacc[2 * j][0], sacc[2 * j][1]);
        __nv_bfloat162 h23 = __floats2bfloat162_rn(sacc[2 * j][2], sacc[2 * j][3]);
        pha[0] = bf2bits(h01);
        pha[1] = bf2bits(h23);
        pla[0] = bf2bits(__floats2bfloat162_rn(
            sacc[2 * j][0] - __low2float(h01), sacc[2 * j][1] - __high2float(h01)));
        pla[1] = bf2bits(__floats2bfloat162_rn(
            sacc[2 * j][2] - __low2float(h23), sacc[2 * j][3] - __high2float(h23)));
        __nv_bfloat162 g01 =
            __floats2bfloat162_rn(sacc[2 * j + 1][0], sacc[2 * j + 1][1]);
        __nv_bfloat162 g23 =
            __floats2bfloat162_rn(sacc[2 * j + 1][2], sacc[2 * j + 1][3]);
        pha[2] = bf2bits(g01);
        pha[3] = bf2bits(g23);
        pla[2] = bf2bits(__floats2bfloat162_rn(sacc[2 * j + 1][0] - __low2float(g01),
                                               sacc[2 * j + 1][1] - __high2float(g01)));
        pla[3] = bf2bits(__floats2bfloat162_rn(sacc[2 * j + 1][2] - __low2float(g23),
                                               sacc[2 * j + 1][3] - __high2float(g23)));
      }
#pragma unroll
      for (int np = 0; np < 8; np++) {
        uint32_t va = sVh + ((j * 16 + vRow) * FA_STRIDE + np * 16 + vCol) * 2;
        uint32_t vh[4], vl[4];
        LDSM4T(vh, va);
        LDSM4T(vl, va + FA_MAT);
        MMA16816(o[2 * np], pha, vh);
        MMA16816(o[2 * np], pha, vl);
        MMA16816(o[2 * np], pla, vh);
        MMA16816(o[2 * np + 1], pha, vh + 2);
        MMA16816(o[2 * np + 1], pha, vl + 2);
        MMA16816(o[2 * np + 1], pla, vh + 2);
      }
    }
    __syncthreads();
  }

  float inv0 = 1.0f / l0, inv1 = 1.0f / l1;
  int r0 = qb * 64 + rloc;
#pragma unroll
  for (int t = 0; t < 16; t++) {
    int col = t * 8 + (lane & 3) * 2;
    float* p0 = Ctx + ((size_t)r0 * NQH + hq) * 128 + col;
    *(float2*)p0 = make_float2(o[t][0] * inv0, o[t][1] * inv0);
    float* p1 = Ctx + ((size_t)(r0 + 8) * NQH + hq) * 128 + col;
    *(float2*)p1 = make_float2(o[t][2] * inv1, o[t][3] * inv1);
  }
}

// ---------------------------------------------------------------------------
// Launch
// ---------------------------------------------------------------------------
extern "C" void kernel_launch(void* const* d_in, const int* in_sizes, int n_in,
                              void* d_out, int out_size) {
  const float* X = (const float*)d_in[0];
  const float* cosp = (const float*)d_in[1];
  const float* sinp = (const float*)d_in[2];
  const float* wq = (const float*)d_in[3];
  const float* wk = (const float*)d_in[4];
  const float* wv = (const float*)d_in[5];
  const float* wo = (const float*)d_in[6];
  float* out = (float*)d_out;

  float *QKV, *Ctx;
  __half *Ahi, *Alo, *Bh;
  __nv_bfloat16 *Qh, *Ql, *Kh, *Kl, *Vh, *Vl;
  cudaGetSymbolAddress((void**)&QKV, g_QKV);
  cudaGetSymbolAddress((void**)&Ctx, g_Ctx);
  cudaGetSymbolAddress((void**)&Ahi, g_Ahi);
  cudaGetSymbolAddress((void**)&Alo, g_Alo);
  cudaGetSymbolAddress((void**)&Bh, g_Bh);
  cudaGetSymbolAddress((void**)&Qh, g_Qh);
  cudaGetSymbolAddress((void**)&Ql, g_Ql);
  cudaGetSymbolAddress((void**)&Kh, g_Kh);
  cudaGetSymbolAddress((void**)&Kl, g_Kl);
  cudaGetSymbolAddress((void**)&Vh, g_Vh);
  cudaGetSymbolAddress((void**)&Vl, g_Vl);

  cudaFuncSetAttribute(gemm_mma_h, cudaFuncAttributeMaxDynamicSharedMemorySize,
                       GEMM_SMEM);
  cudaFuncSetAttribute(flash_mma, cudaFuncAttributeMaxDynamicSharedMemorySize,
                       FA_SMEM);

  dim3 blk(256);
  dim3 tblk(32, 8);

  // Activations -> fp16 hi/lo
  split_convert_h<<<(S_LEN * KDIM / 4 + 255) / 256, 256>>>(X, Ahi, Alo,
                                                           S_LEN * KDIM);
  // Fused QKV weights -> [N,K] fp16
  transpose_half<<<dim3(128, 128), tblk>>>(wq, Bh, KDIM, 4096);
  transpose_half<<<dim3(32, 128), tblk>>>(wk, Bh + (size_t)4096 * KDIM, KDIM,
                                          1024);
  transpose_half<<<dim3(32, 128), tblk>>>(wv, Bh + (size_t)5120 * KDIM, KDIM,
                                          1024);
  // Fused QKV projection
  gemm_mma_h<<<dim3(48, 16), blk, GEMM_SMEM>>>(Ahi, Alo, Bh, QKV, NQKV);
  // RoPE + scale + split for attention
  int rtot = S_LEN * NQH * 64 + 2 * S_LEN * NKVH * 64;
  rope_split<<<(rtot + 255) / 256, 256>>>(QKV, cosp, sinp);
  // Attention (bf16 3-term HMMA)
  flash_mma<<<dim3(32, 32), dim3(128), FA_SMEM>>>(Qh, Ql, Kh, Kl, Vh, Vl, Ctx);
  // Output projection
  split_convert_h<<<(S_LEN * KDIM / 4 + 255) / 256, 256>>>(Ctx, Ahi, Alo,
                                                           S_LEN * KDIM);
  transpose_half<<<dim3(128, 128), tblk>>>(wo, Bh, KDIM, 4096);
  gemm_mma_h<<<dim3(32, 16), blk, GEMM_SMEM>>>(Ahi, Alo, Bh, out, 4096);
}

// round 12
// speedup vs baseline: 2.4079x; 1.0700x over previous
#include <cuda_runtime.h>
#include <cuda_fp16.h>
#include <math.h>
#include <stdint.h>

#define S_LEN 2048
#define H_DIM 4096
#define NQH 32
#define NKVH 8
#define HDIM 128
#define KDIM 4096
#define NQKV 6144

// ---------------------------------------------------------------------------
// Scratch (device globals; no allocation allowed)
// ---------------------------------------------------------------------------
__device__ float g_QKV[S_LEN * NQKV];
__device__ float g_Ctx[S_LEN * H_DIM];

// fp16 GEMM operands: activations hi/lo, weights single fp16 [N,K]
__device__ __half g_Ahi[S_LEN * KDIM];
__device__ __half g_Alo[S_LEN * KDIM];
__device__ __half g_Bh[NQKV * KDIM];

// attention operands (fp16; Q split, K single (scale folded), V split)
__device__ __half g_Qh[S_LEN * NQH * HDIM];
__device__ __half g_Ql[S_LEN * NQH * HDIM];
__device__ __half g_Kh[S_LEN * NKVH * HDIM];
__device__ __half g_Vh[S_LEN * NKVH * HDIM];
__device__ __half g_Vl[S_LEN * NKVH * HDIM];

// ---------------------------------------------------------------------------
// Helpers
// ---------------------------------------------------------------------------
__device__ __forceinline__ uint32_t smem_u32(const void* p) {
  uint32_t a;
  asm("{ .reg .u64 t; cvta.to.shared.u64 t, %1; cvt.u32.u64 %0, t; }"
      : "=r"(a) : "l"(p));
  return a;
}

__device__ __forceinline__ void cp16(uint32_t dst, const void* src) {
  asm volatile("cp.async.cg.shared.global [%0], [%1], 16;" ::"r"(dst), "l"(src));
}

#define LDSM4(R, ADDR)                                                         \
  asm volatile("ldmatrix.sync.aligned.m8n8.x4.shared.b16 {%0,%1,%2,%3}, [%4];" \
               : "=r"((R)[0]), "=r"((R)[1]), "=r"((R)[2]), "=r"((R)[3])        \
               : "r"(ADDR))

#define LDSM4T(R, ADDR)                                                        \
  asm volatile(                                                                \
      "ldmatrix.sync.aligned.m8n8.x4.trans.shared.b16 {%0,%1,%2,%3}, [%4];"    \
      : "=r"((R)[0]), "=r"((R)[1]), "=r"((R)[2]), "=r"((R)[3])                 \
      : "r"(ADDR))

// fp16 MMA
#define MMAH16816(D, A, B)                                                     \
  asm volatile(                                                                \
      "mma.sync.aligned.m16n8k16.row.col.f32.f16.f16.f32 "                     \
      "{%0,%1,%2,%3}, {%4,%5,%6,%7}, {%8,%9}, {%0,%1,%2,%3};"                  \
      : "+f"((D)[0]), "+f"((D)[1]), "+f"((D)[2]), "+f"((D)[3])                 \
      : "r"((A)[0]), "r"((A)[1]), "r"((A)[2]), "r"((A)[3]), "r"((B)[0]),       \
        "r"((B)[1]))

__device__ __forceinline__ uint32_t h2bits(__half2 v) {
  return *reinterpret_cast<uint32_t*>(&v);
}

// ---------------------------------------------------------------------------
// Split-convert fp32 -> fp16 hi/lo
// ---------------------------------------------------------------------------
__global__ void split_convert_h(const float* __restrict__ X,
                                __half* __restrict__ Hi,
                                __half* __restrict__ Lo, int n) {
  int i = (blockIdx.x * 256 + threadIdx.x) * 4;
  if (i >= n) return;
  float4 x = *(const float4*)(X + i);
  float v[4] = {x.x, x.y, x.z, x.w};
  __half h[4], l[4];
#pragma unroll
  for (int j = 0; j < 4; j++) {
    h[j] = __float2half_rn(v[j]);
    l[j] = __float2half_rn(v[j] - __half2float(h[j]));
  }
  __half2 h01, h23, l01, l23;
  h01.x = h[0]; h01.y = h[1]; h23.x = h[2]; h23.y = h[3];
  l01.x = l[0]; l01.y = l[1]; l23.x = l[2]; l23.y = l[3];
  *(__half2*)(Hi + i) = h01;
  *(__half2*)(Hi + i + 2) = h23;
  *(__half2*)(Lo + i) = l01;
  *(__half2*)(Lo + i + 2) = l23;
}

// ---------------------------------------------------------------------------
// Transpose-convert W[K,N] fp32 -> [N,K] fp16 (single)
// ---------------------------------------------------------------------------
__global__ void transpose_half(const float* __restrict__ W,
                               __half* __restrict__ Hi, int K, int N) {
  __shared__ float tile[32][33];
  int tx = threadIdx.x, ty = threadIdx.y;
  int k0 = blockIdx.y * 32, n0 = blockIdx.x * 32;
#pragma unroll
  for (int i = 0; i < 4; i++)
    tile[ty + i * 8][tx] = W[(size_t)(k0 + ty + i * 8) * N + n0 + tx];
  __syncthreads();
#pragma unroll
  for (int i = 0; i < 4; i++) {
    float v = tile[tx][ty + i * 8];
    Hi[(size_t)(n0 + ty + i * 8) * K + k0 + tx] = __float2half_rn(v);
  }
}

// ---------------------------------------------------------------------------
// fp16 2-term GEMM: C = (Ah+Al) * Bh^T  (B stored [N,K]).
// CTA tile 128x128, BK=32, 4 warps (2x2), warp tile 64x64 (96 B smem/MMA).
// 3-stage cp.async pipeline, 2 CTAs/SM (256 regs/thread available).
// ---------------------------------------------------------------------------
#define NCH (KDIM / 32)
#define MAT_BYTES 10240       // 128 * 40 * 2
#define STAGE_BYTES 30720     // 3 matrices
#define GEMM_SMEM (3 * STAGE_BYTES)  // 92160 -> 2 CTAs/SM

__global__ __launch_bounds__(128, 2) void gemm_mma_h(
    const __half* __restrict__ Ahi, const __half* __restrict__ Alo,
    const __half* __restrict__ Bh_, float* __restrict__ C, int N) {
  extern __shared__ char smc[];
  const int tid = threadIdx.x;
  const int lane = tid & 31, wid = tid >> 5;
  const int wm = wid & 1, wn = wid >> 1;  // 2x2 warp grid
  const int bm = blockIdx.y * 128, bn = blockIdx.x * 128;
  const size_t Kb = (size_t)KDIM * 2;

  uint32_t sbase = smem_u32(smc);

  const char* gp0 = (const char*)Ahi + (size_t)bm * Kb;
  const char* gp1 = (const char*)Alo + (size_t)bm * Kb;
  const char* gp2 = (const char*)Bh_ + (size_t)bn * Kb;

  const int r = tid >> 2;          // 0..31
  const int cb = (tid & 3) * 16;   // 16B chunk in 64B row

  auto load_stage = [&](int stage, int k0) {
    uint32_t sb = sbase + stage * STAGE_BYTES;
    size_t gk = (size_t)k0 * 2;
    const char* gp[3] = {gp0, gp1, gp2};
#pragma unroll
    for (int m = 0; m < 3; m++) {
      uint32_t sd = sb + m * MAT_BYTES;
#pragma unroll
      for (int j = 0; j < 4; j++) {
        int rr = r + j * 32;
        cp16(sd + rr * 80 + cb, gp[m] + (size_t)rr * Kb + gk + cb);
      }
    }
    asm volatile("cp.async.commit_group;" ::: "memory");
  };

  float acc[4][8][4];
#pragma unroll
  for (int a = 0; a < 4; a++)
#pragma unroll
    for (int b = 0; b < 8; b++)
#pragma unroll
      for (int c = 0; c < 4; c++) acc[a][b][c] = 0.f;

  const int arow = wm * 64 + (lane & 15);
  const int aoff = (lane >> 4) * 8;
  const int brow = wn * 64 + (lane >> 4) * 8 + (lane & 7);
  const int boff = ((lane >> 3) & 1) * 8;

  load_stage(0, 0);
  load_stage(1, 32);

  for (int i = 0; i < NCH; ++i) {
    if (i + 2 < NCH)
      asm volatile("cp.async.wait_group 1;" ::: "memory");
    else
      asm volatile("cp.async.wait_group 0;" ::: "memory");
    __syncthreads();
    if (i + 2 < NCH) load_stage((i + 2) % 3, (i + 2) * 32);

    uint32_t sb = sbase + (i % 3) * STAGE_BYTES;
    uint32_t sAh = sb;                  // Alo at +MAT_BYTES
    uint32_t sBh = sb + 2 * MAT_BYTES;

#pragma unroll
    for (int ks = 0; ks < 32; ks += 16) {
      // B fragments for all 8 n-tiles (hoisted; 16 regs)
      uint32_t Bh[8][2];
#pragma unroll
      for (int ni = 0; ni < 4; ni++) {
        uint32_t bd = sBh + ((brow + ni * 16) * 40 + ks + boff) * 2;
        uint32_t t[4];
        LDSM4(t, bd);
        Bh[ni * 2][0] = t[0]; Bh[ni * 2][1] = t[1];
        Bh[ni * 2 + 1][0] = t[2]; Bh[ni * 2 + 1][1] = t[3];
      }
#pragma unroll
      for (int mi = 0; mi < 4; mi++) {
        uint32_t ad = sAh + ((arow + mi * 16) * 40 + ks + aoff) * 2;
        uint32_t Ah[4], Al[4];
        LDSM4(Ah, ad);
        LDSM4(Al, ad + MAT_BYTES);
#pragma unroll
        for (int nj = 0; nj < 8; nj++) {
          MMAH16816(acc[mi][nj], Ah, Bh[nj]);
          MMAH16816(acc[mi][nj], Al, Bh[nj]);
        }
      }
    }
  }

  const int tg = lane >> 2, tc = (lane & 3) * 2;
#pragma unroll
  for (int mi = 0; mi < 4; mi++) {
    int row = bm + wm * 64 + mi * 16 + tg;
#pragma unroll
    for (int nj = 0; nj < 8; nj++) {
      int col = bn + wn * 64 + nj * 8 + tc;
      float* p = C + (size_t)row * N + col;
      p[0] = acc[mi][nj][0];
      p[1] = acc[mi][nj][1];
      float* p2 = p + 8 * (size_t)N;
      p2[0] = acc[mi][nj][2];
      p2[1] = acc[mi][nj][3];
    }
  }
}

// ---------------------------------------------------------------------------
// RoPE + fp16 split for attention. Q split hi/lo (unscaled), K single fp16
// with softmax scale folded in, V split hi/lo.
// ---------------------------------------------------------------------------
#define FA_SCALE 0.08838834764831845f

__global__ void rope_split(const float* __restrict__ QKV,
                           const float* __restrict__ cosp,
                           const float* __restrict__ sinp) {
  int idx = blockIdx.x * blockDim.x + threadIdx.x;
  const int nq = S_LEN * NQH * 64;
  const int nk = S_LEN * NKVH * 64;
  if (idx < nq) {
    int d = idx & 63;
    int h = (idx >> 6) & 31;
    int s = idx >> 11;
    const float* src = QKV + (size_t)s * NQKV + h * 128;
    float c1 = cosp[s * 128 + d], s1 = sinp[s * 128 + d];
    float c2 = cosp[s * 128 + d + 64], s2 = sinp[s * 128 + d + 64];
    float x1 = src[d], x2 = src[d + 64];
    float y1 = x1 * c1 - x2 * s1;
    float y2 = x2 * c2 + x1 * s2;
    size_t o = ((size_t)s * NQH + h) * 128 + d;
    __half h1 = __float2half_rn(y1);
    __half h2 = __float2half_rn(y2);
    g_Qh[o] = h1;
    g_Ql[o] = __float2half_rn(y1 - __half2float(h1));
    g_Qh[o + 64] = h2;
    g_Ql[o + 64] = __float2half_rn(y2 - __half2float(h2));
  } else if (idx < nq + nk) {
    int t = idx - nq;
    int d = t & 63;
    int h = (t >> 6) & 7;
    int s = t >> 9;
    const float* src = QKV + (size_t)s * NQKV + 4096 + h * 128;
    float c1 = cosp[s * 128 + d], s1 = sinp[s * 128 + d];
    float c2 = cosp[s * 128 + d + 64], s2 = sinp[s * 128 + d + 64];
    float x1 = src[d], x2 = src[d + 64];
    float y1 = (x1 * c1 - x2 * s1) * FA_SCALE;
    float y2 = (x2 * c2 + x1 * s2) * FA_SCALE;
    size_t o = ((size_t)s * NKVH + h) * 128 + d;
    g_Kh[o] = __float2half_rn(y1);
    g_Kh[o + 64] = __float2half_rn(y2);
  } else if (idx < nq + 2 * nk) {
    int t = idx - nq - nk;
    int d = t & 63;
    int h = (t >> 6) & 7;
    int s = t >> 9;
    const float* src = QKV + (size_t)s * NQKV + 5120 + h * 128;
    float x1 = src[d], x2 = src[d + 64];
    size_t o = ((size_t)s * NKVH + h) * 128 + d;
    __half h1 = __float2half_rn(x1);
    __half h2 = __float2half_rn(x2);
    g_Vh[o] = h1;
    g_Vl[o] = __float2half_rn(x1 - __half2float(h1));
    g_Vh[o + 64] = h2;
    g_Vl[o + 64] = __float2half_rn(x2 - __half2float(h2));
  }
}

// ---------------------------------------------------------------------------
// fp16 flash attention, causal, GQA. Tile 64x64, HD=128, 4 warps.
// 2-term: S = (Qh+Ql)K, O += P(Vh+Vl). SMEM 5 mats = 87040 B -> 2 CTAs/SM.
// ---------------------------------------------------------------------------
#define FA_STRIDE 136
#define FA_MAT 17408
#define FA_SMEM (5 * FA_MAT)  // 87040

__global__ __launch_bounds__(128) void flash_mma(
    const __half* __restrict__ Qh_, const __half* __restrict__ Ql_,
    const __half* __restrict__ Kh_, const __half* __restrict__ Vh_,
    const __half* __restrict__ Vl_, float* __restrict__ Ctx) {
  extern __shared__ char smf[];
  const uint32_t sb = smem_u32(smf);
  const uint32_t sQh = sb;                   // Qh, Ql
  const uint32_t sKh = sb + 2 * FA_MAT;      // K single
  const uint32_t sVh = sb + 3 * FA_MAT;      // Vh, Vl

  const int tid = threadIdx.x;
  const int lane = tid & 31, w = tid >> 5;
  const int qb = (int)gridDim.x - 1 - (int)blockIdx.x;
  const int hq = blockIdx.y, hkv = hq >> 2;

#pragma unroll
  for (int j = 0; j < 8; j++) {
    int idx = tid + j * 128;
    int r = idx >> 4;
    int c = (idx & 15) * 16;
    size_t g = ((size_t)(qb * 64 + r) * NQH + hq) * 256 + c;
    uint32_t d = r * (FA_STRIDE * 2) + c;
    cp16(sQh + d, (const char*)Qh_ + g);
    cp16(sQh + FA_MAT + d, (const char*)Ql_ + g);
  }
  asm volatile("cp.async.commit_group;" ::: "memory");

  float o[16][4];
#pragma unroll
  for (int t = 0; t < 16; t++)
#pragma unroll
    for (int c = 0; c < 4; c++) o[t][c] = 0.f;
  float m0 = -1e30f, m1 = -1e30f, l0 = 0.f, l1 = 0.f;

  const int arow = w * 16 + (lane & 15);
  const int aoff = (lane >> 4) * 8;
  const int bRow = (lane >> 4) * 8 + (lane & 7);
  const int bCol = ((lane >> 3) & 1) * 8;
  const int vRow = (lane & 7) + ((lane >> 3) & 1) * 8;
  const int vCol = (lane >> 4) * 8;
  const int rloc = w * 16 + (lane >> 2);

  for (int kb = 0; kb <= qb; ++kb) {
#pragma unroll
    for (int j = 0; j < 8; j++) {
      int idx = tid + j * 128;
      int r = idx >> 4;
      int c = (idx & 15) * 16;
      size_t g = ((size_t)(kb * 64 + r) * NKVH + hkv) * 256 + c;
      uint32_t d = r * (FA_STRIDE * 2) + c;
      cp16(sKh + d, (const char*)Kh_ + g);
      cp16(sVh + d, (const char*)Vh_ + g);
      cp16(sVh + FA_MAT + d, (const char*)Vl_ + g);
    }
    asm volatile("cp.async.commit_group;" ::: "memory");
    asm volatile("cp.async.wait_group 0;" ::: "memory");
    __syncthreads();

    float sacc[8][4];
#pragma unroll
    for (int t = 0; t < 8; t++)
#pragma unroll
      for (int c = 0; c < 4; c++) sacc[t][c] = 0.f;

#pragma unroll
    for (int kk = 0; kk < 8; ++kk) {
      uint32_t qh[4], ql[4];
      uint32_t qa = sQh + (arow * FA_STRIDE + kk * 16 + aoff) * 2;
      LDSM4(qh, qa);
      LDSM4(ql, qa + FA_MAT);
#pragma unroll
      for (int np = 0; np < 4; np++) {
        uint32_t ka = sKh + ((np * 16 + bRow) * FA_STRIDE + kk * 16 + bCol) * 2;
        uint32_t kh[4];
        LDSM4(kh, ka);
        MMAH16816(sacc[2 * np], qh, kh);
        MMAH16816(sacc[2 * np], ql, kh);
        MMAH16816(sacc[2 * np + 1], qh, kh + 2);
        MMAH16816(sacc[2 * np + 1], ql, kh + 2);
      }
    }

    if (kb == qb) {
#pragma unroll
      for (int t = 0; t < 8; t++) {
        int n = t * 8 + (lane & 3) * 2;
        if (n > rloc) sacc[t][0] = -1e30f;
        if (n + 1 > rloc) sacc[t][1] = -1e30f;
        if (n > rloc + 8) sacc[t][2] = -1e30f;
        if (n + 1 > rloc + 8) sacc[t][3] = -1e30f;
      }
    }

    float mx0 = -1e30f, mx1 = -1e30f;
#pragma unroll
    for (int t = 0; t < 8; t++) {
      mx0 = fmaxf(mx0, fmaxf(sacc[t][0], sacc[t][1]));
      mx1 = fmaxf(mx1, fmaxf(sacc[t][2], sacc[t][3]));
    }
    mx0 = fmaxf(mx0, __shfl_xor_sync(0xffffffffu, mx0, 1));
    mx0 = fmaxf(mx0, __shfl_xor_sync(0xffffffffu, mx0, 2));
    mx1 = fmaxf(mx1, __shfl_xor_sync(0xffffffffu, mx1, 1));
    mx1 = fmaxf(mx1, __shfl_xor_sync(0xffffffffu, mx1, 2));
    float mn0 = fmaxf(m0, mx0), mn1 = fmaxf(m1, mx1);
    float al0 = __expf(m0 - mn0), al1 = __expf(m1 - mn1);
    m0 = mn0;
    m1 = mn1;
    float sum0 = 0.f, sum1 = 0.f;
#pragma unroll
    for (int t = 0; t < 8; t++) {
      sacc[t][0] = __expf(sacc[t][0] - m0);
      sacc[t][1] = __expf(sacc[t][1] - m0);
      sacc[t][2] = __expf(sacc[t][2] - m1);
      sacc[t][3] = __expf(sacc[t][3] - m1);
      sum0 += sacc[t][0] + sacc[t][1];
      sum1 += sacc[t][2] + sacc[t][3];
    }
    sum0 += __shfl_xor_sync(0xffffffffu, sum0, 1);
    sum0 += __shfl_xor_sync(0xffffffffu, sum0, 2);
    sum1 += __shfl_xor_sync(0xffffffffu, sum1, 1);
    sum1 += __shfl_xor_sync(0xffffffffu, sum1, 2);
    l0 = l0 * al0 + sum0;
    l1 = l1 * al1 + sum1;
#pragma unroll
    for (int t = 0; t < 16; t++) {
      o[t][0] *= al0;
      o[t][1] *= al0;
      o[t][2] *= al1;
      o[t][3] *= al1;
    }

    // O += P (Vh + Vl), P single fp16
#pragma unroll
    for (int j = 0; j < 4; j++) {
      uint32_t pha[4];
      pha[0] = h2bits(__floats2half2_rn(sacc[2 * j][0], sacc[2 * j][1]));
      pha[1] = h2bits(__floats2half2_rn(sacc[2 * j][2], sacc[2 * j][3]));
      pha[2] = h2bits(__floats2half2_rn(sacc[2 * j + 1][0], sacc[2 * j + 1][1]));
      pha[3] = h2bits(__floats2half2_rn(sacc[2 * j + 1][2], sacc[2 * j + 1][3]));
#pragma unroll
      for (int np = 0; np < 8; np++) {
        uint32_t va = sVh + ((j * 16 + vRow) * FA_STRIDE + np * 16 + vCol) * 2;
        uint32_t vh[4], vl[4];
        LDSM4T(vh, va);
        LDSM4T(vl, va + FA_MAT);
        MMAH16816(o[2 * np], pha, vh);
        MMAH16816(o[2 * np], pha, vl);
        MMAH16816(o[2 * np + 1], pha, vh + 2);
        MMAH16816(o[2 * np + 1], pha, vl + 2);
      }
    }
    __syncthreads();
  }

  float inv0 = 1.0f / l0, inv1 = 1.0f / l1;
  int r0 = qb * 64 + rloc;
#pragma unroll
  for (int t = 0; t < 16; t++) {
    int col = t * 8 + (lane & 3) * 2;
    float* p0 = Ctx + ((size_t)r0 * NQH + hq) * 128 + col;
    *(float2*)p0 = make_float2(o[t][0] * inv0, o[t][1] * inv0);
    float* p1 = Ctx + ((size_t)(r0 + 8) * NQH + hq) * 128 + col;
    *(float2*)p1 = make_float2(o[t][2] * inv1, o[t][3] * inv1);
  }
}

// ---------------------------------------------------------------------------
// Launch
// ---------------------------------------------------------------------------
extern "C" void kernel_launch(void* const* d_in, const int* in_sizes, int n_in,
                              void* d_out, int out_size) {
  const float* X = (const float*)d_in[0];
  const float* cosp = (const float*)d_in[1];
  const float* sinp = (const float*)d_in[2];
  const float* wq = (const float*)d_in[3];
  const float* wk = (const float*)d_in[4];
  const float* wv = (const float*)d_in[5];
  const float* wo = (const float*)d_in[6];
  float* out = (float*)d_out;

  float *QKV, *Ctx;
  __half *Ahi, *Alo, *Bh, *Qh, *Ql, *Kh, *Vh, *Vl;
  cudaGetSymbolAddress((void**)&QKV, g_QKV);
  cudaGetSymbolAddress((void**)&Ctx, g_Ctx);
  cudaGetSymbolAddress((void**)&Ahi, g_Ahi);
  cudaGetSymbolAddress((void**)&Alo, g_Alo);
  cudaGetSymbolAddress((void**)&Bh, g_Bh);
  cudaGetSymbolAddress((void**)&Qh, g_Qh);
  cudaGetSymbolAddress((void**)&Ql, g_Ql);
  cudaGetSymbolAddress((void**)&Kh, g_Kh);
  cudaGetSymbolAddress((void**)&Vh, g_Vh);
  cudaGetSymbolAddress((void**)&Vl, g_Vl);

  cudaFuncSetAttribute(gemm_mma_h, cudaFuncAttributeMaxDynamicSharedMemorySize,
                       GEMM_SMEM);
  cudaFuncSetAttribute(flash_mma, cudaFuncAttributeMaxDynamicSharedMemorySize,
                       FA_SMEM);

  dim3 tblk(32, 8);

  // Activations -> fp16 hi/lo
  split_convert_h<<<(S_LEN * KDIM / 4 + 255) / 256, 256>>>(X, Ahi, Alo,
                                                           S_LEN * KDIM);
  // Fused QKV weights -> [N,K] fp16
  transpose_half<<<dim3(128, 128), tblk>>>(wq, Bh, KDIM, 4096);
  transpose_half<<<dim3(32, 128), tblk>>>(wk, Bh + (size_t)4096 * KDIM, KDIM,
                                          1024);
  transpose_half<<<dim3(32, 128), tblk>>>(wv, Bh + (size_t)5120 * KDIM, KDIM,
                                          1024);
  // Fused QKV projection (4-warp CTAs, 64x64 warp tiles)
  gemm_mma_h<<<dim3(48, 16), dim3(128), GEMM_SMEM>>>(Ahi, Alo, Bh, QKV, NQKV);
  // RoPE + fp16 split for attention
  int rtot = S_LEN * NQH * 64 + 2 * S_LEN * NKVH * 64;
  rope_split<<<(rtot + 255) / 256, 256>>>(QKV, cosp, sinp);
  // Attention (fp16 2-term HMMA)
  flash_mma<<<dim3(32, 32), dim3(128), FA_SMEM>>>(Qh, Ql, Kh, Vh, Vl, Ctx);
  // Output projection
  split_convert_h<<<(S_LEN * KDIM / 4 + 255) / 256, 256>>>(Ctx, Ahi, Alo,
                                                           S_LEN * KDIM);
  transpose_half<<<dim3(128, 128), tblk>>>(wo, Bh, KDIM, 4096);
  gemm_mma_h<<<dim3(32, 16), dim3(128), GEMM_SMEM>>>(Ahi, Alo, Bh, out, 4096);
}

// round 13
// speedup vs baseline: 2.4690x; 1.0254x over previous
#include <cuda_runtime.h>
#include <cuda_fp16.h>
#include <math.h>
#include <stdint.h>

#define S_LEN 2048
#define H_DIM 4096
#define NQH 32
#define NKVH 8
#define HDIM 128
#define KDIM 4096
#define NQKV 6144

// ---------------------------------------------------------------------------
// Scratch (device globals; no allocation allowed)
// ---------------------------------------------------------------------------
__device__ float g_QKV[S_LEN * NQKV];

// fp16 GEMM operands: activations hi/lo, weights single fp16 [N,K]
__device__ __half g_Ahi[S_LEN * KDIM];
__device__ __half g_Alo[S_LEN * KDIM];
__device__ __half g_Bh[NQKV * KDIM];

// attention operands (fp16; Q split, K single (scale folded), V split)
__device__ __half g_Qh[S_LEN * NQH * HDIM];
__device__ __half g_Ql[S_LEN * NQH * HDIM];
__device__ __half g_Kh[S_LEN * NKVH * HDIM];
__device__ __half g_Vh[S_LEN * NKVH * HDIM];
__device__ __half g_Vl[S_LEN * NKVH * HDIM];

// ---------------------------------------------------------------------------
// Helpers
// ---------------------------------------------------------------------------
__device__ __forceinline__ uint32_t smem_u32(const void* p) {
  uint32_t a;
  asm("{ .reg .u64 t; cvta.to.shared.u64 t, %1; cvt.u32.u64 %0, t; }"
      : "=r"(a) : "l"(p));
  return a;
}

__device__ __forceinline__ void cp16(uint32_t dst, const void* src) {
  asm volatile("cp.async.cg.shared.global [%0], [%1], 16;" ::"r"(dst), "l"(src));
}

#define LDSM4(R, ADDR)                                                         \
  asm volatile("ldmatrix.sync.aligned.m8n8.x4.shared.b16 {%0,%1,%2,%3}, [%4];" \
               : "=r"((R)[0]), "=r"((R)[1]), "=r"((R)[2]), "=r"((R)[3])        \
               : "r"(ADDR))

#define LDSM4T(R, ADDR)                                                        \
  asm volatile(                                                                \
      "ldmatrix.sync.aligned.m8n8.x4.trans.shared.b16 {%0,%1,%2,%3}, [%4];"    \
      : "=r"((R)[0]), "=r"((R)[1]), "=r"((R)[2]), "=r"((R)[3])                 \
      : "r"(ADDR))

// fp16 MMA
#define MMAH16816(D, A, B)                                                     \
  asm volatile(                                                                \
      "mma.sync.aligned.m16n8k16.row.col.f32.f16.f16.f32 "                     \
      "{%0,%1,%2,%3}, {%4,%5,%6,%7}, {%8,%9}, {%0,%1,%2,%3};"                  \
      : "+f"((D)[0]), "+f"((D)[1]), "+f"((D)[2]), "+f"((D)[3])                 \
      : "r"((A)[0]), "r"((A)[1]), "r"((A)[2]), "r"((A)[3]), "r"((B)[0]),       \
        "r"((B)[1]))

__device__ __forceinline__ uint32_t h2bits(__half2 v) {
  return *reinterpret_cast<uint32_t*>(&v);
}

// ---------------------------------------------------------------------------
// Split-convert fp32 -> fp16 hi/lo
// ---------------------------------------------------------------------------
__global__ void split_convert_h(const float* __restrict__ X,
                                __half* __restrict__ Hi,
                                __half* __restrict__ Lo, int n) {
  int i = (blockIdx.x * 256 + threadIdx.x) * 4;
  if (i >= n) return;
  float4 x = *(const float4*)(X + i);
  float v[4] = {x.x, x.y, x.z, x.w};
  __half h[4], l[4];
#pragma unroll
  for (int j = 0; j < 4; j++) {
    h[j] = __float2half_rn(v[j]);
    l[j] = __float2half_rn(v[j] - __half2float(h[j]));
  }
  __half2 h01, h23, l01, l23;
  h01.x = h[0]; h01.y = h[1]; h23.x = h[2]; h23.y = h[3];
  l01.x = l[0]; l01.y = l[1]; l23.x = l[2]; l23.y = l[3];
  *(__half2*)(Hi + i) = h01;
  *(__half2*)(Hi + i + 2) = h23;
  *(__half2*)(Lo + i) = l01;
  *(__half2*)(Lo + i + 2) = l23;
}

// ---------------------------------------------------------------------------
// Transpose-convert W[K,N] fp32 -> [N,K] fp16 (single)
// ---------------------------------------------------------------------------
__global__ void transpose_half(const float* __restrict__ W,
                               __half* __restrict__ Hi, int K, int N) {
  __shared__ float tile[32][33];
  int tx = threadIdx.x, ty = threadIdx.y;
  int k0 = blockIdx.y * 32, n0 = blockIdx.x * 32;
#pragma unroll
  for (int i = 0; i < 4; i++)
    tile[ty + i * 8][tx] = W[(size_t)(k0 + ty + i * 8) * N + n0 + tx];
  __syncthreads();
#pragma unroll
  for (int i = 0; i < 4; i++) {
    float v = tile[tx][ty + i * 8];
    Hi[(size_t)(n0 + ty + i * 8) * K + k0 + tx] = __float2half_rn(v);
  }
}

// ---------------------------------------------------------------------------
// fp16 2-term GEMM: C = (Ah+Al) * Bh^T  (B stored [N,K]).
// CTA tile 128x128, BK=32, 4 warps (2x2), warp tile 64x64.
// 2-stage cp.async pipeline, 3 CTAs/SM (12 warps/SM; regs capped at 170).
// ---------------------------------------------------------------------------
#define NCH (KDIM / 32)
#define MAT_BYTES 10240       // 128 * 40 * 2
#define STAGE_BYTES 30720     // 3 matrices
#define GEMM_SMEM (2 * STAGE_BYTES)  // 61440 -> 3 CTAs/SM

__global__ __launch_bounds__(128, 3) void gemm_mma_h(
    const __half* __restrict__ Ahi, const __half* __restrict__ Alo,
    const __half* __restrict__ Bh_, float* __restrict__ C, int N) {
  extern __shared__ char smc[];
  const int tid = threadIdx.x;
  const int lane = tid & 31, wid = tid >> 5;
  const int wm = wid & 1, wn = wid >> 1;  // 2x2 warp grid
  const int bm = blockIdx.y * 128, bn = blockIdx.x * 128;
  const size_t Kb = (size_t)KDIM * 2;

  uint32_t sbase = smem_u32(smc);

  const char* gp0 = (const char*)Ahi + (size_t)bm * Kb;
  const char* gp1 = (const char*)Alo + (size_t)bm * Kb;
  const char* gp2 = (const char*)Bh_ + (size_t)bn * Kb;

  const int r = tid >> 2;          // 0..31
  const int cb = (tid & 3) * 16;   // 16B chunk in 64B row

  auto load_stage = [&](int stage, int k0) {
    uint32_t sb = sbase + stage * STAGE_BYTES;
    size_t gk = (size_t)k0 * 2;
    const char* gp[3] = {gp0, gp1, gp2};
#pragma unroll
    for (int m = 0; m < 3; m++) {
      uint32_t sd = sb + m * MAT_BYTES;
#pragma unroll
      for (int j = 0; j < 4; j++) {
        int rr = r + j * 32;
        cp16(sd + rr * 80 + cb, gp[m] + (size_t)rr * Kb + gk + cb);
      }
    }
    asm volatile("cp.async.commit_group;" ::: "memory");
  };

  float acc[4][8][4];
#pragma unroll
  for (int a = 0; a < 4; a++)
#pragma unroll
    for (int b = 0; b < 8; b++)
#pragma unroll
      for (int c = 0; c < 4; c++) acc[a][b][c] = 0.f;

  const int arow = wm * 64 + (lane & 15);
  const int aoff = (lane >> 4) * 8;
  const int brow = wn * 64 + (lane >> 4) * 8 + (lane & 7);
  const int boff = ((lane >> 3) & 1) * 8;

  load_stage(0, 0);

  for (int i = 0; i < NCH; ++i) {
    if (i + 1 < NCH) {
      // trailing __syncthreads of iter i-1 guarantees stage (i+1)&1 is free
      load_stage((i + 1) & 1, (i + 1) * 32);
      asm volatile("cp.async.wait_group 1;" ::: "memory");
    } else {
      asm volatile("cp.async.wait_group 0;" ::: "memory");
    }
    __syncthreads();

    uint32_t sb = sbase + (i & 1) * STAGE_BYTES;
    uint32_t sAh = sb;                  // Alo at +MAT_BYTES
    uint32_t sBh = sb + 2 * MAT_BYTES;

#pragma unroll
    for (int ks = 0; ks < 32; ks += 16) {
      uint32_t Bh[8][2];
#pragma unroll
      for (int ni = 0; ni < 4; ni++) {
        uint32_t bd = sBh + ((brow + ni * 16) * 40 + ks + boff) * 2;
        uint32_t t[4];
        LDSM4(t, bd);
        Bh[ni * 2][0] = t[0]; Bh[ni * 2][1] = t[1];
        Bh[ni * 2 + 1][0] = t[2]; Bh[ni * 2 + 1][1] = t[3];
      }
#pragma unroll
      for (int mi = 0; mi < 4; mi++) {
        uint32_t ad = sAh + ((arow + mi * 16) * 40 + ks + aoff) * 2;
        uint32_t Ah[4], Al[4];
        LDSM4(Ah, ad);
        LDSM4(Al, ad + MAT_BYTES);
#pragma unroll
        for (int nj = 0; nj < 8; nj++) {
          MMAH16816(acc[mi][nj], Ah, Bh[nj]);
          MMAH16816(acc[mi][nj], Al, Bh[nj]);
        }
      }
    }
    __syncthreads();
  }

  const int tg = lane >> 2, tc = (lane & 3) * 2;
#pragma unroll
  for (int mi = 0; mi < 4; mi++) {
    int row = bm + wm * 64 + mi * 16 + tg;
#pragma unroll
    for (int nj = 0; nj < 8; nj++) {
      int col = bn + wn * 64 + nj * 8 + tc;
      float* p = C + (size_t)row * N + col;
      p[0] = acc[mi][nj][0];
      p[1] = acc[mi][nj][1];
      float* p2 = p + 8 * (size_t)N;
      p2[0] = acc[mi][nj][2];
      p2[1] = acc[mi][nj][3];
    }
  }
}

// ---------------------------------------------------------------------------
// RoPE + fp16 split for attention. Q split hi/lo (unscaled), K single fp16
// with softmax scale folded in, V split hi/lo.
// ---------------------------------------------------------------------------
#define FA_SCALE 0.08838834764831845f

__global__ void rope_split(const float* __restrict__ QKV,
                           const float* __restrict__ cosp,
                           const float* __restrict__ sinp) {
  int idx = blockIdx.x * blockDim.x + threadIdx.x;
  const int nq = S_LEN * NQH * 64;
  const int nk = S_LEN * NKVH * 64;
  if (idx < nq) {
    int d = idx & 63;
    int h = (idx >> 6) & 31;
    int s = idx >> 11;
    const float* src = QKV + (size_t)s * NQKV + h * 128;
    float c1 = cosp[s * 128 + d], s1 = sinp[s * 128 + d];
    float c2 = cosp[s * 128 + d + 64], s2 = sinp[s * 128 + d + 64];
    float x1 = src[d], x2 = src[d + 64];
    float y1 = x1 * c1 - x2 * s1;
    float y2 = x2 * c2 + x1 * s2;
    size_t o = ((size_t)s * NQH + h) * 128 + d;
    __half h1 = __float2half_rn(y1);
    __half h2 = __float2half_rn(y2);
    g_Qh[o] = h1;
    g_Ql[o] = __float2half_rn(y1 - __half2float(h1));
    g_Qh[o + 64] = h2;
    g_Ql[o + 64] = __float2half_rn(y2 - __half2float(h2));
  } else if (idx < nq + nk) {
    int t = idx - nq;
    int d = t & 63;
    int h = (t >> 6) & 7;
    int s = t >> 9;
    const float* src = QKV + (size_t)s * NQKV + 4096 + h * 128;
    float c1 = cosp[s * 128 + d], s1 = sinp[s * 128 + d];
    float c2 = cosp[s * 128 + d + 64], s2 = sinp[s * 128 + d + 64];
    float x1 = src[d], x2 = src[d + 64];
    float y1 = (x1 * c1 - x2 * s1) * FA_SCALE;
    float y2 = (x2 * c2 + x1 * s2) * FA_SCALE;
    size_t o = ((size_t)s * NKVH + h) * 128 + d;
    g_Kh[o] = __float2half_rn(y1);
    g_Kh[o + 64] = __float2half_rn(y2);
  } else if (idx < nq + 2 * nk) {
    int t = idx - nq - nk;
    int d = t & 63;
    int h = (t >> 6) & 7;
    int s = t >> 9;
    const float* src = QKV + (size_t)s * NQKV + 5120 + h * 128;
    float x1 = src[d], x2 = src[d + 64];
    size_t o = ((size_t)s * NKVH + h) * 128 + d;
    __half h1 = __float2half_rn(x1);
    __half h2 = __float2half_rn(x2);
    g_Vh[o] = h1;
    g_Vl[o] = __float2half_rn(x1 - __half2float(h1));
    g_Vh[o + 64] = h2;
    g_Vl[o + 64] = __float2half_rn(x2 - __half2float(h2));
  }
}

// ---------------------------------------------------------------------------
// fp16 flash attention, causal, GQA. Tile 64x64, HD=128, 4 warps.
// 2-term: S = (Qh+Ql)K, O += P(Vh+Vl). SMEM 5 mats = 87040 B -> 2 CTAs/SM.
// Epilogue writes context directly as fp16 hi/lo into the out-proj A buffers.
// ---------------------------------------------------------------------------
#define FA_STRIDE 136
#define FA_MAT 17408
#define FA_SMEM (5 * FA_MAT)  // 87040

__global__ __launch_bounds__(128) void flash_mma(
    const __half* __restrict__ Qh_, const __half* __restrict__ Ql_,
    const __half* __restrict__ Kh_, const __half* __restrict__ Vh_,
    const __half* __restrict__ Vl_, __half* __restrict__ CtxHi,
    __half* __restrict__ CtxLo) {
  extern __shared__ char smf[];
  const uint32_t sb = smem_u32(smf);
  const uint32_t sQh = sb;                   // Qh, Ql
  const uint32_t sKh = sb + 2 * FA_MAT;      // K single
  const uint32_t sVh = sb + 3 * FA_MAT;      // Vh, Vl

  const int tid = threadIdx.x;
  const int lane = tid & 31, w = tid >> 5;
  const int qb = (int)gridDim.x - 1 - (int)blockIdx.x;
  const int hq = blockIdx.y, hkv = hq >> 2;

#pragma unroll
  for (int j = 0; j < 8; j++) {
    int idx = tid + j * 128;
    int r = idx >> 4;
    int c = (idx & 15) * 16;
    size_t g = ((size_t)(qb * 64 + r) * NQH + hq) * 256 + c;
    uint32_t d = r * (FA_STRIDE * 2) + c;
    cp16(sQh + d, (const char*)Qh_ + g);
    cp16(sQh + FA_MAT + d, (const char*)Ql_ + g);
  }
  asm volatile("cp.async.commit_group;" ::: "memory");

  float o[16][4];
#pragma unroll
  for (int t = 0; t < 16; t++)
#pragma unroll
    for (int c = 0; c < 4; c++) o[t][c] = 0.f;
  float m0 = -1e30f, m1 = -1e30f, l0 = 0.f, l1 = 0.f;

  const int arow = w * 16 + (lane & 15);
  const int aoff = (lane >> 4) * 8;
  const int bRow = (lane >> 4) * 8 + (lane & 7);
  const int bCol = ((lane >> 3) & 1) * 8;
  const int vRow = (lane & 7) + ((lane >> 3) & 1) * 8;
  const int vCol = (lane >> 4) * 8;
  const int rloc = w * 16 + (lane >> 2);

  for (int kb = 0; kb <= qb; ++kb) {
#pragma unroll
    for (int j = 0; j < 8; j++) {
      int idx = tid + j * 128;
      int r = idx >> 4;
      int c = (idx & 15) * 16;
      size_t g = ((size_t)(kb * 64 + r) * NKVH + hkv) * 256 + c;
      uint32_t d = r * (FA_STRIDE * 2) + c;
      cp16(sKh + d, (const char*)Kh_ + g);
      cp16(sVh + d, (const char*)Vh_ + g);
      cp16(sVh + FA_MAT + d, (const char*)Vl_ + g);
    }
    asm volatile("cp.async.commit_group;" ::: "memory");
    asm volatile("cp.async.wait_group 0;" ::: "memory");
    __syncthreads();

    float sacc[8][4];
#pragma unroll
    for (int t = 0; t < 8; t++)
#pragma unroll
      for (int c = 0; c < 4; c++) sacc[t][c] = 0.f;

#pragma unroll
    for (int kk = 0; kk < 8; ++kk) {
      uint32_t qh[4], ql[4];
      uint32_t qa = sQh + (arow * FA_STRIDE + kk * 16 + aoff) * 2;
      LDSM4(qh, qa);
      LDSM4(ql, qa + FA_MAT);
#pragma unroll
      for (int np = 0; np < 4; np++) {
        uint32_t ka = sKh + ((np * 16 + bRow) * FA_STRIDE + kk * 16 + bCol) * 2;
        uint32_t kh[4];
        LDSM4(kh, ka);
        MMAH16816(sacc[2 * np], qh, kh);
        MMAH16816(sacc[2 * np], ql, kh);
        MMAH16816(sacc[2 * np + 1], qh, kh + 2);
        MMAH16816(sacc[2 * np + 1], ql, kh + 2);
      }
    }

    if (kb == qb) {
#pragma unroll
      for (int t = 0; t < 8; t++) {
        int n = t * 8 + (lane & 3) * 2;
        if (n > rloc) sacc[t][0] = -1e30f;
        if (n + 1 > rloc) sacc[t][1] = -1e30f;
        if (n > rloc + 8) sacc[t][2] = -1e30f;
        if (n + 1 > rloc + 8) sacc[t][3] = -1e30f;
      }
    }

    float mx0 = -1e30f, mx1 = -1e30f;
#pragma unroll
    for (int t = 0; t < 8; t++) {
      mx0 = fmaxf(mx0, fmaxf(sacc[t][0], sacc[t][1]));
      mx1 = fmaxf(mx1, fmaxf(sacc[t][2], sacc[t][3]));
    }
    mx0 = fmaxf(mx0, __shfl_xor_sync(0xffffffffu, mx0, 1));
    mx0 = fmaxf(mx0, __shfl_xor_sync(0xffffffffu, mx0, 2));
    mx1 = fmaxf(mx1, __shfl_xor_sync(0xffffffffu, mx1, 1));
    mx1 = fmaxf(mx1, __shfl_xor_sync(0xffffffffu, mx1, 2));
    float mn0 = fmaxf(m0, mx0), mn1 = fmaxf(m1, mx1);
    float al0 = __expf(m0 - mn0), al1 = __expf(m1 - mn1);
    m0 = mn0;
    m1 = mn1;
    float sum0 = 0.f, sum1 = 0.f;
#pragma unroll
    for (int t = 0; t < 8; t++) {
      sacc[t][0] = __expf(sacc[t][0] - m0);
      sacc[t][1] = __expf(sacc[t][1] - m0);
      sacc[t][2] = __expf(sacc[t][2] - m1);
      sacc[t][3] = __expf(sacc[t][3] - m1);
      sum0 += sacc[t][0] + sacc[t][1];
      sum1 += sacc[t][2] + sacc[t][3];
    }
    sum0 += __shfl_xor_sync(0xffffffffu, sum0, 1);
    sum0 += __shfl_xor_sync(0xffffffffu, sum0, 2);
    sum1 += __shfl_xor_sync(0xffffffffu, sum1, 1);
    sum1 += __shfl_xor_sync(0xffffffffu, sum1, 2);
    l0 = l0 * al0 + sum0;
    l1 = l1 * al1 + sum1;
#pragma unroll
    for (int t = 0; t < 16; t++) {
      o[t][0] *= al0;
      o[t][1] *= al0;
      o[t][2] *= al1;
      o[t][3] *= al1;
    }

    // O += P (Vh + Vl), P single fp16
#pragma unroll
    for (int j = 0; j < 4; j++) {
      uint32_t pha[4];
      pha[0] = h2bits(__floats2half2_rn(sacc[2 * j][0], sacc[2 * j][1]));
      pha[1] = h2bits(__floats2half2_rn(sacc[2 * j][2], sacc[2 * j][3]));
      pha[2] = h2bits(__floats2half2_rn(sacc[2 * j + 1][0], sacc[2 * j + 1][1]));
      pha[3] = h2bits(__floats2half2_rn(sacc[2 * j + 1][2], sacc[2 * j + 1][3]));
#pragma unroll
      for (int np = 0; np < 8; np++) {
        uint32_t va = sVh + ((j * 16 + vRow) * FA_STRIDE + np * 16 + vCol) * 2;
        uint32_t vh[4], vl[4];
        LDSM4T(vh, va);
        LDSM4T(vl, va + FA_MAT);
        MMAH16816(o[2 * np], pha, vh);
        MMAH16816(o[2 * np], pha, vl);
        MMAH16816(o[2 * np + 1], pha, vh + 2);
        MMAH16816(o[2 * np + 1], pha, vl + 2);
      }
    }
    __syncthreads();
  }

  // Epilogue: write context as fp16 hi/lo directly into out-proj A buffers
  float inv0 = 1.0f / l0, inv1 = 1.0f / l1;
  int r0 = qb * 64 + rloc;
#pragma unroll
  for (int t = 0; t < 16; t++) {
    int col = t * 8 + (lane & 3) * 2;
    {
      float v0 = o[t][0] * inv0, v1 = o[t][1] * inv0;
      __half h0 = __float2half_rn(v0), h1 = __float2half_rn(v1);
      __half2 hi; hi.x = h0; hi.y = h1;
      __half2 lo;
      lo.x = __float2half_rn(v0 - __half2float(h0));
      lo.y = __float2half_rn(v1 - __half2float(h1));
      size_t off = ((size_t)r0 * NQH + hq) * 128 + col;
      *(__half2*)(CtxHi + off) = hi;
      *(__half2*)(CtxLo + off) = lo;
    }
    {
      float v0 = o[t][2] * inv1, v1 = o[t][3] * inv1;
      __half h0 = __float2half_rn(v0), h1 = __float2half_rn(v1);
      __half2 hi; hi.x = h0; hi.y = h1;
      __half2 lo;
      lo.x = __float2half_rn(v0 - __half2float(h0));
      lo.y = __float2half_rn(v1 - __half2float(h1));
      size_t off = ((size_t)(r0 + 8) * NQH + hq) * 128 + col;
      *(__half2*)(CtxHi + off) = hi;
      *(__half2*)(CtxLo + off) = lo;
    }
  }
}

// ---------------------------------------------------------------------------
// Launch
// ---------------------------------------------------------------------------
extern "C" void kernel_launch(void* const* d_in, const int* in_sizes, int n_in,
                              void* d_out, int out_size) {
  const float* X = (const float*)d_in[0];
  const float* cosp = (const float*)d_in[1];
  const float* sinp = (const float*)d_in[2];
  const float* wq = (const float*)d_in[3];
  const float* wk = (const float*)d_in[4];
  const float* wv = (const float*)d_in[5];
  const float* wo = (const float*)d_in[6];
  float* out = (float*)d_out;

  float* QKV;
  __half *Ahi, *Alo, *Bh, *Qh, *Ql, *Kh, *Vh, *Vl;
  cudaGetSymbolAddress((void**)&QKV, g_QKV);
  cudaGetSymbolAddress((void**)&Ahi, g_Ahi);
  cudaGetSymbolAddress((void**)&Alo, g_Alo);
  cudaGetSymbolAddress((void**)&Bh, g_Bh);
  cudaGetSymbolAddress((void**)&Qh, g_Qh);
  cudaGetSymbolAddress((void**)&Ql, g_Ql);
  cudaGetSymbolAddress((void**)&Kh, g_Kh);
  cudaGetSymbolAddress((void**)&Vh, g_Vh);
  cudaGetSymbolAddress((void**)&Vl, g_Vl);

  cudaFuncSetAttribute(gemm_mma_h, cudaFuncAttributeMaxDynamicSharedMemorySize,
                       GEMM_SMEM);
  cudaFuncSetAttribute(flash_mma, cudaFuncAttributeMaxDynamicSharedMemorySize,
                       FA_SMEM);

  dim3 tblk(32, 8);

  // Activations -> fp16 hi/lo
  split_convert_h<<<(S_LEN * KDIM / 4 + 255) / 256, 256>>>(X, Ahi, Alo,
                                                           S_LEN * KDIM);
  // Fused QKV weights -> [N,K] fp16
  transpose_half<<<dim3(128, 128), tblk>>>(wq, Bh, KDIM, 4096);
  transpose_half<<<dim3(32, 128), tblk>>>(wk, Bh + (size_t)4096 * KDIM, KDIM,
                                          1024);
  transpose_half<<<dim3(32, 128), tblk>>>(wv, Bh + (size_t)5120 * KDIM, KDIM,
                                          1024);
  // Fused QKV projection (4-warp CTAs, 64x64 warp tiles, 3 CTAs/SM)
  gemm_mma_h<<<dim3(48, 16), dim3(128), GEMM_SMEM>>>(Ahi, Alo, Bh, QKV, NQKV);
  // RoPE + fp16 split for attention
  int rtot = S_LEN * NQH * 64 + 2 * S_LEN * NKVH * 64;
  rope_split<<<(rtot + 255) / 256, 256>>>(QKV, cosp, sinp);
  // Attention (fp16 2-term HMMA); writes context hi/lo directly into Ahi/Alo
  flash_mma<<<dim3(32, 32), dim3(128), FA_SMEM>>>(Qh, Ql, Kh, Vh, Vl, Ahi, Alo);
  // Output projection
  transpose_half<<<dim3(128, 128), tblk>>>(wo, Bh, KDIM, 4096);
  gemm_mma_h<<<dim3(32, 16), dim3(128), GEMM_SMEM>>>(Ahi, Alo, Bh, out, 4096);
}

// round 14
// speedup vs baseline: 2.7592x; 1.1175x over previous
#include <cuda_runtime.h>
#include <cuda_fp16.h>
#include <math.h>
#include <stdint.h>

#define S_LEN 2048
#define H_DIM 4096
#define NQH 32
#define NKVH 8
#define HDIM 128
#define KDIM 4096
#define NQKV 6144

// ---------------------------------------------------------------------------
// Scratch (device globals; no allocation allowed)
// ---------------------------------------------------------------------------
__device__ float g_QKV[S_LEN * NQKV];

// fp16 GEMM operands: activations hi/lo, weights single fp16 [N,K]
__device__ __half g_Ahi[S_LEN * KDIM];
__device__ __half g_Alo[S_LEN * KDIM];
__device__ __half g_Bh[NQKV * KDIM];

// attention operands (fp16; Q split, K single (scale folded), V split)
__device__ __half g_Qh[S_LEN * NQH * HDIM];
__device__ __half g_Ql[S_LEN * NQH * HDIM];
__device__ __half g_Kh[S_LEN * NKVH * HDIM];
__device__ __half g_Vh[S_LEN * NKVH * HDIM];
__device__ __half g_Vl[S_LEN * NKVH * HDIM];

// ---------------------------------------------------------------------------
// Helpers
// ---------------------------------------------------------------------------
__device__ __forceinline__ uint32_t smem_u32(const void* p) {
  uint32_t a;
  asm("{ .reg .u64 t; cvta.to.shared.u64 t, %1; cvt.u32.u64 %0, t; }"
      : "=r"(a) : "l"(p));
  return a;
}

__device__ __forceinline__ void cp16(uint32_t dst, const void* src) {
  asm volatile("cp.async.cg.shared.global [%0], [%1], 16;" ::"r"(dst), "l"(src));
}

#define LDSM4(R, ADDR)                                                         \
  asm volatile("ldmatrix.sync.aligned.m8n8.x4.shared.b16 {%0,%1,%2,%3}, [%4];" \
               : "=r"((R)[0]), "=r"((R)[1]), "=r"((R)[2]), "=r"((R)[3])        \
               : "r"(ADDR))

#define LDSM4T(R, ADDR)                                                        \
  asm volatile(                                                                \
      "ldmatrix.sync.aligned.m8n8.x4.trans.shared.b16 {%0,%1,%2,%3}, [%4];"    \
      : "=r"((R)[0]), "=r"((R)[1]), "=r"((R)[2]), "=r"((R)[3])                 \
      : "r"(ADDR))

// fp16 MMA
#define MMAH16816(D, A, B)                                                     \
  asm volatile(                                                                \
      "mma.sync.aligned.m16n8k16.row.col.f32.f16.f16.f32 "                     \
      "{%0,%1,%2,%3}, {%4,%5,%6,%7}, {%8,%9}, {%0,%1,%2,%3};"                  \
      : "+f"((D)[0]), "+f"((D)[1]), "+f"((D)[2]), "+f"((D)[3])                 \
      : "r"((A)[0]), "r"((A)[1]), "r"((A)[2]), "r"((A)[3]), "r"((B)[0]),       \
        "r"((B)[1]))

__device__ __forceinline__ uint32_t h2bits(__half2 v) {
  return *reinterpret_cast<uint32_t*>(&v);
}

// ---------------------------------------------------------------------------
// Split-convert fp32 -> fp16 hi/lo
// ---------------------------------------------------------------------------
__global__ void split_convert_h(const float* __restrict__ X,
                                __half* __restrict__ Hi,
                                __half* __restrict__ Lo, int n) {
  int i = (blockIdx.x * 256 + threadIdx.x) * 4;
  if (i >= n) return;
  float4 x = *(const float4*)(X + i);
  float v[4] = {x.x, x.y, x.z, x.w};
  __half h[4], l[4];
#pragma unroll
  for (int j = 0; j < 4; j++) {
    h[j] = __float2half_rn(v[j]);
    l[j] = __float2half_rn(v[j] - __half2float(h[j]));
  }
  __half2 h01, h23, l01, l23;
  h01.x = h[0]; h01.y = h[1]; h23.x = h[2]; h23.y = h[3];
  l01.x = l[0]; l01.y = l[1]; l23.x = l[2]; l23.y = l[3];
  *(__half2*)(Hi + i) = h01;
  *(__half2*)(Hi + i + 2) = h23;
  *(__half2*)(Lo + i) = l01;
  *(__half2*)(Lo + i + 2) = l23;
}

// ---------------------------------------------------------------------------
// Transpose-convert W[K,N] fp32 -> [N,K] fp16 (single)
// ---------------------------------------------------------------------------
__global__ void transpose_half(const float* __restrict__ W,
                               __half* __restrict__ Hi, int K, int N) {
  __shared__ float tile[32][33];
  int tx = threadIdx.x, ty = threadIdx.y;
  int k0 = blockIdx.y * 32, n0 = blockIdx.x * 32;
#pragma unroll
  for (int i = 0; i < 4; i++)
    tile[ty + i * 8][tx] = W[(size_t)(k0 + ty + i * 8) * N + n0 + tx];
  __syncthreads();
#pragma unroll
  for (int i = 0; i < 4; i++) {
    float v = tile[tx][ty + i * 8];
    Hi[(size_t)(n0 + ty + i * 8) * K + k0 + tx] = __float2half_rn(v);
  }
}

// ---------------------------------------------------------------------------
// fp16 2-term GEMM: C = (Ah+Al) * Bh^T  (B stored [N,K]).
// CTA tile 64x128, BK=32, 4 warps (2x2), warp tile 32x64.
// 2-stage cp.async pipeline, 4 CTAs/SM (16 warps/SM) -- small work quanta
// kill the wave-quantization tail (O-proj was 58% filled at 128x128 tiles).
// Stage: A hi 64r + A lo 64r + B 128r, 80 B/row = 20480 B.
// ---------------------------------------------------------------------------
#define NCH (KDIM / 32)
#define A_MAT 5120            // 64 * 80
#define B_OFF 10240           // A hi + A lo
#define STAGE_BYTES 20480
#define GEMM_SMEM (2 * STAGE_BYTES)  // 40960 -> 4 CTAs/SM

__global__ __launch_bounds__(128, 4) void gemm_mma_h(
    const __half* __restrict__ Ahi, const __half* __restrict__ Alo,
    const __half* __restrict__ Bh_, float* __restrict__ C, int N) {
  extern __shared__ char smc[];
  const int tid = threadIdx.x;
  const int lane = tid & 31, wid = tid >> 5;
  const int wm = wid & 1, wn = wid >> 1;  // 2x2 warp grid (32m x 64n tiles)
  const int bm = blockIdx.y * 64, bn = blockIdx.x * 128;
  const size_t Kb = (size_t)KDIM * 2;

  uint32_t sbase = smem_u32(smc);

  const char* gp0 = (const char*)Ahi + (size_t)bm * Kb;
  const char* gp1 = (const char*)Alo + (size_t)bm * Kb;
  const char* gp2 = (const char*)Bh_ + (size_t)bn * Kb;

  const int r = tid >> 2;          // 0..31
  const int cb = (tid & 3) * 16;   // 16B chunk in 64B row

  auto load_stage = [&](int stage, int k0) {
    uint32_t sb = sbase + stage * STAGE_BYTES;
    size_t gk = (size_t)k0 * 2;
#pragma unroll
    for (int j = 0; j < 2; j++) {  // A hi + lo rows r, r+32
      int rr = r + j * 32;
      cp16(sb + rr * 80 + cb, gp0 + (size_t)rr * Kb + gk + cb);
      cp16(sb + A_MAT + rr * 80 + cb, gp1 + (size_t)rr * Kb + gk + cb);
    }
#pragma unroll
    for (int j = 0; j < 4; j++) {  // B rows r, r+32, r+64, r+96
      int rr = r + j * 32;
      cp16(sb + B_OFF + rr * 80 + cb, gp2 + (size_t)rr * Kb + gk + cb);
    }
    asm volatile("cp.async.commit_group;" ::: "memory");
  };

  float acc[2][8][4];
#pragma unroll
  for (int a = 0; a < 2; a++)
#pragma unroll
    for (int b = 0; b < 8; b++)
#pragma unroll
      for (int c = 0; c < 4; c++) acc[a][b][c] = 0.f;

  const int arow = wm * 32 + (lane & 15);
  const int aoff = (lane >> 4) * 8;
  const int brow = wn * 64 + (lane >> 4) * 8 + (lane & 7);
  const int boff = ((lane >> 3) & 1) * 8;

  load_stage(0, 0);

  for (int i = 0; i < NCH; ++i) {
    if (i + 1 < NCH) {
      load_stage((i + 1) & 1, (i + 1) * 32);
      asm volatile("cp.async.wait_group 1;" ::: "memory");
    } else {
      asm volatile("cp.async.wait_group 0;" ::: "memory");
    }
    __syncthreads();

    uint32_t sb = sbase + (i & 1) * STAGE_BYTES;
    uint32_t sAh = sb;                  // Alo at +A_MAT
    uint32_t sBh = sb + B_OFF;

#pragma unroll
    for (int ks = 0; ks < 32; ks += 16) {
      uint32_t Bh[8][2];
#pragma unroll
      for (int ni = 0; ni < 4; ni++) {
        uint32_t bd = sBh + ((brow + ni * 16) * 40 + ks + boff) * 2;
        uint32_t t[4];
        LDSM4(t, bd);
        Bh[ni * 2][0] = t[0]; Bh[ni * 2][1] = t[1];
        Bh[ni * 2 + 1][0] = t[2]; Bh[ni * 2 + 1][1] = t[3];
      }
#pragma unroll
      for (int mi = 0; mi < 2; mi++) {
        uint32_t ad = sAh + ((arow + mi * 16) * 40 + ks + aoff) * 2;
        uint32_t Ah[4], Al[4];
        LDSM4(Ah, ad);
        LDSM4(Al, ad + A_MAT);
#pragma unroll
        for (int nj = 0; nj < 8; nj++) {
          MMAH16816(acc[mi][nj], Ah, Bh[nj]);
          MMAH16816(acc[mi][nj], Al, Bh[nj]);
        }
      }
    }
    __syncthreads();
  }

  const int tg = lane >> 2, tc = (lane & 3) * 2;
#pragma unroll
  for (int mi = 0; mi < 2; mi++) {
    int row = bm + wm * 32 + mi * 16 + tg;
#pragma unroll
    for (int nj = 0; nj < 8; nj++) {
      int col = bn + wn * 64 + nj * 8 + tc;
      float* p = C + (size_t)row * N + col;
      p[0] = acc[mi][nj][0];
      p[1] = acc[mi][nj][1];
      float* p2 = p + 8 * (size_t)N;
      p2[0] = acc[mi][nj][2];
      p2[1] = acc[mi][nj][3];
    }
  }
}

// ---------------------------------------------------------------------------
// RoPE + fp16 split for attention. Q split hi/lo (unscaled), K single fp16
// with softmax scale folded in, V split hi/lo.
// ---------------------------------------------------------------------------
#define FA_SCALE 0.08838834764831845f

__global__ void rope_split(const float* __restrict__ QKV,
                           const float* __restrict__ cosp,
                           const float* __restrict__ sinp) {
  int idx = blockIdx.x * blockDim.x + threadIdx.x;
  const int nq = S_LEN * NQH * 64;
  const int nk = S_LEN * NKVH * 64;
  if (idx < nq) {
    int d = idx & 63;
    int h = (idx >> 6) & 31;
    int s = idx >> 11;
    const float* src = QKV + (size_t)s * NQKV + h * 128;
    float c1 = cosp[s * 128 + d], s1 = sinp[s * 128 + d];
    float c2 = cosp[s * 128 + d + 64], s2 = sinp[s * 128 + d + 64];
    float x1 = src[d], x2 = src[d + 64];
    float y1 = x1 * c1 - x2 * s1;
    float y2 = x2 * c2 + x1 * s2;
    size_t o = ((size_t)s * NQH + h) * 128 + d;
    __half h1 = __float2half_rn(y1);
    __half h2 = __float2half_rn(y2);
    g_Qh[o] = h1;
    g_Ql[o] = __float2half_rn(y1 - __half2float(h1));
    g_Qh[o + 64] = h2;
    g_Ql[o + 64] = __float2half_rn(y2 - __half2float(h2));
  } else if (idx < nq + nk) {
    int t = idx - nq;
    int d = t & 63;
    int h = (t >> 6) & 7;
    int s = t >> 9;
    const float* src = QKV + (size_t)s * NQKV + 4096 + h * 128;
    float c1 = cosp[s * 128 + d], s1 = sinp[s * 128 + d];
    float c2 = cosp[s * 128 + d + 64], s2 = sinp[s * 128 + d + 64];
    float x1 = src[d], x2 = src[d + 64];
    float y1 = (x1 * c1 - x2 * s1) * FA_SCALE;
    float y2 = (x2 * c2 + x1 * s2) * FA_SCALE;
    size_t o = ((size_t)s * NKVH + h) * 128 + d;
    g_Kh[o] = __float2half_rn(y1);
    g_Kh[o + 64] = __float2half_rn(y2);
  } else if (idx < nq + 2 * nk) {
    int t = idx - nq - nk;
    int d = t & 63;
    int h = (t >> 6) & 7;
    int s = t >> 9;
    const float* src = QKV + (size_t)s * NQKV + 5120 + h * 128;
    float x1 = src[d], x2 = src[d + 64];
    size_t o = ((size_t)s * NKVH + h) * 128 + d;
    __half h1 = __float2half_rn(x1);
    __half h2 = __float2half_rn(x2);
    g_Vh[o] = h1;
    g_Vl[o] = __float2half_rn(x1 - __half2float(h1));
    g_Vh[o + 64] = h2;
    g_Vl[o + 64] = __float2half_rn(x2 - __half2float(h2));
  }
}

// ---------------------------------------------------------------------------
// fp16 flash attention, causal, GQA. Tile 64x64, HD=128, 4 warps.
// 2-term: S = (Qh+Ql)K, O += P(Vh+Vl). SMEM 5 mats = 87040 B -> 2 CTAs/SM.
// Epilogue writes context directly as fp16 hi/lo into the out-proj A buffers.
// ---------------------------------------------------------------------------
#define FA_STRIDE 136
#define FA_MAT 17408
#define FA_SMEM (5 * FA_MAT)  // 87040

__global__ __launch_bounds__(128) void flash_mma(
    const __half* __restrict__ Qh_, const __half* __restrict__ Ql_,
    const __half* __restrict__ Kh_, const __half* __restrict__ Vh_,
    const __half* __restrict__ Vl_, __half* __restrict__ CtxHi,
    __half* __restrict__ CtxLo) {
  extern __shared__ char smf[];
  const uint32_t sb = smem_u32(smf);
  const uint32_t sQh = sb;                   // Qh, Ql
  const uint32_t sKh = sb + 2 * FA_MAT;      // K single
  const uint32_t sVh = sb + 3 * FA_MAT;      // Vh, Vl

  const int tid = threadIdx.x;
  const int lane = tid & 31, w = tid >> 5;
  const int qb = (int)gridDim.x - 1 - (int)blockIdx.x;
  const int hq = blockIdx.y, hkv = hq >> 2;

#pragma unroll
  for (int j = 0; j < 8; j++) {
    int idx = tid + j * 128;
    int r = idx >> 4;
    int c = (idx & 15) * 16;
    size_t g = ((size_t)(qb * 64 + r) * NQH + hq) * 256 + c;
    uint32_t d = r * (FA_STRIDE * 2) + c;
    cp16(sQh + d, (const char*)Qh_ + g);
    cp16(sQh + FA_MAT + d, (const char*)Ql_ + g);
  }
  asm volatile("cp.async.commit_group;" ::: "memory");

  float o[16][4];
#pragma unroll
  for (int t = 0; t < 16; t++)
#pragma unroll
    for (int c = 0; c < 4; c++) o[t][c] = 0.f;
  float m0 = -1e30f, m1 = -1e30f, l0 = 0.f, l1 = 0.f;

  const int arow = w * 16 + (lane & 15);
  const int aoff = (lane >> 4) * 8;
  const int bRow = (lane >> 4) * 8 + (lane & 7);
  const int bCol = ((lane >> 3) & 1) * 8;
  const int vRow = (lane & 7) + ((lane >> 3) & 1) * 8;
  const int vCol = (lane >> 4) * 8;
  const int rloc = w * 16 + (lane >> 2);

  for (int kb = 0; kb <= qb; ++kb) {
#pragma unroll
    for (int j = 0; j < 8; j++) {
      int idx = tid + j * 128;
      int r = idx >> 4;
      int c = (idx & 15) * 16;
      size_t g = ((size_t)(kb * 64 + r) * NKVH + hkv) * 256 + c;
      uint32_t d = r * (FA_STRIDE * 2) + c;
      cp16(sKh + d, (const char*)Kh_ + g);
      cp16(sVh + d, (const char*)Vh_ + g);
      cp16(sVh + FA_MAT + d, (const char*)Vl_ + g);
    }
    asm volatile("cp.async.commit_group;" ::: "memory");
    asm volatile("cp.async.wait_group 0;" ::: "memory");
    __syncthreads();

    float sacc[8][4];
#pragma unroll
    for (int t = 0; t < 8; t++)
#pragma unroll
      for (int c = 0; c < 4; c++) sacc[t][c] = 0.f;

#pragma unroll
    for (int kk = 0; kk < 8; ++kk) {
      uint32_t qh[4], ql[4];
      uint32_t qa = sQh + (arow * FA_STRIDE + kk * 16 + aoff) * 2;
      LDSM4(qh, qa);
      LDSM4(ql, qa + FA_MAT);
#pragma unroll
      for (int np = 0; np < 4; np++) {
        uint32_t ka = sKh + ((np * 16 + bRow) * FA_STRIDE + kk * 16 + bCol) * 2;
        uint32_t kh[4];
        LDSM4(kh, ka);
        MMAH16816(sacc[2 * np], qh, kh);
        MMAH16816(sacc[2 * np], ql, kh);
        MMAH16816(sacc[2 * np + 1], qh, kh + 2);
        MMAH16816(sacc[2 * np + 1], ql, kh + 2);
      }
    }

    if (kb == qb) {
#pragma unroll
      for (int t = 0; t < 8; t++) {
        int n = t * 8 + (lane & 3) * 2;
        if (n > rloc) sacc[t][0] = -1e30f;
        if (n + 1 > rloc) sacc[t][1] = -1e30f;
        if (n > rloc + 8) sacc[t][2] = -1e30f;
        if (n + 1 > rloc + 8) sacc[t][3] = -1e30f;
      }
    }

    float mx0 = -1e30f, mx1 = -1e30f;
#pragma unroll
    for (int t = 0; t < 8; t++) {
      mx0 = fmaxf(mx0, fmaxf(sacc[t][0], sacc[t][1]));
      mx1 = fmaxf(mx1, fmaxf(sacc[t][2], sacc[t][3]));
    }
    mx0 = fmaxf(mx0, __shfl_xor_sync(0xffffffffu, mx0, 1));
    mx0 = fmaxf(mx0, __shfl_xor_sync(0xffffffffu, mx0, 2));
    mx1 = fmaxf(mx1, __shfl_xor_sync(0xffffffffu, mx1, 1));
    mx1 = fmaxf(mx1, __shfl_xor_sync(0xffffffffu, mx1, 2));
    float mn0 = fmaxf(m0, mx0), mn1 = fmaxf(m1, mx1);
    float al0 = __expf(m0 - mn0), al1 = __expf(m1 - mn1);
    m0 = mn0;
    m1 = mn1;
    float sum0 = 0.f, sum1 = 0.f;
#pragma unroll
    for (int t = 0; t < 8; t++) {
      sacc[t][0] = __expf(sacc[t][0] - m0);
      sacc[t][1] = __expf(sacc[t][1] - m0);
      sacc[t][2] = __expf(sacc[t][2] - m1);
      sacc[t][3] = __expf(sacc[t][3] - m1);
      sum0 += sacc[t][0] + sacc[t][1];
      sum1 += sacc[t][2] + sacc[t][3];
    }
    sum0 += __shfl_xor_sync(0xffffffffu, sum0, 1);
    sum0 += __shfl_xor_sync(0xffffffffu, sum0, 2);
    sum1 += __shfl_xor_sync(0xffffffffu, sum1, 1);
    sum1 += __shfl_xor_sync(0xffffffffu, sum1, 2);
    l0 = l0 * al0 + sum0;
    l1 = l1 * al1 + sum1;
#pragma unroll
    for (int t = 0; t < 16; t++) {
      o[t][0] *= al0;
      o[t][1] *= al0;
      o[t][2] *= al1;
      o[t][3] *= al1;
    }

    // O += P (Vh + Vl), P single fp16
#pragma unroll
    for (int j = 0; j < 4; j++) {
      uint32_t pha[4];
      pha[0] = h2bits(__floats2half2_rn(sacc[2 * j][0], sacc[2 * j][1]));
      pha[1] = h2bits(__floats2half2_rn(sacc[2 * j][2], sacc[2 * j][3]));
      pha[2] = h2bits(__floats2half2_rn(sacc[2 * j + 1][0], sacc[2 * j + 1][1]));
      pha[3] = h2bits(__floats2half2_rn(sacc[2 * j + 1][2], sacc[2 * j + 1][3]));
#pragma unroll
      for (int np = 0; np < 8; np++) {
        uint32_t va = sVh + ((j * 16 + vRow) * FA_STRIDE + np * 16 + vCol) * 2;
        uint32_t vh[4], vl[4];
        LDSM4T(vh, va);
        LDSM4T(vl, va + FA_MAT);
        MMAH16816(o[2 * np], pha, vh);
        MMAH16816(o[2 * np], pha, vl);
        MMAH16816(o[2 * np + 1], pha, vh + 2);
        MMAH16816(o[2 * np + 1], pha, vl + 2);
      }
    }
    __syncthreads();
  }

  // Epilogue: write context as fp16 hi/lo directly into out-proj A buffers
  float inv0 = 1.0f / l0, inv1 = 1.0f / l1;
  int r0 = qb * 64 + rloc;
#pragma unroll
  for (int t = 0; t < 16; t++) {
    int col = t * 8 + (lane & 3) * 2;
    {
      float v0 = o[t][0] * inv0, v1 = o[t][1] * inv0;
      __half h0 = __float2half_rn(v0), h1 = __float2half_rn(v1);
      __half2 hi; hi.x = h0; hi.y = h1;
      __half2 lo;
      lo.x = __float2half_rn(v0 - __half2float(h0));
      lo.y = __float2half_rn(v1 - __half2float(h1));
      size_t off = ((size_t)r0 * NQH + hq) * 128 + col;
      *(__half2*)(CtxHi + off) = hi;
      *(__half2*)(CtxLo + off) = lo;
    }
    {
      float v0 = o[t][2] * inv1, v1 = o[t][3] * inv1;
      __half h0 = __float2half_rn(v0), h1 = __float2half_rn(v1);
      __half2 hi; hi.x = h0; hi.y = h1;
      __half2 lo;
      lo.x = __float2half_rn(v0 - __half2float(h0));
      lo.y = __float2half_rn(v1 - __half2float(h1));
      size_t off = ((size_t)(r0 + 8) * NQH + hq) * 128 + col;
      *(__half2*)(CtxHi + off) = hi;
      *(__half2*)(CtxLo + off) = lo;
    }
  }
}

// ---------------------------------------------------------------------------
// Launch
// ---------------------------------------------------------------------------
extern "C" void kernel_launch(void* const* d_in, const int* in_sizes, int n_in,
                              void* d_out, int out_size) {
  const float* X = (const float*)d_in[0];
  const float* cosp = (const float*)d_in[1];
  const float* sinp = (const float*)d_in[2];
  const float* wq = (const float*)d_in[3];
  const float* wk = (const float*)d_in[4];
  const float* wv = (const float*)d_in[5];
  const float* wo = (const float*)d_in[6];
  float* out = (float*)d_out;

  float* QKV;
  __half *Ahi, *Alo, *Bh, *Qh, *Ql, *Kh, *Vh, *Vl;
  cudaGetSymbolAddress((void**)&QKV, g_QKV);
  cudaGetSymbolAddress((void**)&Ahi, g_Ahi);
  cudaGetSymbolAddress((void**)&Alo, g_Alo);
  cudaGetSymbolAddress((void**)&Bh, g_Bh);
  cudaGetSymbolAddress((void**)&Qh, g_Qh);
  cudaGetSymbolAddress((void**)&Ql, g_Ql);
  cudaGetSymbolAddress((void**)&Kh, g_Kh);
  cudaGetSymbolAddress((void**)&Vh, g_Vh);
  cudaGetSymbolAddress((void**)&Vl, g_Vl);

  cudaFuncSetAttribute(gemm_mma_h, cudaFuncAttributeMaxDynamicSharedMemorySize,
                       GEMM_SMEM);
  cudaFuncSetAttribute(flash_mma, cudaFuncAttributeMaxDynamicSharedMemorySize,
                       FA_SMEM);

  dim3 tblk(32, 8);

  // Activations -> fp16 hi/lo
  split_convert_h<<<(S_LEN * KDIM / 4 + 255) / 256, 256>>>(X, Ahi, Alo,
                                                           S_LEN * KDIM);
  // Fused QKV weights -> [N,K] fp16
  transpose_half<<<dim3(128, 128), tblk>>>(wq, Bh, KDIM, 4096);
  transpose_half<<<dim3(32, 128), tblk>>>(wk, Bh + (size_t)4096 * KDIM, KDIM,
                                          1024);
  transpose_half<<<dim3(32, 128), tblk>>>(wv, Bh + (size_t)5120 * KDIM, KDIM,
                                          1024);
  // Fused QKV projection (64x128 tiles, 4 CTAs/SM)
  gemm_mma_h<<<dim3(48, 32), dim3(128), GEMM_SMEM>>>(Ahi, Alo, Bh, QKV, NQKV);
  // RoPE + fp16 split for attention
  int rtot = S_LEN * NQH * 64 + 2 * S_LEN * NKVH * 64;
  rope_split<<<(rtot + 255) / 256, 256>>>(QKV, cosp, sinp);
  // Attention (fp16 2-term HMMA); writes context hi/lo directly into Ahi/Alo
  flash_mma<<<dim3(32, 32), dim3(128), FA_SMEM>>>(Qh, Ql, Kh, Vh, Vl, Ahi, Alo);
  // Output projection (64x128 tiles)
  transpose_half<<<dim3(128, 128), tblk>>>(wo, Bh, KDIM, 4096);
  gemm_mma_h<<<dim3(32, 32), dim3(128), GEMM_SMEM>>>(Ahi, Alo, Bh, out, 4096);
}

// round 15
// speedup vs baseline: 3.0140x; 1.0924x over previous
#include <cuda_runtime.h>
#include <cuda_fp16.h>
#include <math.h>
#include <stdint.h>

#define S_LEN 2048
#define H_DIM 4096
#define NQH 32
#define NKVH 8
#define HDIM 128
#define KDIM 4096
#define NQKV 6144

// ---------------------------------------------------------------------------
// Scratch (device globals; no allocation allowed)
// ---------------------------------------------------------------------------
__device__ float g_QKV[S_LEN * NQKV];

// fp16 GEMM operands: activations hi/lo [M,K]; weights fp16 in NATURAL [K,N]
__device__ __half g_Ahi[S_LEN * KDIM];
__device__ __half g_Alo[S_LEN * KDIM];
__device__ __half g_Bh[KDIM * NQKV];

// attention operands (fp16; Q split, K single (scale folded), V split)
__device__ __half g_Qh[S_LEN * NQH * HDIM];
__device__ __half g_Ql[S_LEN * NQH * HDIM];
__device__ __half g_Kh[S_LEN * NKVH * HDIM];
__device__ __half g_Vh[S_LEN * NKVH * HDIM];
__device__ __half g_Vl[S_LEN * NKVH * HDIM];

// ---------------------------------------------------------------------------
// Helpers
// ---------------------------------------------------------------------------
__device__ __forceinline__ uint32_t smem_u32(const void* p) {
  uint32_t a;
  asm("{ .reg .u64 t; cvta.to.shared.u64 t, %1; cvt.u32.u64 %0, t; }"
      : "=r"(a) : "l"(p));
  return a;
}

__device__ __forceinline__ void cp16(uint32_t dst, const void* src) {
  asm volatile("cp.async.cg.shared.global [%0], [%1], 16;" ::"r"(dst), "l"(src));
}

#define LDSM4(R, ADDR)                                                         \
  asm volatile("ldmatrix.sync.aligned.m8n8.x4.shared.b16 {%0,%1,%2,%3}, [%4];" \
               : "=r"((R)[0]), "=r"((R)[1]), "=r"((R)[2]), "=r"((R)[3])        \
               : "r"(ADDR))

#define LDSM4T(R, ADDR)                                                        \
  asm volatile(                                                                \
      "ldmatrix.sync.aligned.m8n8.x4.trans.shared.b16 {%0,%1,%2,%3}, [%4];"    \
      : "=r"((R)[0]), "=r"((R)[1]), "=r"((R)[2]), "=r"((R)[3])                 \
      : "r"(ADDR))

// fp16 MMA
#define MMAH16816(D, A, B)                                                     \
  asm volatile(                                                                \
      "mma.sync.aligned.m16n8k16.row.col.f32.f16.f16.f32 "                     \
      "{%0,%1,%2,%3}, {%4,%5,%6,%7}, {%8,%9}, {%0,%1,%2,%3};"                  \
      : "+f"((D)[0]), "+f"((D)[1]), "+f"((D)[2]), "+f"((D)[3])                 \
      : "r"((A)[0]), "r"((A)[1]), "r"((A)[2]), "r"((A)[3]), "r"((B)[0]),       \
        "r"((B)[1]))

__device__ __forceinline__ uint32_t h2bits(__half2 v) {
  return *reinterpret_cast<uint32_t*>(&v);
}

// ---------------------------------------------------------------------------
// Split-convert fp32 -> fp16 hi/lo
// ---------------------------------------------------------------------------
__global__ void split_convert_h(const float* __restrict__ X,
                                __half* __restrict__ Hi,
                                __half* __restrict__ Lo, int n) {
  int i = (blockIdx.x * 256 + threadIdx.x) * 4;
  if (i >= n) return;
  float4 x = *(const float4*)(X + i);
  float v[4] = {x.x, x.y, x.z, x.w};
  __half h[4], l[4];
#pragma unroll
  for (int j = 0; j < 4; j++) {
    h[j] = __float2half_rn(v[j]);
    l[j] = __float2half_rn(v[j] - __half2float(h[j]));
  }
  __half2 h01, h23, l01, l23;
  h01.x = h[0]; h01.y = h[1]; h23.x = h[2]; h23.y = h[3];
  l01.x = l[0]; l01.y = l[1]; l23.x = l[2]; l23.y = l[3];
  *(__half2*)(Hi + i) = h01;
  *(__half2*)(Hi + i + 2) = h23;
  *(__half2*)(Lo + i) = l01;
  *(__half2*)(Lo + i + 2) = l23;
}

// ---------------------------------------------------------------------------
// Fused QKV weight convert: wq[K,4096], wk[K,1024], wv[K,1024] (fp32)
//   -> g_Bh [K, 6144] fp16, columns [0:4096)=q, [4096:5120)=k, [5120:6144)=v.
// Fully coalesced (no transpose needed; GEMM uses ldmatrix.trans).
// ---------------------------------------------------------------------------
__global__ void convert_wqkv(const float* __restrict__ wq,
                             const float* __restrict__ wk,
                             const float* __restrict__ wv,
                             __half* __restrict__ B) {
  int i = (blockIdx.x * 256 + threadIdx.x) * 4;
  if (i >= KDIM * NQKV) return;
  int k = i / NQKV, n = i % NQKV;
  const float* src;
  if (n < 4096)
    src = wq + (size_t)k * 4096 + n;
  else if (n < 5120)
    src = wk + (size_t)k * 1024 + (n - 4096);
  else
    src = wv + (size_t)k * 1024 + (n - 5120);
  float4 v = *(const float4*)src;
  __half2 a, b;
  a.x = __float2half_rn(v.x); a.y = __float2half_rn(v.y);
  b.x = __float2half_rn(v.z); b.y = __float2half_rn(v.w);
  *(__half2*)(B + i) = a;
  *(__half2*)(B + i + 2) = b;
}

// Plain fp32 -> fp16 convert (for wo, same layout)
__global__ void convert_plain(const float* __restrict__ W,
                              __half* __restrict__ B, int n) {
  int i = (blockIdx.x * 256 + threadIdx.x) * 4;
  if (i >= n) return;
  float4 v = *(const float4*)(W + i);
  __half2 a, b;
  a.x = __float2half_rn(v.x); a.y = __float2half_rn(v.y);
  b.x = __float2half_rn(v.z); b.y = __float2half_rn(v.w);
  *(__half2*)(B + i) = a;
  *(__half2*)(B + i + 2) = b;
}

// ---------------------------------------------------------------------------
// fp16 2-term GEMM: C = (Ah+Al) * W  (W stored natural [K,N] fp16).
// CTA tile 64x128, BK=32, 4 warps (2x2), warp tile 32x64.
// A tiles k-major (LDSM4); B tiles loaded as 32 k-rows x 128 n-cols and
// fragments built with LDSM4T (pattern identical to flash PV path).
// 2-stage cp.async, 4 CTAs/SM.
// Stage: A hi/lo 2x(64x80B) + B 32x272B = 18944 B.
// ---------------------------------------------------------------------------
#define NCH (KDIM / 32)
#define A_MAT 5120            // 64 * 80
#define B_OFF 10240
#define B_STRIDE 136          // halves; 272B rows (proven conflict-free)
#define STAGE_BYTES 18944
#define GEMM_SMEM (2 * STAGE_BYTES)  // 37888 -> 4 CTAs/SM

__global__ __launch_bounds__(128, 4) void gemm_mma_h(
    const __half* __restrict__ Ahi, const __half* __restrict__ Alo,
    const __half* __restrict__ Bh_, float* __restrict__ C, int N) {
  extern __shared__ char smc[];
  const int tid = threadIdx.x;
  const int lane = tid & 31, wid = tid >> 5;
  const int wm = wid & 1, wn = wid >> 1;  // 2x2 warp grid (32m x 64n)
  const int bm = blockIdx.y * 64, bn = blockIdx.x * 128;
  const size_t Kb = (size_t)KDIM * 2;
  const size_t Nb = (size_t)N * 2;

  uint32_t sbase = smem_u32(smc);

  const char* gp0 = (const char*)Ahi + (size_t)bm * Kb;
  const char* gp1 = (const char*)Alo + (size_t)bm * Kb;
  const char* gp2 = (const char*)Bh_ + (size_t)bn * 2;  // column offset

  const int rA = tid >> 2;          // 0..31
  const int cA = (tid & 3) * 16;    // 16B chunk in 64B row
  const int rB = tid >> 4;          // 0..7
  const int cB = (tid & 15) * 16;   // 16B chunk in 256B row

  auto load_stage = [&](int stage, int k0) {
    uint32_t sb = sbase + stage * STAGE_BYTES;
    size_t gkA = (size_t)k0 * 2;
#pragma unroll
    for (int j = 0; j < 2; j++) {  // A hi + lo rows rA, rA+32
      int rr = rA + j * 32;
      cp16(sb + rr * 80 + cA, gp0 + (size_t)rr * Kb + gkA + cA);
      cp16(sb + A_MAT + rr * 80 + cA, gp1 + (size_t)rr * Kb + gkA + cA);
    }
#pragma unroll
    for (int j = 0; j < 4; j++) {  // B k-rows rB, +8, +16, +24
      int rr = rB + j * 8;
      cp16(sb + B_OFF + rr * (B_STRIDE * 2) + cB,
           gp2 + (size_t)(k0 + rr) * Nb + cB);
    }
    asm volatile("cp.async.commit_group;" ::: "memory");
  };

  float acc[2][8][4];
#pragma unroll
  for (int a = 0; a < 2; a++)
#pragma unroll
    for (int b = 0; b < 8; b++)
#pragma unroll
      for (int c = 0; c < 4; c++) acc[a][b][c] = 0.f;

  const int arow = wm * 32 + (lane & 15);
  const int aoff = (lane >> 4) * 8;
  // LDSM4T mapping (same as flash V path)
  const int bRowT = (lane & 7) + ((lane >> 3) & 1) * 8;
  const int bColT = (lane >> 4) * 8;

  load_stage(0, 0);

  for (int i = 0; i < NCH; ++i) {
    if (i + 1 < NCH) {
      load_stage((i + 1) & 1, (i + 1) * 32);
      asm volatile("cp.async.wait_group 1;" ::: "memory");
    } else {
      asm volatile("cp.async.wait_group 0;" ::: "memory");
    }
    __syncthreads();

    uint32_t sb = sbase + (i & 1) * STAGE_BYTES;
    uint32_t sAh = sb;                  // Alo at +A_MAT
    uint32_t sB = sb + B_OFF;

#pragma unroll
    for (int ks = 0; ks < 32; ks += 16) {
      uint32_t Bf[8][2];
#pragma unroll
      for (int ni = 0; ni < 4; ni++) {
        uint32_t bd =
            sB + ((ks + bRowT) * B_STRIDE + wn * 64 + ni * 16 + bColT) * 2;
        uint32_t t[4];
        LDSM4T(t, bd);
        Bf[ni * 2][0] = t[0]; Bf[ni * 2][1] = t[1];
        Bf[ni * 2 + 1][0] = t[2]; Bf[ni * 2 + 1][1] = t[3];
      }
#pragma unroll
      for (int mi = 0; mi < 2; mi++) {
        uint32_t ad = sAh + ((arow + mi * 16) * 40 + ks + aoff) * 2;
        uint32_t Ah[4], Al[4];
        LDSM4(Ah, ad);
        LDSM4(Al, ad + A_MAT);
#pragma unroll
        for (int nj = 0; nj < 8; nj++) {
          MMAH16816(acc[mi][nj], Ah, Bf[nj]);
          MMAH16816(acc[mi][nj], Al, Bf[nj]);
        }
      }
    }
    __syncthreads();
  }

  const int tg = lane >> 2, tc = (lane & 3) * 2;
#pragma unroll
  for (int mi = 0; mi < 2; mi++) {
    int row = bm + wm * 32 + mi * 16 + tg;
#pragma unroll
    for (int nj = 0; nj < 8; nj++) {
      int col = bn + wn * 64 + nj * 8 + tc;
      float* p = C + (size_t)row * N + col;
      p[0] = acc[mi][nj][0];
      p[1] = acc[mi][nj][1];
      float* p2 = p + 8 * (size_t)N;
      p2[0] = acc[mi][nj][2];
      p2[1] = acc[mi][nj][3];
    }
  }
}

// ---------------------------------------------------------------------------
// RoPE + fp16 split for attention. Q split hi/lo (unscaled), K single fp16
// with softmax scale folded in, V split hi/lo.
// ---------------------------------------------------------------------------
#define FA_SCALE 0.08838834764831845f

__global__ void rope_split(const float* __restrict__ QKV,
                           const float* __restrict__ cosp,
                           const float* __restrict__ sinp) {
  int idx = blockIdx.x * blockDim.x + threadIdx.x;
  const int nq = S_LEN * NQH * 64;
  const int nk = S_LEN * NKVH * 64;
  if (idx < nq) {
    int d = idx & 63;
    int h = (idx >> 6) & 31;
    int s = idx >> 11;
    const float* src = QKV + (size_t)s * NQKV + h * 128;
    float c1 = cosp[s * 128 + d], s1 = sinp[s * 128 + d];
    float c2 = cosp[s * 128 + d + 64], s2 = sinp[s * 128 + d + 64];
    float x1 = src[d], x2 = src[d + 64];
    float y1 = x1 * c1 - x2 * s1;
    float y2 = x2 * c2 + x1 * s2;
    size_t o = ((size_t)s * NQH + h) * 128 + d;
    __half h1 = __float2half_rn(y1);
    __half h2 = __float2half_rn(y2);
    g_Qh[o] = h1;
    g_Ql[o] = __float2half_rn(y1 - __half2float(h1));
    g_Qh[o + 64] = h2;
    g_Ql[o + 64] = __float2half_rn(y2 - __half2float(h2));
  } else if (idx < nq + nk) {
    int t = idx - nq;
    int d = t & 63;
    int h = (t >> 6) & 7;
    int s = t >> 9;
    const float* src = QKV + (size_t)s * NQKV + 4096 + h * 128;
    float c1 = cosp[s * 128 + d], s1 = sinp[s * 128 + d];
    float c2 = cosp[s * 128 + d + 64], s2 = sinp[s * 128 + d + 64];
    float x1 = src[d], x2 = src[d + 64];
    float y1 = (x1 * c1 - x2 * s1) * FA_SCALE;
    float y2 = (x2 * c2 + x1 * s2) * FA_SCALE;
    size_t o = ((size_t)s * NKVH + h) * 128 + d;
    g_Kh[o] = __float2half_rn(y1);
    g_Kh[o + 64] = __float2half_rn(y2);
  } else if (idx < nq + 2 * nk) {
    int t = idx - nq - nk;
    int d = t & 63;
    int h = (t >> 6) & 7;
    int s = t >> 9;
    const float* src = QKV + (size_t)s * NQKV + 5120 + h * 128;
    float x1 = src[d], x2 = src[d + 64];
    size_t o = ((size_t)s * NKVH + h) * 128 + d;
    __half h1 = __float2half_rn(x1);
    __half h2 = __float2half_rn(x2);
    g_Vh[o] = h1;
    g_Vl[o] = __float2half_rn(x1 - __half2float(h1));
    g_Vh[o + 64] = h2;
    g_Vl[o + 64] = __float2half_rn(x2 - __half2float(h2));
  }
}

// ---------------------------------------------------------------------------
// fp16 flash attention, causal, GQA. Tile 64x64, HD=128, 4 warps.
// 2-term: S = (Qh+Ql)K, O += P(Vh+Vl). SMEM 5 mats = 87040 B -> 2 CTAs/SM.
// Epilogue writes context directly as fp16 hi/lo into the out-proj A buffers.
// ---------------------------------------------------------------------------
#define FA_STRIDE 136
#define FA_MAT 17408
#define FA_SMEM (5 * FA_MAT)  // 87040

__global__ __launch_bounds__(128) void flash_mma(
    const __half* __restrict__ Qh_, const __half* __restrict__ Ql_,
    const __half* __restrict__ Kh_, const __half* __restrict__ Vh_,
    const __half* __restrict__ Vl_, __half* __restrict__ CtxHi,
    __half* __restrict__ CtxLo) {
  extern __shared__ char smf[];
  const uint32_t sb = smem_u32(smf);
  const uint32_t sQh = sb;                   // Qh, Ql
  const uint32_t sKh = sb + 2 * FA_MAT;      // K single
  const uint32_t sVh = sb + 3 * FA_MAT;      // Vh, Vl

  const int tid = threadIdx.x;
  const int lane = tid & 31, w = tid >> 5;
  const int qb = (int)gridDim.x - 1 - (int)blockIdx.x;
  const int hq = blockIdx.y, hkv = hq >> 2;

#pragma unroll
  for (int j = 0; j < 8; j++) {
    int idx = tid + j * 128;
    int r = idx >> 4;
    int c = (idx & 15) * 16;
    size_t g = ((size_t)(qb * 64 + r) * NQH + hq) * 256 + c;
    uint32_t d = r * (FA_STRIDE * 2) + c;
    cp16(sQh + d, (const char*)Qh_ + g);
    cp16(sQh + FA_MAT + d, (const char*)Ql_ + g);
  }
  asm volatile("cp.async.commit_group;" ::: "memory");

  float o[16][4];
#pragma unroll
  for (int t = 0; t < 16; t++)
#pragma unroll
    for (int c = 0; c < 4; c++) o[t][c] = 0.f;
  float m0 = -1e30f, m1 = -1e30f, l0 = 0.f, l1 = 0.f;

  const int arow = w * 16 + (lane & 15);
  const int aoff = (lane >> 4) * 8;
  const int bRow = (lane >> 4) * 8 + (lane & 7);
  const int bCol = ((lane >> 3) & 1) * 8;
  const int vRow = (lane & 7) + ((lane >> 3) & 1) * 8;
  const int vCol = (lane >> 4) * 8;
  const int rloc = w * 16 + (lane >> 2);

  for (int kb = 0; kb <= qb; ++kb) {
#pragma unroll
    for (int j = 0; j < 8; j++) {
      int idx = tid + j * 128;
      int r = idx >> 4;
      int c = (idx & 15) * 16;
      size_t g = ((size_t)(kb * 64 + r) * NKVH + hkv) * 256 + c;
      uint32_t d = r * (FA_STRIDE * 2) + c;
      cp16(sKh + d, (const char*)Kh_ + g);
      cp16(sVh + d, (const char*)Vh_ + g);
      cp16(sVh + FA_MAT + d, (const char*)Vl_ + g);
    }
    asm volatile("cp.async.commit_group;" ::: "memory");
    asm volatile("cp.async.wait_group 0;" ::: "memory");
    __syncthreads();

    float sacc[8][4];
#pragma unroll
    for (int t = 0; t < 8; t++)
#pragma unroll
      for (int c = 0; c < 4; c++) sacc[t][c] = 0.f;

#pragma unroll
    for (int kk = 0; kk < 8; ++kk) {
      uint32_t qh[4], ql[4];
      uint32_t qa = sQh + (arow * FA_STRIDE + kk * 16 + aoff) * 2;
      LDSM4(qh, qa);
      LDSM4(ql, qa + FA_MAT);
#pragma unroll
      for (int np = 0; np < 4; np++) {
        uint32_t ka = sKh + ((np * 16 + bRow) * FA_STRIDE + kk * 16 + bCol) * 2;
        uint32_t kh[4];
        LDSM4(kh, ka);
        MMAH16816(sacc[2 * np], qh, kh);
        MMAH16816(sacc[2 * np], ql, kh);
        MMAH16816(sacc[2 * np + 1], qh, kh + 2);
        MMAH16816(sacc[2 * np + 1], ql, kh + 2);
      }
    }

    if (kb == qb) {
#pragma unroll
      for (int t = 0; t < 8; t++) {
        int n = t * 8 + (lane & 3) * 2;
        if (n > rloc) sacc[t][0] = -1e30f;
        if (n + 1 > rloc) sacc[t][1] = -1e30f;
        if (n > rloc + 8) sacc[t][2] = -1e30f;
        if (n + 1 > rloc + 8) sacc[t][3] = -1e30f;
      }
    }

    float mx0 = -1e30f, mx1 = -1e30f;
#pragma unroll
    for (int t = 0; t < 8; t++) {
      mx0 = fmaxf(mx0, fmaxf(sacc[t][0], sacc[t][1]));
      mx1 = fmaxf(mx1, fmaxf(sacc[t][2], sacc[t][3]));
    }
    mx0 = fmaxf(mx0, __shfl_xor_sync(0xffffffffu, mx0, 1));
    mx0 = fmaxf(mx0, __shfl_xor_sync(0xffffffffu, mx0, 2));
    mx1 = fmaxf(mx1, __shfl_xor_sync(0xffffffffu, mx1, 1));
    mx1 = fmaxf(mx1, __shfl_xor_sync(0xffffffffu, mx1, 2));
    float mn0 = fmaxf(m0, mx0), mn1 = fmaxf(m1, mx1);
    float al0 = __expf(m0 - mn0), al1 = __expf(m1 - mn1);
    m0 = mn0;
    m1 = mn1;
    float sum0 = 0.f, sum1 = 0.f;
#pragma unroll
    for (int t = 0; t < 8; t++) {
      sacc[t][0] = __expf(sacc[t][0] - m0);
      sacc[t][1] = __expf(sacc[t][1] - m0);
      sacc[t][2] = __expf(sacc[t][2] - m1);
      sacc[t][3] = __expf(sacc[t][3] - m1);
      sum0 += sacc[t][0] + sacc[t][1];
      sum1 += sacc[t][2] + sacc[t][3];
    }
    sum0 += __shfl_xor_sync(0xffffffffu, sum0, 1);
    sum0 += __shfl_xor_sync(0xffffffffu, sum0, 2);
    sum1 += __shfl_xor_sync(0xffffffffu, sum1, 1);
    sum1 += __shfl_xor_sync(0xffffffffu, sum1, 2);
    l0 = l0 * al0 + sum0;
    l1 = l1 * al1 + sum1;
#pragma unroll
    for (int t = 0; t < 16; t++) {
      o[t][0] *= al0;
      o[t][1] *= al0;
      o[t][2] *= al1;
      o[t][3] *= al1;
    }

    // O += P (Vh + Vl), P single fp16
#pragma unroll
    for (int j = 0; j < 4; j++) {
      uint32_t pha[4];
      pha[0] = h2bits(__floats2half2_rn(sacc[2 * j][0], sacc[2 * j][1]));
      pha[1] = h2bits(__floats2half2_rn(sacc[2 * j][2], sacc[2 * j][3]));
      pha[2] = h2bits(__floats2half2_rn(sacc[2 * j + 1][0], sacc[2 * j + 1][1]));
      pha[3] = h2bits(__floats2half2_rn(sacc[2 * j + 1][2], sacc[2 * j + 1][3]));
#pragma unroll
      for (int np = 0; np < 8; np++) {
        uint32_t va = sVh + ((j * 16 + vRow) * FA_STRIDE + np * 16 + vCol) * 2;
        uint32_t vh[4], vl[4];
        LDSM4T(vh, va);
        LDSM4T(vl, va + FA_MAT);
        MMAH16816(o[2 * np], pha, vh);
        MMAH16816(o[2 * np], pha, vl);
        MMAH16816(o[2 * np + 1], pha, vh + 2);
        MMAH16816(o[2 * np + 1], pha, vl + 2);
      }
    }
    __syncthreads();
  }

  // Epilogue: write context as fp16 hi/lo directly into out-proj A buffers
  float inv0 = 1.0f / l0, inv1 = 1.0f / l1;
  int r0 = qb * 64 + rloc;
#pragma unroll
  for (int t = 0; t < 16; t++) {
    int col = t * 8 + (lane & 3) * 2;
    {
      float v0 = o[t][0] * inv0, v1 = o[t][1] * inv0;
      __half h0 = __float2half_rn(v0), h1 = __float2half_rn(v1);
      __half2 hi; hi.x = h0; hi.y = h1;
      __half2 lo;
      lo.x = __float2half_rn(v0 - __half2float(h0));
      lo.y = __float2half_rn(v1 - __half2float(h1));
      size_t off = ((size_t)r0 * NQH + hq) * 128 + col;
      *(__half2*)(CtxHi + off) = hi;
      *(__half2*)(CtxLo + off) = lo;
    }
    {
      float v0 = o[t][2] * inv1, v1 = o[t][3] * inv1;
      __half h0 = __float2half_rn(v0), h1 = __float2half_rn(v1);
      __half2 hi; hi.x = h0; hi.y = h1;
      __half2 lo;
      lo.x = __float2half_rn(v0 - __half2float(h0));
      lo.y = __float2half_rn(v1 - __half2float(h1));
      size_t off = ((size_t)(r0 + 8) * NQH + hq) * 128 + col;
      *(__half2*)(CtxHi + off) = hi;
      *(__half2*)(CtxLo + off) = lo;
    }
  }
}

// ---------------------------------------------------------------------------
// Launch
// ---------------------------------------------------------------------------
extern "C" void kernel_launch(void* const* d_in, const int* in_sizes, int n_in,
                              void* d_out, int out_size) {
  const float* X = (const float*)d_in[0];
  const float* cosp = (const float*)d_in[1];
  const float* sinp = (const float*)d_in[2];
  const float* wq = (const float*)d_in[3];
  const float* wk = (const float*)d_in[4];
  const float* wv = (const float*)d_in[5];
  const float* wo = (const float*)d_in[6];
  float* out = (float*)d_out;

  float* QKV;
  __half *Ahi, *Alo, *Bh, *Qh, *Ql, *Kh, *Vh, *Vl;
  cudaGetSymbolAddress((void**)&QKV, g_QKV);
  cudaGetSymbolAddress((void**)&Ahi, g_Ahi);
  cudaGetSymbolAddress((void**)&Alo, g_Alo);
  cudaGetSymbolAddress((void**)&Bh, g_Bh);
  cudaGetSymbolAddress((void**)&Qh, g_Qh);
  cudaGetSymbolAddress((void**)&Ql, g_Ql);
  cudaGetSymbolAddress((void**)&Kh, g_Kh);
  cudaGetSymbolAddress((void**)&Vh, g_Vh);
  cudaGetSymbolAddress((void**)&Vl, g_Vl);

  cudaFuncSetAttribute(gemm_mma_h, cudaFuncAttributeMaxDynamicSharedMemorySize,
                       GEMM_SMEM);
  cudaFuncSetAttribute(flash_mma, cudaFuncAttributeMaxDynamicSharedMemorySize,
                       FA_SMEM);

  // Activations -> fp16 hi/lo
  split_convert_h<<<(S_LEN * KDIM / 4 + 255) / 256, 256>>>(X, Ahi, Alo,
                                                           S_LEN * KDIM);
  // Fused QKV weights -> [K,N] fp16 (coalesced, no transpose)
  convert_wqkv<<<(KDIM * NQKV / 4 + 255) / 256, 256>>>(wq, wk, wv, Bh);
  // Fused QKV projection (64x128 tiles, 4 CTAs/SM, ldmatrix.trans B)
  gemm_mma_h<<<dim3(48, 32), dim3(128), GEMM_SMEM>>>(Ahi, Alo, Bh, QKV, NQKV);
  // RoPE + fp16 split for attention
  int rtot = S_LEN * NQH * 64 + 2 * S_LEN * NKVH * 64;
  rope_split<<<(rtot + 255) / 256, 256>>>(QKV, cosp, sinp);
  // Attention (fp16 2-term HMMA); writes context hi/lo directly into Ahi/Alo
  flash_mma<<<dim3(32, 32), dim3(128), FA_SMEM>>>(Qh, Ql, Kh, Vh, Vl, Ahi, Alo);
  // Output projection
  convert_plain<<<(KDIM * H_DIM / 4 + 255) / 256, 256>>>(wo, Bh,
                                                         KDIM * H_DIM);
  gemm_mma_h<<<dim3(32, 32), dim3(128), GEMM_SMEM>>>(Ahi, Alo, Bh, out, 4096);
}

// round 16
// speedup vs baseline: 3.9471x; 1.3096x over previous
#include <cuda_runtime.h>
#include <cuda_fp16.h>
#include <math.h>
#include <stdint.h>

#define S_LEN 2048
#define H_DIM 4096
#define NQH 32
#define NKVH 8
#define HDIM 128
#define KDIM 4096
#define NQKV 6144

// ---------------------------------------------------------------------------
// Scratch (device globals; no allocation allowed)
// ---------------------------------------------------------------------------
__device__ float g_QKV[S_LEN * NQKV];

// fp16 GEMM operands: activations single fp16 [M,K]; weights natural [K,N]
__device__ __half g_Ah[S_LEN * KDIM];
__device__ __half g_Bh[KDIM * NQKV];

// attention operands (fp16; Q split, K single (scale folded), V split)
__device__ __half g_Qh[S_LEN * NQH * HDIM];
__device__ __half g_Ql[S_LEN * NQH * HDIM];
__device__ __half g_Kh[S_LEN * NKVH * HDIM];
__device__ __half g_Vh[S_LEN * NKVH * HDIM];
__device__ __half g_Vl[S_LEN * NKVH * HDIM];

// ---------------------------------------------------------------------------
// Helpers
// ---------------------------------------------------------------------------
__device__ __forceinline__ uint32_t smem_u32(const void* p) {
  uint32_t a;
  asm("{ .reg .u64 t; cvta.to.shared.u64 t, %1; cvt.u32.u64 %0, t; }"
      : "=r"(a) : "l"(p));
  return a;
}

__device__ __forceinline__ void cp16(uint32_t dst, const void* src) {
  asm volatile("cp.async.cg.shared.global [%0], [%1], 16;" ::"r"(dst), "l"(src));
}

#define LDSM4(R, ADDR)                                                         \
  asm volatile("ldmatrix.sync.aligned.m8n8.x4.shared.b16 {%0,%1,%2,%3}, [%4];" \
               : "=r"((R)[0]), "=r"((R)[1]), "=r"((R)[2]), "=r"((R)[3])        \
               : "r"(ADDR))

#define LDSM4T(R, ADDR)                                                        \
  asm volatile(                                                                \
      "ldmatrix.sync.aligned.m8n8.x4.trans.shared.b16 {%0,%1,%2,%3}, [%4];"    \
      : "=r"((R)[0]), "=r"((R)[1]), "=r"((R)[2]), "=r"((R)[3])                 \
      : "r"(ADDR))

// fp16 MMA
#define MMAH16816(D, A, B)                                                     \
  asm volatile(                                                                \
      "mma.sync.aligned.m16n8k16.row.col.f32.f16.f16.f32 "                     \
      "{%0,%1,%2,%3}, {%4,%5,%6,%7}, {%8,%9}, {%0,%1,%2,%3};"                  \
      : "+f"((D)[0]), "+f"((D)[1]), "+f"((D)[2]), "+f"((D)[3])                 \
      : "r"((A)[0]), "r"((A)[1]), "r"((A)[2]), "r"((A)[3]), "r"((B)[0]),       \
        "r"((B)[1]))

__device__ __forceinline__ uint32_t h2bits(__half2 v) {
  return *reinterpret_cast<uint32_t*>(&v);
}

// ---------------------------------------------------------------------------
// Plain fp32 -> fp16 convert (X, wo; coalesced)
// ---------------------------------------------------------------------------
__global__ void convert_plain(const float* __restrict__ W,
                              __half* __restrict__ B, int n) {
  int i = (blockIdx.x * 256 + threadIdx.x) * 4;
  if (i >= n) return;
  float4 v = *(const float4*)(W + i);
  __half2 a, b;
  a.x = __float2half_rn(v.x); a.y = __float2half_rn(v.y);
  b.x = __float2half_rn(v.z); b.y = __float2half_rn(v.w);
  *(__half2*)(B + i) = a;
  *(__half2*)(B + i + 2) = b;
}

// ---------------------------------------------------------------------------
// Fused QKV weight convert: wq[K,4096], wk[K,1024], wv[K,1024] (fp32)
//   -> g_Bh [K, 6144] fp16 (natural layout; GEMM uses ldmatrix.trans).
// ---------------------------------------------------------------------------
__global__ void convert_wqkv(const float* __restrict__ wq,
                             const float* __restrict__ wk,
                             const float* __restrict__ wv,
                             __half* __restrict__ B) {
  int i = (blockIdx.x * 256 + threadIdx.x) * 4;
  if (i >= KDIM * NQKV) return;
  int k = i / NQKV, n = i % NQKV;
  const float* src;
  if (n < 4096)
    src = wq + (size_t)k * 4096 + n;
  else if (n < 5120)
    src = wk + (size_t)k * 1024 + (n - 4096);
  else
    src = wv + (size_t)k * 1024 + (n - 5120);
  float4 v = *(const float4*)src;
  __half2 a, b;
  a.x = __float2half_rn(v.x); a.y = __float2half_rn(v.y);
  b.x = __float2half_rn(v.z); b.y = __float2half_rn(v.w);
  *(__half2*)(B + i) = a;
  *(__half2*)(B + i + 2) = b;
}

// ---------------------------------------------------------------------------
// fp16 single-term GEMM: C = A * W  (A [M,K] fp16, W natural [K,N] fp16).
// CTA tile 64x128, BK=32, 4 warps (2x2), warp tile 32x64.
// A via LDSM4 (k-major); B via LDSM4T from k-row-major tile.
// 3-stage cp.async, 4 CTAs/SM. Stage: A 64x80B + B 32x272B = 13824 B.
// ---------------------------------------------------------------------------
#define NCH (KDIM / 32)
#define B_OFF 5120            // A = 64 * 80
#define B_STRIDE 136          // halves; 272B rows (conflict-free)
#define STAGE_BYTES 13824
#define GEMM_SMEM (3 * STAGE_BYTES)  // 41472 -> 4 CTAs/SM

__global__ __launch_bounds__(128, 4) void gemm_mma_h(
    const __half* __restrict__ Ah_, const __half* __restrict__ Bh_,
    float* __restrict__ C, int N) {
  extern __shared__ char smc[];
  const int tid = threadIdx.x;
  const int lane = tid & 31, wid = tid >> 5;
  const int wm = wid & 1, wn = wid >> 1;  // 2x2 warp grid (32m x 64n)
  const int bm = blockIdx.y * 64, bn = blockIdx.x * 128;
  const size_t Kb = (size_t)KDIM * 2;
  const size_t Nb = (size_t)N * 2;

  uint32_t sbase = smem_u32(smc);

  const char* gpA = (const char*)Ah_ + (size_t)bm * Kb;
  const char* gpB = (const char*)Bh_ + (size_t)bn * 2;

  const int rA = tid >> 2;          // 0..31
  const int cA = (tid & 3) * 16;    // 16B chunk in 64B row
  const int rB = tid >> 4;          // 0..7
  const int cB = (tid & 15) * 16;   // 16B chunk in 256B row

  auto load_stage = [&](int stage, int k0) {
    uint32_t sb = sbase + stage * STAGE_BYTES;
    size_t gkA = (size_t)k0 * 2;
#pragma unroll
    for (int j = 0; j < 2; j++) {  // A rows rA, rA+32
      int rr = rA + j * 32;
      cp16(sb + rr * 80 + cA, gpA + (size_t)rr * Kb + gkA + cA);
    }
#pragma unroll
    for (int j = 0; j < 4; j++) {  // B k-rows rB, +8, +16, +24
      int rr = rB + j * 8;
      cp16(sb + B_OFF + rr * (B_STRIDE * 2) + cB,
           gpB + (size_t)(k0 + rr) * Nb + cB);
    }
    asm volatile("cp.async.commit_group;" ::: "memory");
  };

  float acc[2][8][4];
#pragma unroll
  for (int a = 0; a < 2; a++)
#pragma unroll
    for (int b = 0; b < 8; b++)
#pragma unroll
      for (int c = 0; c < 4; c++) acc[a][b][c] = 0.f;

  const int arow = wm * 32 + (lane & 15);
  const int aoff = (lane >> 4) * 8;
  const int bRowT = (lane & 7) + ((lane >> 3) & 1) * 8;
  const int bColT = (lane >> 4) * 8;

  load_stage(0, 0);
  load_stage(1, 32);

  for (int i = 0; i < NCH; ++i) {
    if (i + 2 < NCH)
      asm volatile("cp.async.wait_group 1;" ::: "memory");
    else
      asm volatile("cp.async.wait_group 0;" ::: "memory");
    __syncthreads();
    if (i + 2 < NCH) load_stage((i + 2) % 3, (i + 2) * 32);

    uint32_t sb = sbase + (i % 3) * STAGE_BYTES;
    uint32_t sA = sb;
    uint32_t sB = sb + B_OFF;

#pragma unroll
    for (int ks = 0; ks < 32; ks += 16) {
      uint32_t Bf[8][2];
#pragma unroll
      for (int ni = 0; ni < 4; ni++) {
        uint32_t bd =
            sB + ((ks + bRowT) * B_STRIDE + wn * 64 + ni * 16 + bColT) * 2;
        uint32_t t[4];
        LDSM4T(t, bd);
        Bf[ni * 2][0] = t[0]; Bf[ni * 2][1] = t[1];
        Bf[ni * 2 + 1][0] = t[2]; Bf[ni * 2 + 1][1] = t[3];
      }
#pragma unroll
      for (int mi = 0; mi < 2; mi++) {
        uint32_t ad = sA + ((arow + mi * 16) * 40 + ks + aoff) * 2;
        uint32_t Af[4];
        LDSM4(Af, ad);
#pragma unroll
        for (int nj = 0; nj < 8; nj++) {
          MMAH16816(acc[mi][nj], Af, Bf[nj]);
        }
      }
    }
    __syncthreads();
  }

  const int tg = lane >> 2, tc = (lane & 3) * 2;
#pragma unroll
  for (int mi = 0; mi < 2; mi++) {
    int row = bm + wm * 32 + mi * 16 + tg;
#pragma unroll
    for (int nj = 0; nj < 8; nj++) {
      int col = bn + wn * 64 + nj * 8 + tc;
      float* p = C + (size_t)row * N + col;
      p[0] = acc[mi][nj][0];
      p[1] = acc[mi][nj][1];
      float* p2 = p + 8 * (size_t)N;
      p2[0] = acc[mi][nj][2];
      p2[1] = acc[mi][nj][3];
    }
  }
}

// ---------------------------------------------------------------------------
// RoPE + fp16 split for attention. Q split hi/lo (unscaled), K single fp16
// with softmax scale folded in, V split hi/lo.
// ---------------------------------------------------------------------------
#define FA_SCALE 0.08838834764831845f

__global__ void rope_split(const float* __restrict__ QKV,
                           const float* __restrict__ cosp,
                           const float* __restrict__ sinp) {
  int idx = blockIdx.x * blockDim.x + threadIdx.x;
  const int nq = S_LEN * NQH * 64;
  const int nk = S_LEN * NKVH * 64;
  if (idx < nq) {
    int d = idx & 63;
    int h = (idx >> 6) & 31;
    int s = idx >> 11;
    const float* src = QKV + (size_t)s * NQKV + h * 128;
    float c1 = cosp[s * 128 + d], s1 = sinp[s * 128 + d];
    float c2 = cosp[s * 128 + d + 64], s2 = sinp[s * 128 + d + 64];
    float x1 = src[d], x2 = src[d + 64];
    float y1 = x1 * c1 - x2 * s1;
    float y2 = x2 * c2 + x1 * s2;
    size_t o = ((size_t)s * NQH + h) * 128 + d;
    __half h1 = __float2half_rn(y1);
    __half h2 = __float2half_rn(y2);
    g_Qh[o] = h1;
    g_Ql[o] = __float2half_rn(y1 - __half2float(h1));
    g_Qh[o + 64] = h2;
    g_Ql[o + 64] = __float2half_rn(y2 - __half2float(h2));
  } else if (idx < nq + nk) {
    int t = idx - nq;
    int d = t & 63;
    int h = (t >> 6) & 7;
    int s = t >> 9;
    const float* src = QKV + (size_t)s * NQKV + 4096 + h * 128;
    float c1 = cosp[s * 128 + d], s1 = sinp[s * 128 + d];
    float c2 = cosp[s * 128 + d + 64], s2 = sinp[s * 128 + d + 64];
    float x1 = src[d], x2 = src[d + 64];
    float y1 = (x1 * c1 - x2 * s1) * FA_SCALE;
    float y2 = (x2 * c2 + x1 * s2) * FA_SCALE;
    size_t o = ((size_t)s * NKVH + h) * 128 + d;
    g_Kh[o] = __float2half_rn(y1);
    g_Kh[o + 64] = __float2half_rn(y2);
  } else if (idx < nq + 2 * nk) {
    int t = idx - nq - nk;
    int d = t & 63;
    int h = (t >> 6) & 7;
    int s = t >> 9;
    const float* src = QKV + (size_t)s * NQKV + 5120 + h * 128;
    float x1 = src[d], x2 = src[d + 64];
    size_t o = ((size_t)s * NKVH + h) * 128 + d;
    __half h1 = __float2half_rn(x1);
    __half h2 = __float2half_rn(x2);
    g_Vh[o] = h1;
    g_Vl[o] = __float2half_rn(x1 - __half2float(h1));
    g_Vh[o + 64] = h2;
    g_Vl[o + 64] = __float2half_rn(x2 - __half2float(h2));
  }
}

// ---------------------------------------------------------------------------
// fp16 flash attention, causal, GQA. Tile 64x64, HD=128, 4 warps.
// 2-term: S = (Qh+Ql)K, O += P(Vh+Vl). SMEM 5 mats = 87040 B -> 2 CTAs/SM.
// Epilogue writes context as single fp16 into the out-proj A buffer.
// ---------------------------------------------------------------------------
#define FA_STRIDE 136
#define FA_MAT 17408
#define FA_SMEM (5 * FA_MAT)  // 87040

__global__ __launch_bounds__(128) void flash_mma(
    const __half* __restrict__ Qh_, const __half* __restrict__ Ql_,
    const __half* __restrict__ Kh_, const __half* __restrict__ Vh_,
    const __half* __restrict__ Vl_, __half* __restrict__ CtxHi) {
  extern __shared__ char smf[];
  const uint32_t sb = smem_u32(smf);
  const uint32_t sQh = sb;                   // Qh, Ql
  const uint32_t sKh = sb + 2 * FA_MAT;      // K single
  const uint32_t sVh = sb + 3 * FA_MAT;      // Vh, Vl

  const int tid = threadIdx.x;
  const int lane = tid & 31, w = tid >> 5;
  const int qb = (int)gridDim.x - 1 - (int)blockIdx.x;
  const int hq = blockIdx.y, hkv = hq >> 2;

#pragma unroll
  for (int j = 0; j < 8; j++) {
    int idx = tid + j * 128;
    int r = idx >> 4;
    int c = (idx & 15) * 16;
    size_t g = ((size_t)(qb * 64 + r) * NQH + hq) * 256 + c;
    uint32_t d = r * (FA_STRIDE * 2) + c;
    cp16(sQh + d, (const char*)Qh_ + g);
    cp16(sQh + FA_MAT + d, (const char*)Ql_ + g);
  }
  asm volatile("cp.async.commit_group;" ::: "memory");

  float o[16][4];
#pragma unroll
  for (int t = 0; t < 16; t++)
#pragma unroll
    for (int c = 0; c < 4; c++) o[t][c] = 0.f;
  float m0 = -1e30f, m1 = -1e30f, l0 = 0.f, l1 = 0.f;

  const int arow = w * 16 + (lane & 15);
  const int aoff = (lane >> 4) * 8;
  const int bRow = (lane >> 4) * 8 + (lane & 7);
  const int bCol = ((lane >> 3) & 1) * 8;
  const int vRow = (lane & 7) + ((lane >> 3) & 1) * 8;
  const int vCol = (lane >> 4) * 8;
  const int rloc = w * 16 + (lane >> 2);

  for (int kb = 0; kb <= qb; ++kb) {
#pragma unroll
    for (int j = 0; j < 8; j++) {
      int idx = tid + j * 128;
      int r = idx >> 4;
      int c = (idx & 15) * 16;
      size_t g = ((size_t)(kb * 64 + r) * NKVH + hkv) * 256 + c;
      uint32_t d = r * (FA_STRIDE * 2) + c;
      cp16(sKh + d, (const char*)Kh_ + g);
      cp16(sVh + d, (const char*)Vh_ + g);
      cp16(sVh + FA_MAT + d, (const char*)Vl_ + g);
    }
    asm volatile("cp.async.commit_group;" ::: "memory");
    asm volatile("cp.async.wait_group 0;" ::: "memory");
    __syncthreads();

    float sacc[8][4];
#pragma unroll
    for (int t = 0; t < 8; t++)
#pragma unroll
      for (int c = 0; c < 4; c++) sacc[t][c] = 0.f;

#pragma unroll
    for (int kk = 0; kk < 8; ++kk) {
      uint32_t qh[4], ql[4];
      uint32_t qa = sQh + (arow * FA_STRIDE + kk * 16 + aoff) * 2;
      LDSM4(qh, qa);
      LDSM4(ql, qa + FA_MAT);
#pragma unroll
      for (int np = 0; np < 4; np++) {
        uint32_t ka = sKh + ((np * 16 + bRow) * FA_STRIDE + kk * 16 + bCol) * 2;
        uint32_t kh[4];
        LDSM4(kh, ka);
        MMAH16816(sacc[2 * np], qh, kh);
        MMAH16816(sacc[2 * np], ql, kh);
        MMAH16816(sacc[2 * np + 1], qh, kh + 2);
        MMAH16816(sacc[2 * np + 1], ql, kh + 2);
      }
    }

    if (kb == qb) {
#pragma unroll
      for (int t = 0; t < 8; t++) {
        int n = t * 8 + (lane & 3) * 2;
        if (n > rloc) sacc[t][0] = -1e30f;
        if (n + 1 > rloc) sacc[t][1] = -1e30f;
        if (n > rloc + 8) sacc[t][2] = -1e30f;
        if (n + 1 > rloc + 8) sacc[t][3] = -1e30f;
      }
    }

    float mx0 = -1e30f, mx1 = -1e30f;
#pragma unroll
    for (int t = 0; t < 8; t++) {
      mx0 = fmaxf(mx0, fmaxf(sacc[t][0], sacc[t][1]));
      mx1 = fmaxf(mx1, fmaxf(sacc[t][2], sacc[t][3]));
    }
    mx0 = fmaxf(mx0, __shfl_xor_sync(0xffffffffu, mx0, 1));
    mx0 = fmaxf(mx0, __shfl_xor_sync(0xffffffffu, mx0, 2));
    mx1 = fmaxf(mx1, __shfl_xor_sync(0xffffffffu, mx1, 1));
    mx1 = fmaxf(mx1, __shfl_xor_sync(0xffffffffu, mx1, 2));
    float mn0 = fmaxf(m0, mx0), mn1 = fmaxf(m1, mx1);
    float al0 = __expf(m0 - mn0), al1 = __expf(m1 - mn1);
    m0 = mn0;
    m1 = mn1;
    float sum0 = 0.f, sum1 = 0.f;
#pragma unroll
    for (int t = 0; t < 8; t++) {
      sacc[t][0] = __expf(sacc[t][0] - m0);
      sacc[t][1] = __expf(sacc[t][1] - m0);
      sacc[t][2] = __expf(sacc[t][2] - m1);
      sacc[t][3] = __expf(sacc[t][3] - m1);
      sum0 += sacc[t][0] + sacc[t][1];
      sum1 += sacc[t][2] + sacc[t][3];
    }
    sum0 += __shfl_xor_sync(0xffffffffu, sum0, 1);
    sum0 += __shfl_xor_sync(0xffffffffu, sum0, 2);
    sum1 += __shfl_xor_sync(0xffffffffu, sum1, 1);
    sum1 += __shfl_xor_sync(0xffffffffu, sum1, 2);
    l0 = l0 * al0 + sum0;
    l1 = l1 * al1 + sum1;
#pragma unroll
    for (int t = 0; t < 16; t++) {
      o[t][0] *= al0;
      o[t][1] *= al0;
      o[t][2] *= al1;
      o[t][3] *= al1;
    }

    // O += P (Vh + Vl), P single fp16
#pragma unroll
    for (int j = 0; j < 4; j++) {
      uint32_t pha[4];
      pha[0] = h2bits(__floats2half2_rn(sacc[2 * j][0], sacc[2 * j][1]));
      pha[1] = h2bits(__floats2half2_rn(sacc[2 * j][2], sacc[2 * j][3]));
      pha[2] = h2bits(__floats2half2_rn(sacc[2 * j + 1][0], sacc[2 * j + 1][1]));
      pha[3] = h2bits(__floats2half2_rn(sacc[2 * j + 1][2], sacc[2 * j + 1][3]));
#pragma unroll
      for (int np = 0; np < 8; np++) {
        uint32_t va = sVh + ((j * 16 + vRow) * FA_STRIDE + np * 16 + vCol) * 2;
        uint32_t vh[4], vl[4];
        LDSM4T(vh, va);
        LDSM4T(vl, va + FA_MAT);
        MMAH16816(o[2 * np], pha, vh);
        MMAH16816(o[2 * np], pha, vl);
        MMAH16816(o[2 * np + 1], pha, vh + 2);
        MMAH16816(o[2 * np + 1], pha, vl + 2);
      }
    }
    __syncthreads();
  }

  // Epilogue: write context as single fp16 into out-proj A buffer
  float inv0 = 1.0f / l0, inv1 = 1.0f / l1;
  int r0 = qb * 64 + rloc;
#pragma unroll
  for (int t = 0; t < 16; t++) {
    int col = t * 8 + (lane & 3) * 2;
    {
      __half2 hi = __floats2half2_rn(o[t][0] * inv0, o[t][1] * inv0);
      *(__half2*)(CtxHi + ((size_t)r0 * NQH + hq) * 128 + col) = hi;
    }
    {
      __half2 hi = __floats2half2_rn(o[t][2] * inv1, o[t][3] * inv1);
      *(__half2*)(CtxHi + ((size_t)(r0 + 8) * NQH + hq) * 128 + col) = hi;
    }
  }
}

// ---------------------------------------------------------------------------
// Launch
// ---------------------------------------------------------------------------
extern "C" void kernel_launch(void* const* d_in, const int* in_sizes, int n_in,
                              void* d_out, int out_size) {
  const float* X = (const float*)d_in[0];
  const float* cosp = (const float*)d_in[1];
  const float* sinp = (const float*)d_in[2];
  const float* wq = (const float*)d_in[3];
  const float* wk = (const float*)d_in[4];
  const float* wv = (const float*)d_in[5];
  const float* wo = (const float*)d_in[6];
  float* out = (float*)d_out;

  float* QKV;
  __half *Ah, *Bh, *Qh, *Ql, *Kh, *Vh, *Vl;
  cudaGetSymbolAddress((void**)&QKV, g_QKV);
  cudaGetSymbolAddress((void**)&Ah, g_Ah);
  cudaGetSymbolAddress((void**)&Bh, g_Bh);
  cudaGetSymbolAddress((void**)&Qh, g_Qh);
  cudaGetSymbolAddress((void**)&Ql, g_Ql);
  cudaGetSymbolAddress((void**)&Kh, g_Kh);
  cudaGetSymbolAddress((void**)&Vh, g_Vh);
  cudaGetSymbolAddress((void**)&Vl, g_Vl);

  cudaFuncSetAttribute(gemm_mma_h, cudaFuncAttributeMaxDynamicSharedMemorySize,
                       GEMM_SMEM);
  cudaFuncSetAttribute(flash_mma, cudaFuncAttributeMaxDynamicSharedMemorySize,
                       FA_SMEM);

  // Activations -> fp16 (single)
  convert_plain<<<(S_LEN * KDIM / 4 + 255) / 256, 256>>>(X, Ah, S_LEN * KDIM);
  // Fused QKV weights -> [K,N] fp16 (coalesced, no transpose)
  convert_wqkv<<<(KDIM * NQKV / 4 + 255) / 256, 256>>>(wq, wk, wv, Bh);
  // Fused QKV projection (64x128 tiles, 4 CTAs/SM, single-term)
  gemm_mma_h<<<dim3(48, 32), dim3(128), GEMM_SMEM>>>(Ah, Bh, QKV, NQKV);
  // RoPE + fp16 split for attention
  int rtot = S_LEN * NQH * 64 + 2 * S_LEN * NKVH * 64;
  rope_split<<<(rtot + 255) / 256, 256>>>(QKV, cosp, sinp);
  // Attention (fp16 2-term HMMA); writes context fp16 directly into Ah
  flash_mma<<<dim3(32, 32), dim3(128), FA_SMEM>>>(Qh, Ql, Kh, Vh, Vl, Ah);
  // Output projection
  convert_plain<<<(KDIM * H_DIM / 4 + 255) / 256, 256>>>(wo, Bh, KDIM * H_DIM);
  gemm_mma_h<<<dim3(32, 32), dim3(128), GEMM_SMEM>>>(Ah, Bh, out, 4096);
}

// round 17
// speedup vs baseline: 4.2597x; 1.0792x over previous
#include <cuda_runtime.h>
#include <cuda_fp16.h>
#include <math.h>
#include <stdint.h>

#define S_LEN 2048
#define H_DIM 4096
#define NQH 32
#define NKVH 8
#define HDIM 128
#define KDIM 4096
#define NQKV 6144

// ---------------------------------------------------------------------------
// Scratch (device globals; no allocation allowed)
// ---------------------------------------------------------------------------
__device__ float g_QKV[S_LEN * NQKV];

// fp16 GEMM operands: activations single fp16 [M,K]; weights natural [K,N]
__device__ __half g_Ah[S_LEN * KDIM];
__device__ __half g_Bh[KDIM * NQKV];

// attention operands (fp16; Q split, K single (scale folded), V single)
__device__ __half g_Qh[S_LEN * NQH * HDIM];
__device__ __half g_Ql[S_LEN * NQH * HDIM];
__device__ __half g_Kh[S_LEN * NKVH * HDIM];
__device__ __half g_Vh[S_LEN * NKVH * HDIM];

// ---------------------------------------------------------------------------
// Helpers
// ---------------------------------------------------------------------------
__device__ __forceinline__ uint32_t smem_u32(const void* p) {
  uint32_t a;
  asm("{ .reg .u64 t; cvta.to.shared.u64 t, %1; cvt.u32.u64 %0, t; }"
      : "=r"(a) : "l"(p));
  return a;
}

__device__ __forceinline__ void cp16(uint32_t dst, const void* src) {
  asm volatile("cp.async.cg.shared.global [%0], [%1], 16;" ::"r"(dst), "l"(src));
}

#define LDSM4(R, ADDR)                                                         \
  asm volatile("ldmatrix.sync.aligned.m8n8.x4.shared.b16 {%0,%1,%2,%3}, [%4];" \
               : "=r"((R)[0]), "=r"((R)[1]), "=r"((R)[2]), "=r"((R)[3])        \
               : "r"(ADDR))

#define LDSM4T(R, ADDR)                                                        \
  asm volatile(                                                                \
      "ldmatrix.sync.aligned.m8n8.x4.trans.shared.b16 {%0,%1,%2,%3}, [%4];"    \
      : "=r"((R)[0]), "=r"((R)[1]), "=r"((R)[2]), "=r"((R)[3])                 \
      : "r"(ADDR))

// fp16 MMA
#define MMAH16816(D, A, B)                                                     \
  asm volatile(                                                                \
      "mma.sync.aligned.m16n8k16.row.col.f32.f16.f16.f32 "                     \
      "{%0,%1,%2,%3}, {%4,%5,%6,%7}, {%8,%9}, {%0,%1,%2,%3};"                  \
      : "+f"((D)[0]), "+f"((D)[1]), "+f"((D)[2]), "+f"((D)[3])                 \
      : "r"((A)[0]), "r"((A)[1]), "r"((A)[2]), "r"((A)[3]), "r"((B)[0]),       \
        "r"((B)[1]))

__device__ __forceinline__ uint32_t h2bits(__half2 v) {
  return *reinterpret_cast<uint32_t*>(&v);
}

// ---------------------------------------------------------------------------
// Plain fp32 -> fp16 convert (X, wo; coalesced)
// ---------------------------------------------------------------------------
__global__ void convert_plain(const float* __restrict__ W,
                              __half* __restrict__ B, int n) {
  int i = (blockIdx.x * 256 + threadIdx.x) * 4;
  if (i >= n) return;
  float4 v = *(const float4*)(W + i);
  __half2 a, b;
  a.x = __float2half_rn(v.x); a.y = __float2half_rn(v.y);
  b.x = __float2half_rn(v.z); b.y = __float2half_rn(v.w);
  *(__half2*)(B + i) = a;
  *(__half2*)(B + i + 2) = b;
}

// ---------------------------------------------------------------------------
// Fused QKV weight convert: wq[K,4096], wk[K,1024], wv[K,1024] (fp32)
//   -> g_Bh [K, 6144] fp16 (natural layout; GEMM uses ldmatrix.trans).
// ---------------------------------------------------------------------------
__global__ void convert_wqkv(const float* __restrict__ wq,
                             const float* __restrict__ wk,
                             const float* __restrict__ wv,
                             __half* __restrict__ B) {
  int i = (blockIdx.x * 256 + threadIdx.x) * 4;
  if (i >= KDIM * NQKV) return;
  int k = i / NQKV, n = i % NQKV;
  const float* src;
  if (n < 4096)
    src = wq + (size_t)k * 4096 + n;
  else if (n < 5120)
    src = wk + (size_t)k * 1024 + (n - 4096);
  else
    src = wv + (size_t)k * 1024 + (n - 5120);
  float4 v = *(const float4*)src;
  __half2 a, b;
  a.x = __float2half_rn(v.x); a.y = __float2half_rn(v.y);
  b.x = __float2half_rn(v.z); b.y = __float2half_rn(v.w);
  *(__half2*)(B + i) = a;
  *(__half2*)(B + i + 2) = b;
}

// ---------------------------------------------------------------------------
// fp16 single-term GEMM: C = A * W  (A [M,K] fp16, W natural [K,N] fp16).
// CTA tile 64x128, BK=32, 4 warps (2x2), warp tile 32x64.
// 3-stage cp.async, 4 CTAs/SM. (unchanged from passing round)
// ---------------------------------------------------------------------------
#define NCH (KDIM / 32)
#define B_OFF 5120            // A = 64 * 80
#define B_STRIDE 136          // halves; 272B rows (conflict-free)
#define STAGE_BYTES 13824
#define GEMM_SMEM (3 * STAGE_BYTES)  // 41472 -> 4 CTAs/SM

__global__ __launch_bounds__(128, 4) void gemm_mma_h(
    const __half* __restrict__ Ah_, const __half* __restrict__ Bh_,
    float* __restrict__ C, int N) {
  extern __shared__ char smc[];
  const int tid = threadIdx.x;
  const int lane = tid & 31, wid = tid >> 5;
  const int wm = wid & 1, wn = wid >> 1;
  const int bm = blockIdx.y * 64, bn = blockIdx.x * 128;
  const size_t Kb = (size_t)KDIM * 2;
  const size_t Nb = (size_t)N * 2;

  uint32_t sbase = smem_u32(smc);

  const char* gpA = (const char*)Ah_ + (size_t)bm * Kb;
  const char* gpB = (const char*)Bh_ + (size_t)bn * 2;

  const int rA = tid >> 2;
  const int cA = (tid & 3) * 16;
  const int rB = tid >> 4;
  const int cB = (tid & 15) * 16;

  auto load_stage = [&](int stage, int k0) {
    uint32_t sb = sbase + stage * STAGE_BYTES;
    size_t gkA = (size_t)k0 * 2;
#pragma unroll
    for (int j = 0; j < 2; j++) {
      int rr = rA + j * 32;
      cp16(sb + rr * 80 + cA, gpA + (size_t)rr * Kb + gkA + cA);
    }
#pragma unroll
    for (int j = 0; j < 4; j++) {
      int rr = rB + j * 8;
      cp16(sb + B_OFF + rr * (B_STRIDE * 2) + cB,
           gpB + (size_t)(k0 + rr) * Nb + cB);
    }
    asm volatile("cp.async.commit_group;" ::: "memory");
  };

  float acc[2][8][4];
#pragma unroll
  for (int a = 0; a < 2; a++)
#pragma unroll
    for (int b = 0; b < 8; b++)
#pragma unroll
      for (int c = 0; c < 4; c++) acc[a][b][c] = 0.f;

  const int arow = wm * 32 + (lane & 15);
  const int aoff = (lane >> 4) * 8;
  const int bRowT = (lane & 7) + ((lane >> 3) & 1) * 8;
  const int bColT = (lane >> 4) * 8;

  load_stage(0, 0);
  load_stage(1, 32);

  for (int i = 0; i < NCH; ++i) {
    if (i + 2 < NCH)
      asm volatile("cp.async.wait_group 1;" ::: "memory");
    else
      asm volatile("cp.async.wait_group 0;" ::: "memory");
    __syncthreads();
    if (i + 2 < NCH) load_stage((i + 2) % 3, (i + 2) * 32);

    uint32_t sb = sbase + (i % 3) * STAGE_BYTES;
    uint32_t sA = sb;
    uint32_t sB = sb + B_OFF;

#pragma unroll
    for (int ks = 0; ks < 32; ks += 16) {
      uint32_t Bf[8][2];
#pragma unroll
      for (int ni = 0; ni < 4; ni++) {
        uint32_t bd =
            sB + ((ks + bRowT) * B_STRIDE + wn * 64 + ni * 16 + bColT) * 2;
        uint32_t t[4];
        LDSM4T(t, bd);
        Bf[ni * 2][0] = t[0]; Bf[ni * 2][1] = t[1];
        Bf[ni * 2 + 1][0] = t[2]; Bf[ni * 2 + 1][1] = t[3];
      }
#pragma unroll
      for (int mi = 0; mi < 2; mi++) {
        uint32_t ad = sA + ((arow + mi * 16) * 40 + ks + aoff) * 2;
        uint32_t Af[4];
        LDSM4(Af, ad);
#pragma unroll
        for (int nj = 0; nj < 8; nj++) {
          MMAH16816(acc[mi][nj], Af, Bf[nj]);
        }
      }
    }
    __syncthreads();
  }

  const int tg = lane >> 2, tc = (lane & 3) * 2;
#pragma unroll
  for (int mi = 0; mi < 2; mi++) {
    int row = bm + wm * 32 + mi * 16 + tg;
#pragma unroll
    for (int nj = 0; nj < 8; nj++) {
      int col = bn + wn * 64 + nj * 8 + tc;
      float* p = C + (size_t)row * N + col;
      p[0] = acc[mi][nj][0];
      p[1] = acc[mi][nj][1];
      float* p2 = p + 8 * (size_t)N;
      p2[0] = acc[mi][nj][2];
      p2[1] = acc[mi][nj][3];
    }
  }
}

// ---------------------------------------------------------------------------
// RoPE + fp16 for attention. Q split hi/lo (unscaled), K single fp16 with
// softmax scale folded in, V single fp16.
// ---------------------------------------------------------------------------
#define FA_SCALE 0.08838834764831845f

__global__ void rope_split(const float* __restrict__ QKV,
                           const float* __restrict__ cosp,
                           const float* __restrict__ sinp) {
  int idx = blockIdx.x * blockDim.x + threadIdx.x;
  const int nq = S_LEN * NQH * 64;
  const int nk = S_LEN * NKVH * 64;
  if (idx < nq) {
    int d = idx & 63;
    int h = (idx >> 6) & 31;
    int s = idx >> 11;
    const float* src = QKV + (size_t)s * NQKV + h * 128;
    float c1 = cosp[s * 128 + d], s1 = sinp[s * 128 + d];
    float c2 = cosp[s * 128 + d + 64], s2 = sinp[s * 128 + d + 64];
    float x1 = src[d], x2 = src[d + 64];
    float y1 = x1 * c1 - x2 * s1;
    float y2 = x2 * c2 + x1 * s2;
    size_t o = ((size_t)s * NQH + h) * 128 + d;
    __half h1 = __float2half_rn(y1);
    __half h2 = __float2half_rn(y2);
    g_Qh[o] = h1;
    g_Ql[o] = __float2half_rn(y1 - __half2float(h1));
    g_Qh[o + 64] = h2;
    g_Ql[o + 64] = __float2half_rn(y2 - __half2float(h2));
  } else if (idx < nq + nk) {
    int t = idx - nq;
    int d = t & 63;
    int h = (t >> 6) & 7;
    int s = t >> 9;
    const float* src = QKV + (size_t)s * NQKV + 4096 + h * 128;
    float c1 = cosp[s * 128 + d], s1 = sinp[s * 128 + d];
    float c2 = cosp[s * 128 + d + 64], s2 = sinp[s * 128 + d + 64];
    float x1 = src[d], x2 = src[d + 64];
    float y1 = (x1 * c1 - x2 * s1) * FA_SCALE;
    float y2 = (x2 * c2 + x1 * s2) * FA_SCALE;
    size_t o = ((size_t)s * NKVH + h) * 128 + d;
    g_Kh[o] = __float2half_rn(y1);
    g_Kh[o + 64] = __float2half_rn(y2);
  } else if (idx < nq + 2 * nk) {
    int t = idx - nq - nk;
    int d = t & 63;
    int h = (t >> 6) & 7;
    int s = t >> 9;
    const float* src = QKV + (size_t)s * NQKV + 5120 + h * 128;
    size_t o = ((size_t)s * NKVH + h) * 128 + d;
    g_Vh[o] = __float2half_rn(src[d]);
    g_Vh[o + 64] = __float2half_rn(src[d + 64]);
  }
}

// ---------------------------------------------------------------------------
// fp16 flash attention, causal, GQA. Tile 64x64, HD=128, 4 warps.
// S = (Qh+Ql)K, O += P*V (single V). KV double-buffered:
// SMEM = Qh,Ql + 2 x (K, V) = 6 mats = 104448 B -> 2 CTAs/SM.
// Epilogue writes context as single fp16 into the out-proj A buffer.
// ---------------------------------------------------------------------------
#define FA_STRIDE 136
#define FA_MAT 17408
#define FA_SMEM (6 * FA_MAT)  // 104448

__global__ __launch_bounds__(128) void flash_mma(
    const __half* __restrict__ Qh_, const __half* __restrict__ Ql_,
    const __half* __restrict__ Kh_, const __half* __restrict__ Vh_,
    __half* __restrict__ CtxHi) {
  extern __shared__ char smf[];
  const uint32_t sb = smem_u32(smf);
  const uint32_t sQh = sb;  // Qh, Ql; then KV bufs at (2 + 2*b)*FA_MAT

  const int tid = threadIdx.x;
  const int lane = tid & 31, w = tid >> 5;
  const int qb = (int)gridDim.x - 1 - (int)blockIdx.x;
  const int hq = blockIdx.y, hkv = hq >> 2;

  auto load_kv = [&](int kb, int buf) {
    uint32_t sK = sb + (2 + 2 * buf) * FA_MAT;
    uint32_t sV = sK + FA_MAT;
#pragma unroll
    for (int j = 0; j < 8; j++) {
      int idx = tid + j * 128;
      int r = idx >> 4;
      int c = (idx & 15) * 16;
      size_t g = ((size_t)(kb * 64 + r) * NKVH + hkv) * 256 + c;
      uint32_t d = r * (FA_STRIDE * 2) + c;
      cp16(sK + d, (const char*)Kh_ + g);
      cp16(sV + d, (const char*)Vh_ + g);
    }
    asm volatile("cp.async.commit_group;" ::: "memory");
  };

  // Q tile (hi+lo), then KV(0) -> buf 0
#pragma unroll
  for (int j = 0; j < 8; j++) {
    int idx = tid + j * 128;
    int r = idx >> 4;
    int c = (idx & 15) * 16;
    size_t g = ((size_t)(qb * 64 + r) * NQH + hq) * 256 + c;
    uint32_t d = r * (FA_STRIDE * 2) + c;
    cp16(sQh + d, (const char*)Qh_ + g);
    cp16(sQh + FA_MAT + d, (const char*)Ql_ + g);
  }
  asm volatile("cp.async.commit_group;" ::: "memory");
  load_kv(0, 0);

  float o[16][4];
#pragma unroll
  for (int t = 0; t < 16; t++)
#pragma unroll
    for (int c = 0; c < 4; c++) o[t][c] = 0.f;
  float m0 = -1e30f, m1 = -1e30f, l0 = 0.f, l1 = 0.f;

  const int arow = w * 16 + (lane & 15);
  const int aoff = (lane >> 4) * 8;
  const int bRow = (lane >> 4) * 8 + (lane & 7);
  const int bCol = ((lane >> 3) & 1) * 8;
  const int vRow = (lane & 7) + ((lane >> 3) & 1) * 8;
  const int vCol = (lane >> 4) * 8;
  const int rloc = w * 16 + (lane >> 2);

  for (int kb = 0; kb <= qb; ++kb) {
    const int buf = kb & 1;
    const uint32_t sKh = sb + (2 + 2 * buf) * FA_MAT;
    const uint32_t sVh = sKh + FA_MAT;

    if (kb + 1 <= qb) {
      load_kv(kb + 1, buf ^ 1);
      asm volatile("cp.async.wait_group 1;" ::: "memory");
    } else {
      asm volatile("cp.async.wait_group 0;" ::: "memory");
    }
    __syncthreads();

    float sacc[8][4];
#pragma unroll
    for (int t = 0; t < 8; t++)
#pragma unroll
      for (int c = 0; c < 4; c++) sacc[t][c] = 0.f;

#pragma unroll
    for (int kk = 0; kk < 8; ++kk) {
      uint32_t qh[4], ql[4];
      uint32_t qa = sQh + (arow * FA_STRIDE + kk * 16 + aoff) * 2;
      LDSM4(qh, qa);
      LDSM4(ql, qa + FA_MAT);
#pragma unroll
      for (int np = 0; np < 4; np++) {
        uint32_t ka = sKh + ((np * 16 + bRow) * FA_STRIDE + kk * 16 + bCol) * 2;
        uint32_t kh[4];
        LDSM4(kh, ka);
        MMAH16816(sacc[2 * np], qh, kh);
        MMAH16816(sacc[2 * np], ql, kh);
        MMAH16816(sacc[2 * np + 1], qh, kh + 2);
        MMAH16816(sacc[2 * np + 1], ql, kh + 2);
      }
    }

    if (kb == qb) {
#pragma unroll
      for (int t = 0; t < 8; t++) {
        int n = t * 8 + (lane & 3) * 2;
        if (n > rloc) sacc[t][0] = -1e30f;
        if (n + 1 > rloc) sacc[t][1] = -1e30f;
        if (n > rloc + 8) sacc[t][2] = -1e30f;
        if (n + 1 > rloc + 8) sacc[t][3] = -1e30f;
      }
    }

    float mx0 = -1e30f, mx1 = -1e30f;
#pragma unroll
    for (int t = 0; t < 8; t++) {
      mx0 = fmaxf(mx0, fmaxf(sacc[t][0], sacc[t][1]));
      mx1 = fmaxf(mx1, fmaxf(sacc[t][2], sacc[t][3]));
    }
    mx0 = fmaxf(mx0, __shfl_xor_sync(0xffffffffu, mx0, 1));
    mx0 = fmaxf(mx0, __shfl_xor_sync(0xffffffffu, mx0, 2));
    mx1 = fmaxf(mx1, __shfl_xor_sync(0xffffffffu, mx1, 1));
    mx1 = fmaxf(mx1, __shfl_xor_sync(0xffffffffu, mx1, 2));
    float mn0 = fmaxf(m0, mx0), mn1 = fmaxf(m1, mx1);
    float al0 = __expf(m0 - mn0), al1 = __expf(m1 - mn1);
    m0 = mn0;
    m1 = mn1;
    float sum0 = 0.f, sum1 = 0.f;
#pragma unroll
    for (int t = 0; t < 8; t++) {
      sacc[t][0] = __expf(sacc[t][0] - m0);
      sacc[t][1] = __expf(sacc[t][1] - m0);
      sacc[t][2] = __expf(sacc[t][2] - m1);
      sacc[t][3] = __expf(sacc[t][3] - m1);
      sum0 += sacc[t][0] + sacc[t][1];
      sum1 += sacc[t][2] + sacc[t][3];
    }
    sum0 += __shfl_xor_sync(0xffffffffu, sum0, 1);
    sum0 += __shfl_xor_sync(0xffffffffu, sum0, 2);
    sum1 += __shfl_xor_sync(0xffffffffu, sum1, 1);
    sum1 += __shfl_xor_sync(0xffffffffu, sum1, 2);
    l0 = l0 * al0 + sum0;
    l1 = l1 * al1 + sum1;
#pragma unroll
    for (int t = 0; t < 16; t++) {
      o[t][0] *= al0;
      o[t][1] *= al0;
      o[t][2] *= al1;
      o[t][3] *= al1;
    }

    // O += P * V  (single V)
#pragma unroll
    for (int j = 0; j < 4; j++) {
      uint32_t pha[4];
      pha[0] = h2bits(__floats2half2_rn(sacc[2 * j][0], sacc[2 * j][1]));
      pha[1] = h2bits(__floats2half2_rn(sacc[2 * j][2], sacc[2 * j][3]));
      pha[2] = h2bits(__floats2half2_rn(sacc[2 * j + 1][0], sacc[2 * j + 1][1]));
      pha[3] = h2bits(__floats2half2_rn(sacc[2 * j + 1][2], sacc[2 * j + 1][3]));
#pragma unroll
      for (int np = 0; np < 8; np++) {
        uint32_t va = sVh + ((j * 16 + vRow) * FA_STRIDE + np * 16 + vCol) * 2;
        uint32_t vh[4];
        LDSM4T(vh, va);
        MMAH16816(o[2 * np], pha, vh);
        MMAH16816(o[2 * np + 1], pha, vh + 2);
      }
    }
    __syncthreads();
  }

  // Epilogue: write context as single fp16 into out-proj A buffer
  float inv0 = 1.0f / l0, inv1 = 1.0f / l1;
  int r0 = qb * 64 + rloc;
#pragma unroll
  for (int t = 0; t < 16; t++) {
    int col = t * 8 + (lane & 3) * 2;
    {
      __half2 hi = __floats2half2_rn(o[t][0] * inv0, o[t][1] * inv0);
      *(__half2*)(CtxHi + ((size_t)r0 * NQH + hq) * 128 + col) = hi;
    }
    {
      __half2 hi = __floats2half2_rn(o[t][2] * inv1, o[t][3] * inv1);
      *(__half2*)(CtxHi + ((size_t)(r0 + 8) * NQH + hq) * 128 + col) = hi;
    }
  }
}

// ---------------------------------------------------------------------------
// Launch
// ---------------------------------------------------------------------------
extern "C" void kernel_launch(void* const* d_in, const int* in_sizes, int n_in,
                              void* d_out, int out_size) {
  const float* X = (const float*)d_in[0];
  const float* cosp = (const float*)d_in[1];
  const float* sinp = (const float*)d_in[2];
  const float* wq = (const float*)d_in[3];
  const float* wk = (const float*)d_in[4];
  const float* wv = (const float*)d_in[5];
  const float* wo = (const float*)d_in[6];
  float* out = (float*)d_out;

  float* QKV;
  __half *Ah, *Bh, *Qh, *Ql, *Kh, *Vh;
  cudaGetSymbolAddress((void**)&QKV, g_QKV);
  cudaGetSymbolAddress((void**)&Ah, g_Ah);
  cudaGetSymbolAddress((void**)&Bh, g_Bh);
  cudaGetSymbolAddress((void**)&Qh, g_Qh);
  cudaGetSymbolAddress((void**)&Ql, g_Ql);
  cudaGetSymbolAddress((void**)&Kh, g_Kh);
  cudaGetSymbolAddress((void**)&Vh, g_Vh);

  cudaFuncSetAttribute(gemm_mma_h, cudaFuncAttributeMaxDynamicSharedMemorySize,
                       GEMM_SMEM);
  cudaFuncSetAttribute(flash_mma, cudaFuncAttributeMaxDynamicSharedMemorySize,
                       FA_SMEM);

  // Activations -> fp16 (single)
  convert_plain<<<(S_LEN * KDIM / 4 + 255) / 256, 256>>>(X, Ah, S_LEN * KDIM);
  // Fused QKV weights -> [K,N] fp16 (coalesced, no transpose)
  convert_wqkv<<<(KDIM * NQKV / 4 + 255) / 256, 256>>>(wq, wk, wv, Bh);
  // Fused QKV projection
  gemm_mma_h<<<dim3(48, 32), dim3(128), GEMM_SMEM>>>(Ah, Bh, QKV, NQKV);
  // RoPE + fp16 for attention
  int rtot = S_LEN * NQH * 64 + 2 * S_LEN * NKVH * 64;
  rope_split<<<(rtot + 255) / 256, 256>>>(QKV, cosp, sinp);
  // Attention (KV double-buffered, single-V PV); writes context into Ah
  flash_mma<<<dim3(32, 32), dim3(128), FA_SMEM>>>(Qh, Ql, Kh, Vh, Ah);
  // Output projection
  convert_plain<<<(KDIM * H_DIM / 4 + 255) / 256, 256>>>(wo, Bh, KDIM * H_DIM);
  gemm_mma_h<<<dim3(32, 32), dim3(128), GEMM_SMEM>>>(Ah, Bh, out, 4096);
}